// round 1
// baseline (speedup 1.0000x reference)
#include <cuda_runtime.h>
#include <math.h>

// Problem constants
#define BB 2
#define SS 2048
#define EE 1024
#define HH 16
#define DD 64
#define MROWS (BB*SS)          // 4096

// Scratch (allocation-free: device globals)
__device__ float g_q[BB*HH*SS*DD];     // [B,H,S,D]
__device__ float g_k[BB*HH*SS*DD];
__device__ float g_v[BB*HH*SS*DD];
__device__ float g_attn[MROWS*EE];     // [B*S, E] merged heads

// ---------------------------------------------------------------------------
// SGEMM: C = A[MxK] @ B[KxN] + bias
// mode 0: C row-major output
// mode 1: scatter into g_q/g_k/g_v with [B,H,S,D] layout (N must be 3*E)
// A==nullptr means A = g_attn
// ---------------------------------------------------------------------------
__global__ __launch_bounds__(256) void sgemm_kernel(
    const float* __restrict__ A, const float* __restrict__ Bm,
    const float* __restrict__ bias, float* __restrict__ C,
    int M, int N, int K, int mode)
{
    __shared__ float As[8][128];
    __shared__ float Bs[8][128];

    const float* Ap = A ? A : g_attn;

    int tid = threadIdx.x;
    int m0 = blockIdx.y * 128;
    int n0 = blockIdx.x * 128;

    int a_row = tid >> 1;            // 0..127
    int a_col = (tid & 1) * 4;       // 0 or 4
    int b_row = tid >> 5;            // 0..7
    int b_col = (tid & 31) * 4;      // 0..124

    int ty = tid >> 4, tx = tid & 15;
    int row0 = ty * 8, col0 = tx * 8;

    float acc[8][8];
#pragma unroll
    for (int i = 0; i < 8; i++)
#pragma unroll
        for (int j = 0; j < 8; j++) acc[i][j] = 0.0f;

    for (int k0 = 0; k0 < K; k0 += 8) {
        float4 av = *(const float4*)&Ap[(size_t)(m0 + a_row) * K + k0 + a_col];
        float4 bv = *(const float4*)&Bm[(size_t)(k0 + b_row) * N + n0 + b_col];
        As[a_col + 0][a_row] = av.x;
        As[a_col + 1][a_row] = av.y;
        As[a_col + 2][a_row] = av.z;
        As[a_col + 3][a_row] = av.w;
        *(float4*)&Bs[b_row][b_col] = bv;
        __syncthreads();

#pragma unroll
        for (int kk = 0; kk < 8; kk++) {
            float4 a0 = *(const float4*)&As[kk][row0];
            float4 a1 = *(const float4*)&As[kk][row0 + 4];
            float4 b0 = *(const float4*)&Bs[kk][col0];
            float4 b1 = *(const float4*)&Bs[kk][col0 + 4];
            float af[8] = {a0.x, a0.y, a0.z, a0.w, a1.x, a1.y, a1.z, a1.w};
            float bf[8] = {b0.x, b0.y, b0.z, b0.w, b1.x, b1.y, b1.z, b1.w};
#pragma unroll
            for (int i = 0; i < 8; i++)
#pragma unroll
                for (int j = 0; j < 8; j++)
                    acc[i][j] += af[i] * bf[j];
        }
        __syncthreads();
    }

    if (mode == 0) {
#pragma unroll
        for (int i = 0; i < 8; i++) {
            int r = m0 + row0 + i;
#pragma unroll
            for (int j = 0; j < 8; j++) {
                int c = n0 + col0 + j;
                C[(size_t)r * N + c] = acc[i][j] + bias[c];
            }
        }
    } else {
        // QKV scatter. 8 consecutive cols never cross a part/head boundary.
        int c0 = n0 + col0;
        int part = c0 >> 10;         // 0=q, 1=k, 2=v
        int e0 = c0 & 1023;
        int h = e0 >> 6;
        int d0 = e0 & 63;
        float* dst = (part == 0) ? g_q : (part == 1) ? g_k : g_v;
#pragma unroll
        for (int i = 0; i < 8; i++) {
            int r = m0 + row0 + i;
            int b = r >> 11;          // r / 2048
            int s = r & 2047;
            size_t base = (((size_t)(b * HH + h)) * SS + s) * DD + d0;
#pragma unroll
            for (int j = 0; j < 8; j++)
                dst[base + j] = acc[i][j] + bias[c0 + j];
        }
    }
}

// ---------------------------------------------------------------------------
// Causal flash attention (fp32). One CTA per (b, h, 64-row q-tile).
// 256 threads as 16x16; each thread owns a 4x4 fragment.
// ---------------------------------------------------------------------------
#define SDP 65   // padded smem row stride (bank-conflict avoidance)

__global__ __launch_bounds__(256) void attn_kernel()
{
    extern __shared__ float sm[];
    float* Qs = sm;                    // 64 x SDP
    float* Ks = sm + 64 * SDP;
    float* Vs = sm + 2 * 64 * SDP;
    float* Ps = sm + 3 * 64 * SDP;

    int qt = blockIdx.x;
    int h  = blockIdx.y;
    int b  = blockIdx.z;
    int tid = threadIdx.x;
    int ty = tid >> 4, tx = tid & 15;

    size_t bh_off = (size_t)(b * HH + h) * SS * DD;
    const float* Qg = g_q + bh_off;
    const float* Kg = g_k + bh_off;
    const float* Vg = g_v + bh_off;

    int q0 = qt * 64;

    // Load Q tile
    for (int idx = tid; idx < 64 * 64; idx += 256) {
        int r = idx >> 6, c = idx & 63;
        Qs[r * SDP + c] = Qg[(size_t)(q0 + r) * DD + c];
    }

    float o[4][4];
    float m_i[4], l_i[4];
#pragma unroll
    for (int i = 0; i < 4; i++) {
        m_i[i] = -1e30f;
        l_i[i] = 0.0f;
#pragma unroll
        for (int j = 0; j < 4; j++) o[i][j] = 0.0f;
    }

    const float scale = 1.0f / 16.0f;   // 1/(sqrt(64) * layer_idx=2)

    for (int jt = 0; jt <= qt; jt++) {
        __syncthreads();   // protect smem (Q on first iter, Ps/Vs afterwards)
        int k0 = jt * 64;
        for (int idx = tid; idx < 64 * 64; idx += 256) {
            int r = idx >> 6, c = idx & 63;
            Ks[r * SDP + c] = Kg[(size_t)(k0 + r) * DD + c];
            Vs[r * SDP + c] = Vg[(size_t)(k0 + r) * DD + c];
        }
        __syncthreads();

        // S = Q K^T  (4x4 fragment per thread)
        float s_[4][4];
#pragma unroll
        for (int i = 0; i < 4; i++)
#pragma unroll
            for (int j = 0; j < 4; j++) s_[i][j] = 0.0f;

        for (int d = 0; d < 64; d++) {
            float qf[4], kf[4];
#pragma unroll
            for (int i = 0; i < 4; i++) qf[i] = Qs[(ty * 4 + i) * SDP + d];
#pragma unroll
            for (int j = 0; j < 4; j++) kf[j] = Ks[(tx * 4 + j) * SDP + d];
#pragma unroll
            for (int i = 0; i < 4; i++)
#pragma unroll
                for (int j = 0; j < 4; j++)
                    s_[i][j] += qf[i] * kf[j];
        }

        // scale + causal mask (only the diagonal tile can mask)
#pragma unroll
        for (int i = 0; i < 4; i++) {
            int qg = q0 + ty * 4 + i;
#pragma unroll
            for (int j = 0; j < 4; j++) {
                int kg = k0 + tx * 4 + j;
                float v = s_[i][j] * scale;
                s_[i][j] = (kg > qg) ? -10000.0f : v;
            }
        }

        // online softmax per q-row (16 lanes per row; xor<=8 stays in group)
#pragma unroll
        for (int i = 0; i < 4; i++) {
            float rm = s_[i][0];
#pragma unroll
            for (int j = 1; j < 4; j++) rm = fmaxf(rm, s_[i][j]);
            for (int off = 8; off >= 1; off >>= 1)
                rm = fmaxf(rm, __shfl_xor_sync(0xffffffffu, rm, off));
            float mn = fmaxf(m_i[i], rm);
            float alpha = __expf(m_i[i] - mn);
            float rs = 0.0f;
#pragma unroll
            for (int j = 0; j < 4; j++) {
                float p = __expf(s_[i][j] - mn);
                s_[i][j] = p;
                rs += p;
            }
            for (int off = 8; off >= 1; off >>= 1)
                rs += __shfl_xor_sync(0xffffffffu, rs, off);
            l_i[i] = l_i[i] * alpha + rs;
            m_i[i] = mn;
#pragma unroll
            for (int j = 0; j < 4; j++) o[i][j] *= alpha;
#pragma unroll
            for (int j = 0; j < 4; j++)
                Ps[(ty * 4 + i) * SDP + tx * 4 + j] = s_[i][j];
        }
        __syncthreads();

        // O += P V  (thread owns q rows ty*4.., d cols tx*4..)
        for (int k = 0; k < 64; k++) {
            float pf[4], vf[4];
#pragma unroll
            for (int i = 0; i < 4; i++) pf[i] = Ps[(ty * 4 + i) * SDP + k];
#pragma unroll
            for (int j = 0; j < 4; j++) vf[j] = Vs[k * SDP + tx * 4 + j];
#pragma unroll
            for (int i = 0; i < 4; i++)
#pragma unroll
                for (int j = 0; j < 4; j++)
                    o[i][j] += pf[i] * vf[j];
        }
    }

    // Normalize and write merged-head output [B*S, E]
#pragma unroll
    for (int i = 0; i < 4; i++) {
        float inv = 1.0f / l_i[i];
        int qg = q0 + ty * 4 + i;
        size_t row = (size_t)(b * SS + qg) * EE + h * DD + tx * 4;
#pragma unroll
        for (int j = 0; j < 4; j++)
            g_attn[row + j] = o[i][j] * inv;
    }
}

// ---------------------------------------------------------------------------
extern "C" void kernel_launch(void* const* d_in, const int* in_sizes, int n_in,
                              void* d_out, int out_size)
{
    const float* hidden = (const float*)d_in[0];   // [B,S,E]
    const float* w_attn = (const float*)d_in[1];   // [E, 3E]
    const float* b_attn = (const float*)d_in[2];   // [3E]
    const float* w_proj = (const float*)d_in[3];   // [E, E]
    const float* b_proj = (const float*)d_in[4];   // [E]
    float* out = (float*)d_out;                    // [B,S,E] fp32

    // 1) QKV GEMM: [4096,1024] @ [1024,3072], scatter to Q/K/V [B,H,S,D]
    sgemm_kernel<<<dim3(3 * EE / 128, MROWS / 128), 256>>>(
        hidden, w_attn, b_attn, nullptr, MROWS, 3 * EE, EE, 1);

    // 2) Causal flash attention
    int smem = 4 * 64 * SDP * (int)sizeof(float);  // 66560 B
    cudaFuncSetAttribute(attn_kernel,
                         cudaFuncAttributeMaxDynamicSharedMemorySize, smem);
    attn_kernel<<<dim3(SS / 64, HH, BB), 256, smem>>>();

    // 3) Output projection: g_attn [4096,1024] @ [1024,1024] -> d_out
    sgemm_kernel<<<dim3(EE / 128, MROWS / 128), 256>>>(
        nullptr, w_proj, b_proj, out, MROWS, EE, EE, 0);
}

// round 3
// speedup vs baseline: 1.4251x; 1.4251x over previous
#include <cuda_runtime.h>
#include <cuda_bf16.h>
#include <cstdint>
#include <math.h>

// Problem constants
#define BB 2
#define SS 2048
#define EE 1024
#define HH 16
#define DD 64
#define MROWS (BB*SS)          // 4096
#define KDIM 1024
#define N_QKV 3072

// ---------------------------------------------------------------------------
// Scratch (allocation-free: device globals)
// ---------------------------------------------------------------------------
__device__ float g_q[BB*HH*SS*DD];     // [B,H,S,D]
__device__ float g_k[BB*HH*SS*DD];
__device__ float g_v[BB*HH*SS*DD];
__device__ float g_attn[MROWS*EE];     // [B*S, E] merged heads

// bf16 split (hi/lo) operands for tensor-core GEMMs
__device__ __nv_bfloat16 g_hhi[MROWS*KDIM];     // hidden hi
__device__ __nv_bfloat16 g_hlo[MROWS*KDIM];     // hidden lo
__device__ __nv_bfloat16 g_ahi[MROWS*KDIM];     // attn-out hi
__device__ __nv_bfloat16 g_alo[MROWS*KDIM];     // attn-out lo
__device__ __nv_bfloat16 g_wqkvThi[N_QKV*KDIM]; // w_attn^T hi  [3072,1024]
__device__ __nv_bfloat16 g_wqkvTlo[N_QKV*KDIM];
__device__ __nv_bfloat16 g_wprojThi[EE*KDIM];   // w_proj^T hi  [1024,1024]
__device__ __nv_bfloat16 g_wprojTlo[EE*KDIM];

// ---------------------------------------------------------------------------
// PTX helpers: ldmatrix + mma.sync (bf16), valid on base sm_103 target
// ---------------------------------------------------------------------------
__device__ __forceinline__ uint32_t smem_u32(const void* p) {
    uint32_t a;
    asm("{ .reg .u64 t; cvta.to.shared.u64 t, %1; cvt.u32.u64 %0, t; }"
        : "=r"(a) : "l"(p));
    return a;
}

__device__ __forceinline__ void ldm_x4(uint32_t& r0, uint32_t& r1,
                                       uint32_t& r2, uint32_t& r3,
                                       uint32_t addr) {
    asm volatile("ldmatrix.sync.aligned.m8n8.x4.shared.b16 {%0,%1,%2,%3}, [%4];"
                 : "=r"(r0), "=r"(r1), "=r"(r2), "=r"(r3) : "r"(addr));
}

__device__ __forceinline__ void mma_bf16(float* d, const uint32_t* a,
                                         uint32_t b0, uint32_t b1) {
    asm volatile(
        "mma.sync.aligned.m16n8k16.row.col.f32.bf16.bf16.f32 "
        "{%0,%1,%2,%3}, {%4,%5,%6,%7}, {%8,%9}, {%0,%1,%2,%3};"
        : "+f"(d[0]), "+f"(d[1]), "+f"(d[2]), "+f"(d[3])
        : "r"(a[0]), "r"(a[1]), "r"(a[2]), "r"(a[3]), "r"(b0), "r"(b1));
}

// ---------------------------------------------------------------------------
// Prep kernel 1: split fp32 -> bf16 hi/lo.  which: 0 = hidden, 1 = g_attn
// ---------------------------------------------------------------------------
__global__ __launch_bounds__(256) void split_kernel(const float* __restrict__ x,
                                                    int which)
{
    const float* src = which ? g_attn : x;
    __nv_bfloat16* hi = which ? g_ahi : g_hhi;
    __nv_bfloat16* lo = which ? g_alo : g_hlo;
    size_t i0 = ((size_t)blockIdx.x * 256 + threadIdx.x) * 4;
    float4 v = *(const float4*)&src[i0];
    __nv_bfloat16 h0 = __float2bfloat16(v.x);
    __nv_bfloat16 h1 = __float2bfloat16(v.y);
    __nv_bfloat16 h2 = __float2bfloat16(v.z);
    __nv_bfloat16 h3 = __float2bfloat16(v.w);
    __nv_bfloat162 hp0; hp0.x = h0; hp0.y = h1;
    __nv_bfloat162 hp1; hp1.x = h2; hp1.y = h3;
    __nv_bfloat162 lp0;
    lp0.x = __float2bfloat16(v.x - __bfloat162float(h0));
    lp0.y = __float2bfloat16(v.y - __bfloat162float(h1));
    __nv_bfloat162 lp1;
    lp1.x = __float2bfloat16(v.z - __bfloat162float(h2));
    lp1.y = __float2bfloat16(v.w - __bfloat162float(h3));
    *(__nv_bfloat162*)&hi[i0]     = hp0;
    *(__nv_bfloat162*)&hi[i0 + 2] = hp1;
    *(__nv_bfloat162*)&lo[i0]     = lp0;
    *(__nv_bfloat162*)&lo[i0 + 2] = lp1;
}

// ---------------------------------------------------------------------------
// Prep kernel 2: W [K,N] row-major -> W^T [N,K] bf16 hi/lo
// ---------------------------------------------------------------------------
__global__ __launch_bounds__(256) void tsplit_kernel(const float* __restrict__ W,
                                                     int which, int N)
{
    __nv_bfloat16* Thi = which ? g_wprojThi : g_wqkvThi;
    __nv_bfloat16* Tlo = which ? g_wprojTlo : g_wqkvTlo;
    __shared__ float t[32][33];
    int n0 = blockIdx.x * 32, k0 = blockIdx.y * 32;
    int tx = threadIdx.x & 31, ty = threadIdx.x >> 5;   // ty 0..7
#pragma unroll
    for (int r = 0; r < 32; r += 8)
        t[ty + r][tx] = W[(size_t)(k0 + ty + r) * N + n0 + tx];
    __syncthreads();
#pragma unroll
    for (int r = 0; r < 32; r += 8) {
        float v = t[tx][ty + r];
        __nv_bfloat16 h = __float2bfloat16(v);
        size_t o = (size_t)(n0 + ty + r) * KDIM + k0 + tx;
        Thi[o] = h;
        Tlo[o] = __float2bfloat16(v - __bfloat162float(h));
    }
}

// ---------------------------------------------------------------------------
// Tensor-core GEMM via mma.sync bf16 3-pass split.
// D[M, N] = A[M,K] @ B^T[N,K]^T + bias, fp32 accumulate.
// CTA tile 128x128, BK=32. 8 warps as 2(M) x 4(N); warp tile 64x32.
// mode 1: A = hidden split, B = w_attn^T split, scatter to g_q/g_k/g_v
// mode 0: A = attn split,   B = w_proj^T split, row-major to outp
// ---------------------------------------------------------------------------
#define BK 32
#define LDSR 40  // smem row stride in bf16 elements (80B: conflict-free ldmatrix)

__global__ __launch_bounds__(256) void mma_gemm(const float* __restrict__ bias,
                                                float* __restrict__ outp,
                                                int mode)
{
    __shared__ __nv_bfloat16 Ahi_s[128 * LDSR];
    __shared__ __nv_bfloat16 Alo_s[128 * LDSR];
    __shared__ __nv_bfloat16 Bhi_s[128 * LDSR];
    __shared__ __nv_bfloat16 Blo_s[128 * LDSR];

    const __nv_bfloat16* Ahi = mode ? g_hhi : g_ahi;
    const __nv_bfloat16* Alo = mode ? g_hlo : g_alo;
    const __nv_bfloat16* Bhi = mode ? g_wqkvThi : g_wprojThi;
    const __nv_bfloat16* Blo = mode ? g_wqkvTlo : g_wprojTlo;

    int tid = threadIdx.x;
    int wid = tid >> 5, lane = tid & 31;
    int warp_m = wid & 1, warp_n = wid >> 1;          // 2 x 4
    int m0 = blockIdx.y * 128, n0 = blockIdx.x * 128;

    float acc[4][4][4];                                // [mf][nf][reg]
#pragma unroll
    for (int i = 0; i < 4; i++)
#pragma unroll
        for (int j = 0; j < 4; j++)
#pragma unroll
            for (int r = 0; r < 4; r++) acc[i][j][r] = 0.0f;

    // ldmatrix base addresses (per-lane)
    int lrow = lane & 15, lcol = lane >> 4;
    uint32_t a_hi_b = smem_u32(Ahi_s) +
        (uint32_t)(((warp_m * 64 + lrow) * LDSR + lcol * 8) * 2);
    uint32_t a_lo_b = smem_u32(Alo_s) +
        (uint32_t)(((warp_m * 64 + lrow) * LDSR + lcol * 8) * 2);
    uint32_t b_hi_b = smem_u32(Bhi_s) +
        (uint32_t)(((warp_n * 32 + lrow) * LDSR + lcol * 8) * 2);
    uint32_t b_lo_b = smem_u32(Blo_s) +
        (uint32_t)(((warp_n * 32 + lrow) * LDSR + lcol * 8) * 2);

    for (int kc = 0; kc < KDIM; kc += BK) {
        // Load tiles: 128 rows x 32 cols each (4 uint4 per row)
#pragma unroll
        for (int t = 0; t < 2; t++) {
            int i = tid + t * 256;                     // 0..511
            int r = i >> 2, v = i & 3;
            size_t asrc = (size_t)(m0 + r) * KDIM + kc + v * 8;
            size_t bsrc = (size_t)(n0 + r) * KDIM + kc + v * 8;
            uint32_t so = (uint32_t)(r * LDSR + v * 8);
            *(uint4*)&Ahi_s[so] = *(const uint4*)(Ahi + asrc);
            *(uint4*)&Alo_s[so] = *(const uint4*)(Alo + asrc);
            *(uint4*)&Bhi_s[so] = *(const uint4*)(Bhi + bsrc);
            *(uint4*)&Blo_s[so] = *(const uint4*)(Blo + bsrc);
        }
        __syncthreads();

#pragma unroll
        for (int ks = 0; ks < BK; ks += 16) {
            uint32_t ah[4][4], al[4][4];
#pragma unroll
            for (int mf = 0; mf < 4; mf++) {
                uint32_t off = (uint32_t)(mf * 16 * LDSR + ks) * 2;
                ldm_x4(ah[mf][0], ah[mf][1], ah[mf][2], ah[mf][3], a_hi_b + off);
                ldm_x4(al[mf][0], al[mf][1], al[mf][2], al[mf][3], a_lo_b + off);
            }
            uint32_t bh[4][2], bl[4][2];
#pragma unroll
            for (int pf = 0; pf < 2; pf++) {
                uint32_t off = (uint32_t)(pf * 16 * LDSR + ks) * 2;
                uint32_t r0, r1, r2, r3;
                ldm_x4(r0, r1, r2, r3, b_hi_b + off);
                bh[pf * 2 + 0][0] = r0; bh[pf * 2 + 0][1] = r2;
                bh[pf * 2 + 1][0] = r1; bh[pf * 2 + 1][1] = r3;
                ldm_x4(r0, r1, r2, r3, b_lo_b + off);
                bl[pf * 2 + 0][0] = r0; bl[pf * 2 + 0][1] = r2;
                bl[pf * 2 + 1][0] = r1; bl[pf * 2 + 1][1] = r3;
            }
#pragma unroll
            for (int mf = 0; mf < 4; mf++)
#pragma unroll
                for (int nf = 0; nf < 4; nf++) {
                    mma_bf16(acc[mf][nf], ah[mf], bh[nf][0], bh[nf][1]);
                    mma_bf16(acc[mf][nf], al[mf], bh[nf][0], bh[nf][1]);
                    mma_bf16(acc[mf][nf], ah[mf], bl[nf][0], bl[nf][1]);
                }
        }
        __syncthreads();
    }

    // Epilogue: direct register stores (+bias, mode scatter)
    int gID = lane >> 2, tcol = lane & 3;
#pragma unroll
    for (int mf = 0; mf < 4; mf++) {
#pragma unroll
        for (int nf = 0; nf < 4; nf++) {
            int c = n0 + warp_n * 32 + nf * 8 + tcol * 2;
            float2 bv = *(const float2*)&bias[c];
#pragma unroll
            for (int half = 0; half < 2; half++) {
                int r = m0 + warp_m * 64 + mf * 16 + gID + half * 8;
                float2 v;
                v.x = acc[mf][nf][half * 2 + 0] + bv.x;
                v.y = acc[mf][nf][half * 2 + 1] + bv.y;
                if (mode == 0) {
                    *(float2*)&outp[(size_t)r * EE + c] = v;
                } else {
                    int part = c >> 10, e = c & 1023, h = e >> 6, d0 = e & 63;
                    float* dst = (part == 0) ? g_q : (part == 1) ? g_k : g_v;
                    int b = r >> 11, s = r & 2047;
                    *(float2*)&dst[(((size_t)(b * HH + h)) * SS + s) * DD + d0] = v;
                }
            }
        }
    }
}

// ---------------------------------------------------------------------------
// Causal flash attention (fp32). One CTA per (b, h, 64-row q-tile).
// ---------------------------------------------------------------------------
#define SDP 65

__global__ __launch_bounds__(256) void attn_kernel()
{
    extern __shared__ float sm[];
    float* Qs = sm;
    float* Ks = sm + 64 * SDP;
    float* Vs = sm + 2 * 64 * SDP;
    float* Ps = sm + 3 * 64 * SDP;

    int qt = blockIdx.x;
    int h  = blockIdx.y;
    int b  = blockIdx.z;
    int tid = threadIdx.x;
    int ty = tid >> 4, tx = tid & 15;

    size_t bh_off = (size_t)(b * HH + h) * SS * DD;
    const float* Qg = g_q + bh_off;
    const float* Kg = g_k + bh_off;
    const float* Vg = g_v + bh_off;

    int q0 = qt * 64;

    for (int idx = tid; idx < 64 * 64; idx += 256) {
        int r = idx >> 6, c = idx & 63;
        Qs[r * SDP + c] = Qg[(size_t)(q0 + r) * DD + c];
    }

    float o[4][4];
    float m_i[4], l_i[4];
#pragma unroll
    for (int i = 0; i < 4; i++) {
        m_i[i] = -1e30f;
        l_i[i] = 0.0f;
#pragma unroll
        for (int j = 0; j < 4; j++) o[i][j] = 0.0f;
    }

    const float scale = 1.0f / 16.0f;

    for (int jt = 0; jt <= qt; jt++) {
        __syncthreads();
        int k0 = jt * 64;
        for (int idx = tid; idx < 64 * 64; idx += 256) {
            int r = idx >> 6, c = idx & 63;
            Ks[r * SDP + c] = Kg[(size_t)(k0 + r) * DD + c];
            Vs[r * SDP + c] = Vg[(size_t)(k0 + r) * DD + c];
        }
        __syncthreads();

        float s_[4][4];
#pragma unroll
        for (int i = 0; i < 4; i++)
#pragma unroll
            for (int j = 0; j < 4; j++) s_[i][j] = 0.0f;

        for (int d = 0; d < 64; d++) {
            float qf[4], kf[4];
#pragma unroll
            for (int i = 0; i < 4; i++) qf[i] = Qs[(ty * 4 + i) * SDP + d];
#pragma unroll
            for (int j = 0; j < 4; j++) kf[j] = Ks[(tx * 4 + j) * SDP + d];
#pragma unroll
            for (int i = 0; i < 4; i++)
#pragma unroll
                for (int j = 0; j < 4; j++)
                    s_[i][j] += qf[i] * kf[j];
        }

#pragma unroll
        for (int i = 0; i < 4; i++) {
            int qg = q0 + ty * 4 + i;
#pragma unroll
            for (int j = 0; j < 4; j++) {
                int kg = k0 + tx * 4 + j;
                float v = s_[i][j] * scale;
                s_[i][j] = (kg > qg) ? -10000.0f : v;
            }
        }

#pragma unroll
        for (int i = 0; i < 4; i++) {
            float rm = s_[i][0];
#pragma unroll
            for (int j = 1; j < 4; j++) rm = fmaxf(rm, s_[i][j]);
            for (int off = 8; off >= 1; off >>= 1)
                rm = fmaxf(rm, __shfl_xor_sync(0xffffffffu, rm, off));
            float mn = fmaxf(m_i[i], rm);
            float alpha = __expf(m_i[i] - mn);
            float rs = 0.0f;
#pragma unroll
            for (int j = 0; j < 4; j++) {
                float p = __expf(s_[i][j] - mn);
                s_[i][j] = p;
                rs += p;
            }
            for (int off = 8; off >= 1; off >>= 1)
                rs += __shfl_xor_sync(0xffffffffu, rs, off);
            l_i[i] = l_i[i] * alpha + rs;
            m_i[i] = mn;
#pragma unroll
            for (int j = 0; j < 4; j++) o[i][j] *= alpha;
#pragma unroll
            for (int j = 0; j < 4; j++)
                Ps[(ty * 4 + i) * SDP + tx * 4 + j] = s_[i][j];
        }
        __syncthreads();

        for (int k = 0; k < 64; k++) {
            float pf[4], vf[4];
#pragma unroll
            for (int i = 0; i < 4; i++) pf[i] = Ps[(ty * 4 + i) * SDP + k];
#pragma unroll
            for (int j = 0; j < 4; j++) vf[j] = Vs[k * SDP + tx * 4 + j];
#pragma unroll
            for (int i = 0; i < 4; i++)
#pragma unroll
                for (int j = 0; j < 4; j++)
                    o[i][j] += pf[i] * vf[j];
        }
    }

#pragma unroll
    for (int i = 0; i < 4; i++) {
        float inv = 1.0f / l_i[i];
        int qg = q0 + ty * 4 + i;
        size_t row = (size_t)(b * SS + qg) * EE + h * DD + tx * 4;
#pragma unroll
        for (int j = 0; j < 4; j++)
            g_attn[row + j] = o[i][j] * inv;
    }
}

// ---------------------------------------------------------------------------
extern "C" void kernel_launch(void* const* d_in, const int* in_sizes, int n_in,
                              void* d_out, int out_size)
{
    const float* hidden = (const float*)d_in[0];   // [B,S,E]
    const float* w_attn = (const float*)d_in[1];   // [E, 3E]
    const float* b_attn = (const float*)d_in[2];   // [3E]
    const float* w_proj = (const float*)d_in[3];   // [E, E]
    const float* b_proj = (const float*)d_in[4];   // [E]
    float* out = (float*)d_out;                    // [B,S,E] fp32

    // Prep: bf16 hi/lo splits (+ weight transposes)
    split_kernel<<<(MROWS * KDIM) / (256 * 4), 256>>>(hidden, 0);
    tsplit_kernel<<<dim3(N_QKV / 32, KDIM / 32), 256>>>(w_attn, 0, N_QKV);
    tsplit_kernel<<<dim3(EE / 32, KDIM / 32), 256>>>(w_proj, 1, EE);

    // 1) QKV GEMM (tensor cores): [4096,1024]x[1024,3072] -> g_q/g_k/g_v
    mma_gemm<<<dim3(N_QKV / 128, MROWS / 128), 256>>>(b_attn, nullptr, 1);

    // 2) Causal flash attention (fp32)
    int smem = 4 * 64 * SDP * (int)sizeof(float);
    cudaFuncSetAttribute(attn_kernel,
                         cudaFuncAttributeMaxDynamicSharedMemorySize, smem);
    attn_kernel<<<dim3(SS / 64, HH, BB), 256, smem>>>();

    // 3) Split attention output, then proj GEMM -> d_out
    split_kernel<<<(MROWS * KDIM) / (256 * 4), 256>>>(nullptr, 1);
    mma_gemm<<<dim3(EE / 128, MROWS / 128), 256>>>(b_proj, out, 0);
}

// round 5
// speedup vs baseline: 2.1355x; 1.4986x over previous
#include <cuda_runtime.h>
#include <cuda_bf16.h>
#include <cstdint>
#include <math.h>

// Problem constants
#define BB 2
#define SS 2048
#define EE 1024
#define HH 16
#define DD 64
#define MROWS (BB*SS)          // 4096
#define KDIM 1024
#define N_QKV 3072

// ---------------------------------------------------------------------------
// Scratch (allocation-free: device globals)
// ---------------------------------------------------------------------------
// Q/K/V in bf16 hi/lo, [B,H,S,D] layout (written by QKV GEMM epilogue)
__device__ __nv_bfloat16 g_qhi[BB*HH*SS*DD];
__device__ __nv_bfloat16 g_qlo[BB*HH*SS*DD];
__device__ __nv_bfloat16 g_khi[BB*HH*SS*DD];
__device__ __nv_bfloat16 g_klo[BB*HH*SS*DD];
__device__ __nv_bfloat16 g_vhi[BB*HH*SS*DD];
__device__ __nv_bfloat16 g_vlo[BB*HH*SS*DD];

// bf16 split (hi/lo) operands for tensor-core GEMMs
__device__ __nv_bfloat16 g_hhi[MROWS*KDIM];     // hidden hi
__device__ __nv_bfloat16 g_hlo[MROWS*KDIM];     // hidden lo
__device__ __nv_bfloat16 g_ahi[MROWS*KDIM];     // attn-out hi (merged heads)
__device__ __nv_bfloat16 g_alo[MROWS*KDIM];     // attn-out lo
__device__ __nv_bfloat16 g_wqkvThi[N_QKV*KDIM]; // w_attn^T hi  [3072,1024]
__device__ __nv_bfloat16 g_wqkvTlo[N_QKV*KDIM];
__device__ __nv_bfloat16 g_wprojThi[EE*KDIM];   // w_proj^T hi  [1024,1024]
__device__ __nv_bfloat16 g_wprojTlo[EE*KDIM];

// ---------------------------------------------------------------------------
// PTX helpers: ldmatrix + mma.sync (bf16), valid on base sm_103 target
// ---------------------------------------------------------------------------
__device__ __forceinline__ uint32_t smem_u32(const void* p) {
    uint32_t a;
    asm("{ .reg .u64 t; cvta.to.shared.u64 t, %1; cvt.u32.u64 %0, t; }"
        : "=r"(a) : "l"(p));
    return a;
}

__device__ __forceinline__ void ldm_x4(uint32_t& r0, uint32_t& r1,
                                       uint32_t& r2, uint32_t& r3,
                                       uint32_t addr) {
    asm volatile("ldmatrix.sync.aligned.m8n8.x4.shared.b16 {%0,%1,%2,%3}, [%4];"
                 : "=r"(r0), "=r"(r1), "=r"(r2), "=r"(r3) : "r"(addr));
}
__device__ __forceinline__ void ldm_x4_t(uint32_t& r0, uint32_t& r1,
                                         uint32_t& r2, uint32_t& r3,
                                         uint32_t addr) {
    asm volatile("ldmatrix.sync.aligned.m8n8.x4.trans.shared.b16 {%0,%1,%2,%3}, [%4];"
                 : "=r"(r0), "=r"(r1), "=r"(r2), "=r"(r3) : "r"(addr));
}

__device__ __forceinline__ void mma_bf16(float* d, const uint32_t* a,
                                         uint32_t b0, uint32_t b1) {
    asm volatile(
        "mma.sync.aligned.m16n8k16.row.col.f32.bf16.bf16.f32 "
        "{%0,%1,%2,%3}, {%4,%5,%6,%7}, {%8,%9}, {%0,%1,%2,%3};"
        : "+f"(d[0]), "+f"(d[1]), "+f"(d[2]), "+f"(d[3])
        : "r"(a[0]), "r"(a[1]), "r"(a[2]), "r"(a[3]), "r"(b0), "r"(b1));
}

// pack two fp32 into bf16x2: hi source -> upper half, lo source -> lower half
__device__ __forceinline__ uint32_t packbf(float hi, float lo) {
    uint32_t d;
    asm("cvt.rn.bf16x2.f32 %0, %1, %2;" : "=r"(d) : "f"(hi), "f"(lo));
    return d;
}
__device__ __forceinline__ float lof(uint32_t u) {   // lower bf16 as fp32
    return __uint_as_float(u << 16);
}
__device__ __forceinline__ float hif(uint32_t u) {   // upper bf16 as fp32
    return __uint_as_float(u & 0xffff0000u);
}

// ---------------------------------------------------------------------------
// Prep kernel 1: split fp32 -> bf16 hi/lo (hidden only)
// ---------------------------------------------------------------------------
__global__ __launch_bounds__(256) void split_kernel(const float* __restrict__ x)
{
    size_t i0 = ((size_t)blockIdx.x * 256 + threadIdx.x) * 4;
    float4 v = *(const float4*)&x[i0];
    __nv_bfloat16 h0 = __float2bfloat16(v.x);
    __nv_bfloat16 h1 = __float2bfloat16(v.y);
    __nv_bfloat16 h2 = __float2bfloat16(v.z);
    __nv_bfloat16 h3 = __float2bfloat16(v.w);
    __nv_bfloat162 hp0; hp0.x = h0; hp0.y = h1;
    __nv_bfloat162 hp1; hp1.x = h2; hp1.y = h3;
    __nv_bfloat162 lp0;
    lp0.x = __float2bfloat16(v.x - __bfloat162float(h0));
    lp0.y = __float2bfloat16(v.y - __bfloat162float(h1));
    __nv_bfloat162 lp1;
    lp1.x = __float2bfloat16(v.z - __bfloat162float(h2));
    lp1.y = __float2bfloat16(v.w - __bfloat162float(h3));
    *(__nv_bfloat162*)&g_hhi[i0]     = hp0;
    *(__nv_bfloat162*)&g_hhi[i0 + 2] = hp1;
    *(__nv_bfloat162*)&g_hlo[i0]     = lp0;
    *(__nv_bfloat162*)&g_hlo[i0 + 2] = lp1;
}

// ---------------------------------------------------------------------------
// Prep kernel 2: W [K,N] row-major -> W^T [N,K] bf16 hi/lo
// ---------------------------------------------------------------------------
__global__ __launch_bounds__(256) void tsplit_kernel(const float* __restrict__ W,
                                                     int which, int N)
{
    __nv_bfloat16* Thi = which ? g_wprojThi : g_wqkvThi;
    __nv_bfloat16* Tlo = which ? g_wprojTlo : g_wqkvTlo;
    __shared__ float t[32][33];
    int n0 = blockIdx.x * 32, k0 = blockIdx.y * 32;
    int tx = threadIdx.x & 31, ty = threadIdx.x >> 5;   // ty 0..7
#pragma unroll
    for (int r = 0; r < 32; r += 8)
        t[ty + r][tx] = W[(size_t)(k0 + ty + r) * N + n0 + tx];
    __syncthreads();
#pragma unroll
    for (int r = 0; r < 32; r += 8) {
        float v = t[tx][ty + r];
        __nv_bfloat16 h = __float2bfloat16(v);
        size_t o = (size_t)(n0 + ty + r) * KDIM + k0 + tx;
        Thi[o] = h;
        Tlo[o] = __float2bfloat16(v - __bfloat162float(h));
    }
}

// ---------------------------------------------------------------------------
// Tensor-core GEMM via mma.sync bf16 3-pass split.
// mode 1: A = hidden split, B = w_attn^T split -> Q/K/V bf16 hi/lo [B,H,S,D]
// mode 0: A = attn split,   B = w_proj^T split -> row-major fp32 outp
// ---------------------------------------------------------------------------
#define BK 32
#define LDSR 40  // smem row stride for 32-col tiles (80B: conflict-free ldmatrix)

__global__ __launch_bounds__(256) void mma_gemm(const float* __restrict__ bias,
                                                float* __restrict__ outp,
                                                int mode)
{
    __shared__ __nv_bfloat16 Ahi_s[128 * LDSR];
    __shared__ __nv_bfloat16 Alo_s[128 * LDSR];
    __shared__ __nv_bfloat16 Bhi_s[128 * LDSR];
    __shared__ __nv_bfloat16 Blo_s[128 * LDSR];

    const __nv_bfloat16* Ahi = mode ? g_hhi : g_ahi;
    const __nv_bfloat16* Alo = mode ? g_hlo : g_alo;
    const __nv_bfloat16* Bhi = mode ? g_wqkvThi : g_wprojThi;
    const __nv_bfloat16* Blo = mode ? g_wqkvTlo : g_wprojTlo;

    int tid = threadIdx.x;
    int wid = tid >> 5, lane = tid & 31;
    int warp_m = wid & 1, warp_n = wid >> 1;          // 2 x 4
    int m0 = blockIdx.y * 128, n0 = blockIdx.x * 128;

    float acc[4][4][4];                                // [mf][nf][reg]
#pragma unroll
    for (int i = 0; i < 4; i++)
#pragma unroll
        for (int j = 0; j < 4; j++)
#pragma unroll
            for (int r = 0; r < 4; r++) acc[i][j][r] = 0.0f;

    int lrow = lane & 15, lcol = lane >> 4;
    uint32_t a_hi_b = smem_u32(Ahi_s) +
        (uint32_t)(((warp_m * 64 + lrow) * LDSR + lcol * 8) * 2);
    uint32_t a_lo_b = smem_u32(Alo_s) +
        (uint32_t)(((warp_m * 64 + lrow) * LDSR + lcol * 8) * 2);
    uint32_t b_hi_b = smem_u32(Bhi_s) +
        (uint32_t)(((warp_n * 32 + lrow) * LDSR + lcol * 8) * 2);
    uint32_t b_lo_b = smem_u32(Blo_s) +
        (uint32_t)(((warp_n * 32 + lrow) * LDSR + lcol * 8) * 2);

    for (int kc = 0; kc < KDIM; kc += BK) {
#pragma unroll
        for (int t = 0; t < 2; t++) {
            int i = tid + t * 256;
            int r = i >> 2, v = i & 3;
            size_t asrc = (size_t)(m0 + r) * KDIM + kc + v * 8;
            size_t bsrc = (size_t)(n0 + r) * KDIM + kc + v * 8;
            uint32_t so = (uint32_t)(r * LDSR + v * 8);
            *(uint4*)&Ahi_s[so] = *(const uint4*)(Ahi + asrc);
            *(uint4*)&Alo_s[so] = *(const uint4*)(Alo + asrc);
            *(uint4*)&Bhi_s[so] = *(const uint4*)(Bhi + bsrc);
            *(uint4*)&Blo_s[so] = *(const uint4*)(Blo + bsrc);
        }
        __syncthreads();

#pragma unroll
        for (int ks = 0; ks < BK; ks += 16) {
            uint32_t ah[4][4], al[4][4];
#pragma unroll
            for (int mf = 0; mf < 4; mf++) {
                uint32_t off = (uint32_t)(mf * 16 * LDSR + ks) * 2;
                ldm_x4(ah[mf][0], ah[mf][1], ah[mf][2], ah[mf][3], a_hi_b + off);
                ldm_x4(al[mf][0], al[mf][1], al[mf][2], al[mf][3], a_lo_b + off);
            }
            uint32_t bh[4][2], bl[4][2];
#pragma unroll
            for (int pf = 0; pf < 2; pf++) {
                uint32_t off = (uint32_t)(pf * 16 * LDSR + ks) * 2;
                uint32_t r0, r1, r2, r3;
                ldm_x4(r0, r1, r2, r3, b_hi_b + off);
                bh[pf * 2 + 0][0] = r0; bh[pf * 2 + 0][1] = r2;
                bh[pf * 2 + 1][0] = r1; bh[pf * 2 + 1][1] = r3;
                ldm_x4(r0, r1, r2, r3, b_lo_b + off);
                bl[pf * 2 + 0][0] = r0; bl[pf * 2 + 0][1] = r2;
                bl[pf * 2 + 1][0] = r1; bl[pf * 2 + 1][1] = r3;
            }
#pragma unroll
            for (int mf = 0; mf < 4; mf++)
#pragma unroll
                for (int nf = 0; nf < 4; nf++) {
                    mma_bf16(acc[mf][nf], ah[mf], bh[nf][0], bh[nf][1]);
                    mma_bf16(acc[mf][nf], al[mf], bh[nf][0], bh[nf][1]);
                    mma_bf16(acc[mf][nf], ah[mf], bl[nf][0], bl[nf][1]);
                }
        }
        __syncthreads();
    }

    // Epilogue
    int gID = lane >> 2, tcol = lane & 3;
#pragma unroll
    for (int mf = 0; mf < 4; mf++) {
#pragma unroll
        for (int nf = 0; nf < 4; nf++) {
            int c = n0 + warp_n * 32 + nf * 8 + tcol * 2;
            float2 bv = *(const float2*)&bias[c];
#pragma unroll
            for (int half = 0; half < 2; half++) {
                int r = m0 + warp_m * 64 + mf * 16 + gID + half * 8;
                float2 v;
                v.x = acc[mf][nf][half * 2 + 0] + bv.x;
                v.y = acc[mf][nf][half * 2 + 1] + bv.y;
                if (mode == 0) {
                    *(float2*)&outp[(size_t)r * EE + c] = v;
                } else {
                    // write Q/K/V bf16 hi/lo in [B,H,S,D]
                    int part = c >> 10, e = c & 1023, h = e >> 6, d0 = e & 63;
                    __nv_bfloat16 *dh, *dl;
                    if (part == 0)      { dh = g_qhi; dl = g_qlo; }
                    else if (part == 1) { dh = g_khi; dl = g_klo; }
                    else                { dh = g_vhi; dl = g_vlo; }
                    int b = r >> 11, s = r & 2047;
                    size_t base = (((size_t)(b * HH + h)) * SS + s) * DD + d0;
                    uint32_t hp = packbf(v.y, v.x);
                    uint32_t lp = packbf(v.y - hif(hp), v.x - lof(hp));
                    *(uint32_t*)&dh[base] = hp;
                    *(uint32_t*)&dl[base] = lp;
                }
            }
        }
    }
}

// ---------------------------------------------------------------------------
// Tensor-core causal flash attention, bf16 3-pass split on QK^T and PV.
// CTA: 128 q-rows x (b,h). 8 warps, each m16 x n64 fragments.
// Dynamic smem, row stride ALD=72 (>=64 cols; 144B stride -> conflict-free).
// ---------------------------------------------------------------------------
#define ALD 72
// element offsets into dynamic smem
#define OFF_QHI 0
#define OFF_QLO (128 * ALD)
#define OFF_KHI (2 * 128 * ALD)
#define OFF_KLO (2 * 128 * ALD + 64 * ALD)
#define OFF_VHI (2 * 128 * ALD + 2 * 64 * ALD)
#define OFF_VLO (2 * 128 * ALD + 3 * 64 * ALD)
#define ATTN_SMEM_ELEMS (2 * 128 * ALD + 4 * 64 * ALD)
#define ATTN_SMEM_BYTES (ATTN_SMEM_ELEMS * 2)

__global__ __launch_bounds__(256) void attn_mma_kernel()
{
    extern __shared__ __nv_bfloat16 dsm[];
    __nv_bfloat16* Qhi_s = dsm + OFF_QHI;
    __nv_bfloat16* Qlo_s = dsm + OFF_QLO;
    __nv_bfloat16* Khi_s = dsm + OFF_KHI;
    __nv_bfloat16* Klo_s = dsm + OFF_KLO;
    __nv_bfloat16* Vhi_s = dsm + OFF_VHI;
    __nv_bfloat16* Vlo_s = dsm + OFF_VLO;

    int qt = gridDim.x - 1 - blockIdx.x;        // big tiles first
    int h  = blockIdx.y;
    int b  = blockIdx.z;
    int tid = threadIdx.x, wid = tid >> 5, lane = tid & 31;

    size_t bh = ((size_t)(b * HH + h)) * SS * DD;
    const __nv_bfloat16* Qhg = g_qhi + bh;
    const __nv_bfloat16* Qlg = g_qlo + bh;
    const __nv_bfloat16* Khg = g_khi + bh;
    const __nv_bfloat16* Klg = g_klo + bh;
    const __nv_bfloat16* Vhg = g_vhi + bh;
    const __nv_bfloat16* Vlg = g_vlo + bh;

    int q0 = qt * 128;

    // Load Q tile (128 x 64) hi/lo
#pragma unroll
    for (int t = 0; t < 4; t++) {
        int i = tid + t * 256;
        int r = i >> 3, v = i & 7;
        size_t src = (size_t)(q0 + r) * DD + v * 8;
        uint32_t so = (uint32_t)(r * ALD + v * 8);
        *(uint4*)&Qhi_s[so] = *(const uint4*)(Qhg + src);
        *(uint4*)&Qlo_s[so] = *(const uint4*)(Qlg + src);
    }

    float o[8][4];
#pragma unroll
    for (int j = 0; j < 8; j++)
#pragma unroll
        for (int e = 0; e < 4; e++) o[j][e] = 0.0f;
    float m_[2] = {-1e30f, -1e30f}, l_[2] = {0.0f, 0.0f};

    int lrow = lane & 15, lcol = lane >> 4;
    uint32_t qb_hi = smem_u32(Qhi_s) +
        (uint32_t)(((wid * 16 + lrow) * ALD + lcol * 8) * 2);
    uint32_t qb_lo = smem_u32(Qlo_s) +
        (uint32_t)(((wid * 16 + lrow) * ALD + lcol * 8) * 2);
    uint32_t kb_hi = smem_u32(Khi_s) + (uint32_t)((lrow * ALD + lcol * 8) * 2);
    uint32_t kb_lo = smem_u32(Klo_s) + (uint32_t)((lrow * ALD + lcol * 8) * 2);
    uint32_t vb_hi = smem_u32(Vhi_s) + (uint32_t)((lrow * ALD + lcol * 8) * 2);
    uint32_t vb_lo = smem_u32(Vlo_s) + (uint32_t)((lrow * ALD + lcol * 8) * 2);

    int row0 = q0 + wid * 16 + (lane >> 2);
    const float scale = 1.0f / 16.0f;   // 1/(sqrt(64)*layer_idx)

    int ktmax = 2 * qt + 1;
    for (int kt = 0; kt <= ktmax; kt++) {
        __syncthreads();
        int k0 = kt * 64;
#pragma unroll
        for (int t = 0; t < 2; t++) {
            int i = tid + t * 256;
            int r = i >> 3, v = i & 7;
            size_t src = (size_t)(k0 + r) * DD + v * 8;
            uint32_t so = (uint32_t)(r * ALD + v * 8);
            *(uint4*)&Khi_s[so] = *(const uint4*)(Khg + src);
            *(uint4*)&Klo_s[so] = *(const uint4*)(Klg + src);
            *(uint4*)&Vhi_s[so] = *(const uint4*)(Vhg + src);
            *(uint4*)&Vlo_s[so] = *(const uint4*)(Vlg + src);
        }
        __syncthreads();

        // ---- S = Q K^T (3-pass bf16 split) ----
        float s[8][4];
#pragma unroll
        for (int nf = 0; nf < 8; nf++)
#pragma unroll
            for (int e = 0; e < 4; e++) s[nf][e] = 0.0f;

#pragma unroll
        for (int ks = 0; ks < 4; ks++) {           // k16 chunks over D=64
            uint32_t ah[4], al[4];
            ldm_x4(ah[0], ah[1], ah[2], ah[3], qb_hi + (uint32_t)(ks * 32));
            ldm_x4(al[0], al[1], al[2], al[3], qb_lo + (uint32_t)(ks * 32));
#pragma unroll
            for (int g = 0; g < 4; g++) {          // 16-col n groups
                uint32_t off = (uint32_t)((g * 16 * ALD + ks * 16) * 2);
                uint32_t r0, r1, r2, r3, t0, t1, t2, t3;
                ldm_x4(r0, r1, r2, r3, kb_hi + off);
                ldm_x4(t0, t1, t2, t3, kb_lo + off);
                mma_bf16(s[2 * g],     ah, r0, r2);
                mma_bf16(s[2 * g],     al, r0, r2);
                mma_bf16(s[2 * g],     ah, t0, t2);
                mma_bf16(s[2 * g + 1], ah, r1, r3);
                mma_bf16(s[2 * g + 1], al, r1, r3);
                mma_bf16(s[2 * g + 1], ah, t1, t3);
            }
        }

        // ---- scale + causal mask ----
        if (kt >= ktmax - 1) {
#pragma unroll
            for (int nf = 0; nf < 8; nf++) {
                int cb = k0 + nf * 8 + (lane & 3) * 2;
#pragma unroll
                for (int e = 0; e < 4; e++) {
                    int col = cb + (e & 1);
                    int row = (e < 2) ? row0 : row0 + 8;
                    float v = s[nf][e] * scale;
                    s[nf][e] = (col > row) ? -10000.0f : v;
                }
            }
        } else {
#pragma unroll
            for (int nf = 0; nf < 8; nf++)
#pragma unroll
                for (int e = 0; e < 4; e++) s[nf][e] *= scale;
        }

        // ---- online softmax (rows i=0: row0, i=1: row0+8) ----
#pragma unroll
        for (int i = 0; i < 2; i++) {
            float mx = -1e30f;
#pragma unroll
            for (int nf = 0; nf < 8; nf++)
                mx = fmaxf(mx, fmaxf(s[nf][2 * i], s[nf][2 * i + 1]));
            mx = fmaxf(mx, __shfl_xor_sync(0xffffffffu, mx, 1));
            mx = fmaxf(mx, __shfl_xor_sync(0xffffffffu, mx, 2));
            float mn = fmaxf(m_[i], mx);
            float alpha = __expf(m_[i] - mn);
            float sum = 0.0f;
#pragma unroll
            for (int nf = 0; nf < 8; nf++) {
                float p0 = __expf(s[nf][2 * i] - mn);
                float p1 = __expf(s[nf][2 * i + 1] - mn);
                s[nf][2 * i] = p0; s[nf][2 * i + 1] = p1;
                sum += p0 + p1;
            }
            sum += __shfl_xor_sync(0xffffffffu, sum, 1);
            sum += __shfl_xor_sync(0xffffffffu, sum, 2);
            l_[i] = l_[i] * alpha + sum;
            m_[i] = mn;
#pragma unroll
            for (int j = 0; j < 8; j++) {
                o[j][2 * i] *= alpha; o[j][2 * i + 1] *= alpha;
            }
        }

        // ---- O += P V (3-pass, P from S frags in-register) ----
#pragma unroll
        for (int c = 0; c < 4; c++) {              // k16 chunks over seq 64
            uint32_t aph[4], apl[4];
            aph[0] = packbf(s[2 * c][1], s[2 * c][0]);
            aph[1] = packbf(s[2 * c][3], s[2 * c][2]);
            aph[2] = packbf(s[2 * c + 1][1], s[2 * c + 1][0]);
            aph[3] = packbf(s[2 * c + 1][3], s[2 * c + 1][2]);
            apl[0] = packbf(s[2 * c][1] - hif(aph[0]), s[2 * c][0] - lof(aph[0]));
            apl[1] = packbf(s[2 * c][3] - hif(aph[1]), s[2 * c][2] - lof(aph[1]));
            apl[2] = packbf(s[2 * c + 1][1] - hif(aph[2]),
                            s[2 * c + 1][0] - lof(aph[2]));
            apl[3] = packbf(s[2 * c + 1][3] - hif(aph[3]),
                            s[2 * c + 1][2] - lof(aph[3]));
#pragma unroll
            for (int g = 0; g < 4; g++) {          // 16-col d groups
                uint32_t off = (uint32_t)((c * 16 * ALD + g * 16) * 2);
                uint32_t r0, r1, r2, r3, t0, t1, t2, t3;
                ldm_x4_t(r0, r1, r2, r3, vb_hi + off);
                ldm_x4_t(t0, t1, t2, t3, vb_lo + off);
                mma_bf16(o[2 * g],     aph, r0, r1);
                mma_bf16(o[2 * g],     apl, r0, r1);
                mma_bf16(o[2 * g],     aph, t0, t1);
                mma_bf16(o[2 * g + 1], aph, r2, r3);
                mma_bf16(o[2 * g + 1], apl, r2, r3);
                mma_bf16(o[2 * g + 1], aph, t2, t3);
            }
        }
    }

    // ---- epilogue: O/l -> bf16 hi/lo merged-head [B*S, E] ----
    float inv0 = 1.0f / l_[0], inv1 = 1.0f / l_[1];
    int d0 = (lane & 3) * 2;
    size_t rb0 = ((size_t)(b * SS + row0)) * EE + h * DD;
    size_t rb1 = rb0 + (size_t)8 * EE;
#pragma unroll
    for (int j = 0; j < 8; j++) {
        int d = j * 8 + d0;
        float v0 = o[j][0] * inv0, v1 = o[j][1] * inv0;
        float v2 = o[j][2] * inv1, v3 = o[j][3] * inv1;
        uint32_t h01 = packbf(v1, v0);
        uint32_t l01 = packbf(v1 - hif(h01), v0 - lof(h01));
        uint32_t h23 = packbf(v3, v2);
        uint32_t l23 = packbf(v3 - hif(h23), v2 - lof(h23));
        *(uint32_t*)&g_ahi[rb0 + d] = h01;
        *(uint32_t*)&g_alo[rb0 + d] = l01;
        *(uint32_t*)&g_ahi[rb1 + d] = h23;
        *(uint32_t*)&g_alo[rb1 + d] = l23;
    }
}

// ---------------------------------------------------------------------------
extern "C" void kernel_launch(void* const* d_in, const int* in_sizes, int n_in,
                              void* d_out, int out_size)
{
    const float* hidden = (const float*)d_in[0];   // [B,S,E]
    const float* w_attn = (const float*)d_in[1];   // [E, 3E]
    const float* b_attn = (const float*)d_in[2];   // [3E]
    const float* w_proj = (const float*)d_in[3];   // [E, E]
    const float* b_proj = (const float*)d_in[4];   // [E]
    float* out = (float*)d_out;                    // [B,S,E] fp32

    // Prep: bf16 hi/lo splits (+ weight transposes)
    split_kernel<<<(MROWS * KDIM) / (256 * 4), 256>>>(hidden);
    tsplit_kernel<<<dim3(N_QKV / 32, KDIM / 32), 256>>>(w_attn, 0, N_QKV);
    tsplit_kernel<<<dim3(EE / 32, KDIM / 32), 256>>>(w_proj, 1, EE);

    // 1) QKV GEMM (tensor cores) -> Q/K/V bf16 hi/lo [B,H,S,D]
    mma_gemm<<<dim3(N_QKV / 128, MROWS / 128), 256>>>(b_attn, nullptr, 1);

    // 2) Causal flash attention (tensor cores, 3-pass split both GEMMs)
    cudaFuncSetAttribute(attn_mma_kernel,
                         cudaFuncAttributeMaxDynamicSharedMemorySize,
                         ATTN_SMEM_BYTES);
    attn_mma_kernel<<<dim3(SS / 128, HH, BB), 256, ATTN_SMEM_BYTES>>>();

    // 3) Output projection -> d_out
    mma_gemm<<<dim3(EE / 128, MROWS / 128), 256>>>(b_proj, out, 0);
}

// round 6
// speedup vs baseline: 2.3861x; 1.1173x over previous
#include <cuda_runtime.h>
#include <cuda_bf16.h>
#include <cstdint>
#include <math.h>

// Problem constants
#define BB 2
#define SS 2048
#define EE 1024
#define HH 16
#define DD 64
#define MROWS (BB*SS)          // 4096
#define KDIM 1024
#define N_QKV 3072

// ---------------------------------------------------------------------------
// Scratch (allocation-free: device globals)
// ---------------------------------------------------------------------------
__device__ __nv_bfloat16 g_qhi[BB*HH*SS*DD];
__device__ __nv_bfloat16 g_qlo[BB*HH*SS*DD];
__device__ __nv_bfloat16 g_khi[BB*HH*SS*DD];
__device__ __nv_bfloat16 g_klo[BB*HH*SS*DD];
__device__ __nv_bfloat16 g_vhi[BB*HH*SS*DD];
__device__ __nv_bfloat16 g_vlo[BB*HH*SS*DD];

__device__ __nv_bfloat16 g_hhi[MROWS*KDIM];     // hidden hi
__device__ __nv_bfloat16 g_hlo[MROWS*KDIM];     // hidden lo
__device__ __nv_bfloat16 g_ahi[MROWS*KDIM];     // attn-out hi (merged heads)
__device__ __nv_bfloat16 g_alo[MROWS*KDIM];     // attn-out lo
__device__ __nv_bfloat16 g_wqkvThi[N_QKV*KDIM]; // w_attn^T hi  [3072,1024]
__device__ __nv_bfloat16 g_wqkvTlo[N_QKV*KDIM];
__device__ __nv_bfloat16 g_wprojThi[EE*KDIM];   // w_proj^T hi  [1024,1024]
__device__ __nv_bfloat16 g_wprojTlo[EE*KDIM];

// ---------------------------------------------------------------------------
// PTX helpers
// ---------------------------------------------------------------------------
__device__ __forceinline__ uint32_t smem_u32(const void* p) {
    uint32_t a;
    asm("{ .reg .u64 t; cvta.to.shared.u64 t, %1; cvt.u32.u64 %0, t; }"
        : "=r"(a) : "l"(p));
    return a;
}

__device__ __forceinline__ void ldm_x4(uint32_t& r0, uint32_t& r1,
                                       uint32_t& r2, uint32_t& r3,
                                       uint32_t addr) {
    asm volatile("ldmatrix.sync.aligned.m8n8.x4.shared.b16 {%0,%1,%2,%3}, [%4];"
                 : "=r"(r0), "=r"(r1), "=r"(r2), "=r"(r3) : "r"(addr));
}
__device__ __forceinline__ void ldm_x4_t(uint32_t& r0, uint32_t& r1,
                                         uint32_t& r2, uint32_t& r3,
                                         uint32_t addr) {
    asm volatile("ldmatrix.sync.aligned.m8n8.x4.trans.shared.b16 {%0,%1,%2,%3}, [%4];"
                 : "=r"(r0), "=r"(r1), "=r"(r2), "=r"(r3) : "r"(addr));
}

__device__ __forceinline__ void mma_bf16(float* d, const uint32_t* a,
                                         uint32_t b0, uint32_t b1) {
    asm volatile(
        "mma.sync.aligned.m16n8k16.row.col.f32.bf16.bf16.f32 "
        "{%0,%1,%2,%3}, {%4,%5,%6,%7}, {%8,%9}, {%0,%1,%2,%3};"
        : "+f"(d[0]), "+f"(d[1]), "+f"(d[2]), "+f"(d[3])
        : "r"(a[0]), "r"(a[1]), "r"(a[2]), "r"(a[3]), "r"(b0), "r"(b1));
}

__device__ __forceinline__ void cpa16(uint32_t dst, const void* src) {
    asm volatile("cp.async.cg.shared.global [%0], [%1], 16;"
                 :: "r"(dst), "l"(src));
}
#define CPA_COMMIT() asm volatile("cp.async.commit_group;" ::: "memory")
#define CPA_WAIT(n)  asm volatile("cp.async.wait_group %0;" :: "n"(n) : "memory")

__device__ __forceinline__ uint32_t packbf(float hi, float lo) {
    uint32_t d;
    asm("cvt.rn.bf16x2.f32 %0, %1, %2;" : "=r"(d) : "f"(hi), "f"(lo));
    return d;
}
__device__ __forceinline__ float lof(uint32_t u) {
    return __uint_as_float(u << 16);
}
__device__ __forceinline__ float hif(uint32_t u) {
    return __uint_as_float(u & 0xffff0000u);
}

// ---------------------------------------------------------------------------
// Prep kernel 1: split fp32 -> bf16 hi/lo (hidden only)
// ---------------------------------------------------------------------------
__global__ __launch_bounds__(256) void split_kernel(const float* __restrict__ x)
{
    size_t i0 = ((size_t)blockIdx.x * 256 + threadIdx.x) * 4;
    float4 v = *(const float4*)&x[i0];
    __nv_bfloat16 h0 = __float2bfloat16(v.x);
    __nv_bfloat16 h1 = __float2bfloat16(v.y);
    __nv_bfloat16 h2 = __float2bfloat16(v.z);
    __nv_bfloat16 h3 = __float2bfloat16(v.w);
    __nv_bfloat162 hp0; hp0.x = h0; hp0.y = h1;
    __nv_bfloat162 hp1; hp1.x = h2; hp1.y = h3;
    __nv_bfloat162 lp0;
    lp0.x = __float2bfloat16(v.x - __bfloat162float(h0));
    lp0.y = __float2bfloat16(v.y - __bfloat162float(h1));
    __nv_bfloat162 lp1;
    lp1.x = __float2bfloat16(v.z - __bfloat162float(h2));
    lp1.y = __float2bfloat16(v.w - __bfloat162float(h3));
    *(__nv_bfloat162*)&g_hhi[i0]     = hp0;
    *(__nv_bfloat162*)&g_hhi[i0 + 2] = hp1;
    *(__nv_bfloat162*)&g_hlo[i0]     = lp0;
    *(__nv_bfloat162*)&g_hlo[i0 + 2] = lp1;
}

// ---------------------------------------------------------------------------
// Prep kernel 2: W [K,N] row-major -> W^T [N,K] bf16 hi/lo
// ---------------------------------------------------------------------------
__global__ __launch_bounds__(256) void tsplit_kernel(const float* __restrict__ W,
                                                     int which, int N)
{
    __nv_bfloat16* Thi = which ? g_wprojThi : g_wqkvThi;
    __nv_bfloat16* Tlo = which ? g_wprojTlo : g_wqkvTlo;
    __shared__ float t[32][33];
    int n0 = blockIdx.x * 32, k0 = blockIdx.y * 32;
    int tx = threadIdx.x & 31, ty = threadIdx.x >> 5;   // ty 0..7
#pragma unroll
    for (int r = 0; r < 32; r += 8)
        t[ty + r][tx] = W[(size_t)(k0 + ty + r) * N + n0 + tx];
    __syncthreads();
#pragma unroll
    for (int r = 0; r < 32; r += 8) {
        float v = t[tx][ty + r];
        __nv_bfloat16 h = __float2bfloat16(v);
        size_t o = (size_t)(n0 + ty + r) * KDIM + k0 + tx;
        Thi[o] = h;
        Tlo[o] = __float2bfloat16(v - __bfloat162float(h));
    }
}

// ---------------------------------------------------------------------------
// Tensor-core GEMM via mma.sync bf16 3-pass split, 2-stage cp.async pipeline.
// mode 1: A = hidden split, B = w_attn^T split -> Q/K/V bf16 hi/lo [B,H,S,D]
// mode 0: A = attn split,   B = w_proj^T split -> row-major fp32 outp
// ---------------------------------------------------------------------------
#define BK 32
#define LDSR 40   // smem row stride for 32-col tiles (80B: conflict-free ldmatrix)
#define ARR_ELEMS (128 * LDSR)                 // one hi/lo tile array
#define STAGE_ELEMS (4 * ARR_ELEMS)            // Ahi,Alo,Bhi,Blo
#define GEMM_SMEM_BYTES (2 * STAGE_ELEMS * 2)  // 2 stages, bf16

__global__ __launch_bounds__(256, 2) void mma_gemm(const float* __restrict__ bias,
                                                   float* __restrict__ outp,
                                                   int mode)
{
    extern __shared__ __nv_bfloat16 gsm[];
    uint32_t sbase = smem_u32(gsm);

    const __nv_bfloat16* Ahi = mode ? g_hhi : g_ahi;
    const __nv_bfloat16* Alo = mode ? g_hlo : g_alo;
    const __nv_bfloat16* Bhi = mode ? g_wqkvThi : g_wprojThi;
    const __nv_bfloat16* Blo = mode ? g_wqkvTlo : g_wprojTlo;

    int tid = threadIdx.x;
    int wid = tid >> 5, lane = tid & 31;
    int warp_m = wid & 1, warp_n = wid >> 1;          // 2 x 4
    int m0 = blockIdx.y * 128, n0 = blockIdx.x * 128;

    float acc[4][4][4];
#pragma unroll
    for (int i = 0; i < 4; i++)
#pragma unroll
        for (int j = 0; j < 4; j++)
#pragma unroll
            for (int r = 0; r < 4; r++) acc[i][j][r] = 0.0f;

    // per-thread load coordinates (8 cp.asyncs per stage)
    int lr = tid >> 1;                // row 0..127
    int lv0 = (tid & 1) * 2;          // vec 0 or 2 (each vec = 8 bf16)

    // issue one stage's loads
    auto load_stage = [&](int st, int kc) {
        uint32_t sb = sbase + (uint32_t)(st * STAGE_ELEMS * 2);
#pragma unroll
        for (int vv = 0; vv < 2; vv++) {
            int v = lv0 + vv;
            size_t asrc = (size_t)(m0 + lr) * KDIM + kc + v * 8;
            size_t bsrc = (size_t)(n0 + lr) * KDIM + kc + v * 8;
            uint32_t so = (uint32_t)((lr * LDSR + v * 8) * 2);
            cpa16(sb + so,                       Ahi + asrc);
            cpa16(sb + so + ARR_ELEMS * 2,       Alo + asrc);
            cpa16(sb + so + 2 * ARR_ELEMS * 2,   Bhi + bsrc);
            cpa16(sb + so + 3 * ARR_ELEMS * 2,   Blo + bsrc);
        }
    };

    int lrow = lane & 15, lcol = lane >> 4;
    uint32_t a_off = (uint32_t)(((warp_m * 64 + lrow) * LDSR + lcol * 8) * 2);
    uint32_t b_off = (uint32_t)(((warp_n * 32 + lrow) * LDSR + lcol * 8) * 2);

    load_stage(0, 0);
    CPA_COMMIT();

    const int NITER = KDIM / BK;      // 32
    for (int c = 0; c < NITER; c++) {
        if (c + 1 < NITER) {
            load_stage((c + 1) & 1, (c + 1) * BK);
            CPA_COMMIT();
            CPA_WAIT(1);
        } else {
            CPA_WAIT(0);
        }
        __syncthreads();

        uint32_t sb = sbase + (uint32_t)((c & 1) * STAGE_ELEMS * 2);
        uint32_t a_hi_b = sb + a_off;
        uint32_t a_lo_b = sb + ARR_ELEMS * 2 + a_off;
        uint32_t b_hi_b = sb + 2 * ARR_ELEMS * 2 + b_off;
        uint32_t b_lo_b = sb + 3 * ARR_ELEMS * 2 + b_off;

#pragma unroll
        for (int ks = 0; ks < BK; ks += 16) {
            uint32_t ah[4][4], al[4][4];
#pragma unroll
            for (int mf = 0; mf < 4; mf++) {
                uint32_t off = (uint32_t)(mf * 16 * LDSR + ks) * 2;
                ldm_x4(ah[mf][0], ah[mf][1], ah[mf][2], ah[mf][3], a_hi_b + off);
                ldm_x4(al[mf][0], al[mf][1], al[mf][2], al[mf][3], a_lo_b + off);
            }
            uint32_t bh[4][2], bl[4][2];
#pragma unroll
            for (int pf = 0; pf < 2; pf++) {
                uint32_t off = (uint32_t)(pf * 16 * LDSR + ks) * 2;
                uint32_t r0, r1, r2, r3;
                ldm_x4(r0, r1, r2, r3, b_hi_b + off);
                bh[pf * 2 + 0][0] = r0; bh[pf * 2 + 0][1] = r2;
                bh[pf * 2 + 1][0] = r1; bh[pf * 2 + 1][1] = r3;
                ldm_x4(r0, r1, r2, r3, b_lo_b + off);
                bl[pf * 2 + 0][0] = r0; bl[pf * 2 + 0][1] = r2;
                bl[pf * 2 + 1][0] = r1; bl[pf * 2 + 1][1] = r3;
            }
#pragma unroll
            for (int mf = 0; mf < 4; mf++)
#pragma unroll
                for (int nf = 0; nf < 4; nf++) {
                    mma_bf16(acc[mf][nf], ah[mf], bh[nf][0], bh[nf][1]);
                    mma_bf16(acc[mf][nf], al[mf], bh[nf][0], bh[nf][1]);
                    mma_bf16(acc[mf][nf], ah[mf], bl[nf][0], bl[nf][1]);
                }
        }
        __syncthreads();
    }

    // Epilogue
    int gID = lane >> 2, tcol = lane & 3;
#pragma unroll
    for (int mf = 0; mf < 4; mf++) {
#pragma unroll
        for (int nf = 0; nf < 4; nf++) {
            int c = n0 + warp_n * 32 + nf * 8 + tcol * 2;
            float2 bv = *(const float2*)&bias[c];
#pragma unroll
            for (int half = 0; half < 2; half++) {
                int r = m0 + warp_m * 64 + mf * 16 + gID + half * 8;
                float2 v;
                v.x = acc[mf][nf][half * 2 + 0] + bv.x;
                v.y = acc[mf][nf][half * 2 + 1] + bv.y;
                if (mode == 0) {
                    *(float2*)&outp[(size_t)r * EE + c] = v;
                } else {
                    int part = c >> 10, e = c & 1023, h = e >> 6, d0 = e & 63;
                    __nv_bfloat16 *dh, *dl;
                    if (part == 0)      { dh = g_qhi; dl = g_qlo; }
                    else if (part == 1) { dh = g_khi; dl = g_klo; }
                    else                { dh = g_vhi; dl = g_vlo; }
                    int b = r >> 11, s = r & 2047;
                    size_t base = (((size_t)(b * HH + h)) * SS + s) * DD + d0;
                    uint32_t hp = packbf(v.y, v.x);
                    uint32_t lp = packbf(v.y - hif(hp), v.x - lof(hp));
                    *(uint32_t*)&dh[base] = hp;
                    *(uint32_t*)&dl[base] = lp;
                }
            }
        }
    }
}

// ---------------------------------------------------------------------------
// Tensor-core causal flash attention, bf16 3-pass split on QK^T and PV.
// CTA: 128 q-rows x (b,h). 8 warps, each m16 x n64 fragments.
// ---------------------------------------------------------------------------
#define ALD 72
#define OFF_QHI 0
#define OFF_QLO (128 * ALD)
#define OFF_KHI (2 * 128 * ALD)
#define OFF_KLO (2 * 128 * ALD + 64 * ALD)
#define OFF_VHI (2 * 128 * ALD + 2 * 64 * ALD)
#define OFF_VLO (2 * 128 * ALD + 3 * 64 * ALD)
#define ATTN_SMEM_ELEMS (2 * 128 * ALD + 4 * 64 * ALD)
#define ATTN_SMEM_BYTES (ATTN_SMEM_ELEMS * 2)

__global__ __launch_bounds__(256) void attn_mma_kernel()
{
    extern __shared__ __nv_bfloat16 dsm[];
    __nv_bfloat16* Qhi_s = dsm + OFF_QHI;
    __nv_bfloat16* Qlo_s = dsm + OFF_QLO;
    __nv_bfloat16* Khi_s = dsm + OFF_KHI;
    __nv_bfloat16* Klo_s = dsm + OFF_KLO;
    __nv_bfloat16* Vhi_s = dsm + OFF_VHI;
    __nv_bfloat16* Vlo_s = dsm + OFF_VLO;

    int qt = gridDim.x - 1 - blockIdx.x;        // big tiles first
    int h  = blockIdx.y;
    int b  = blockIdx.z;
    int tid = threadIdx.x, wid = tid >> 5, lane = tid & 31;

    size_t bh = ((size_t)(b * HH + h)) * SS * DD;
    const __nv_bfloat16* Qhg = g_qhi + bh;
    const __nv_bfloat16* Qlg = g_qlo + bh;
    const __nv_bfloat16* Khg = g_khi + bh;
    const __nv_bfloat16* Klg = g_klo + bh;
    const __nv_bfloat16* Vhg = g_vhi + bh;
    const __nv_bfloat16* Vlg = g_vlo + bh;

    int q0 = qt * 128;

#pragma unroll
    for (int t = 0; t < 4; t++) {
        int i = tid + t * 256;
        int r = i >> 3, v = i & 7;
        size_t src = (size_t)(q0 + r) * DD + v * 8;
        uint32_t so = (uint32_t)(r * ALD + v * 8);
        *(uint4*)&Qhi_s[so] = *(const uint4*)(Qhg + src);
        *(uint4*)&Qlo_s[so] = *(const uint4*)(Qlg + src);
    }

    float o[8][4];
#pragma unroll
    for (int j = 0; j < 8; j++)
#pragma unroll
        for (int e = 0; e < 4; e++) o[j][e] = 0.0f;
    float m_[2] = {-1e30f, -1e30f}, l_[2] = {0.0f, 0.0f};

    int lrow = lane & 15, lcol = lane >> 4;
    uint32_t qb_hi = smem_u32(Qhi_s) +
        (uint32_t)(((wid * 16 + lrow) * ALD + lcol * 8) * 2);
    uint32_t qb_lo = smem_u32(Qlo_s) +
        (uint32_t)(((wid * 16 + lrow) * ALD + lcol * 8) * 2);
    uint32_t kb_hi = smem_u32(Khi_s) + (uint32_t)((lrow * ALD + lcol * 8) * 2);
    uint32_t kb_lo = smem_u32(Klo_s) + (uint32_t)((lrow * ALD + lcol * 8) * 2);
    uint32_t vb_hi = smem_u32(Vhi_s) + (uint32_t)((lrow * ALD + lcol * 8) * 2);
    uint32_t vb_lo = smem_u32(Vlo_s) + (uint32_t)((lrow * ALD + lcol * 8) * 2);

    int row0 = q0 + wid * 16 + (lane >> 2);
    const float scale = 1.0f / 16.0f;

    int ktmax = 2 * qt + 1;
    for (int kt = 0; kt <= ktmax; kt++) {
        __syncthreads();
        int k0 = kt * 64;
#pragma unroll
        for (int t = 0; t < 2; t++) {
            int i = tid + t * 256;
            int r = i >> 3, v = i & 7;
            size_t src = (size_t)(k0 + r) * DD + v * 8;
            uint32_t so = (uint32_t)(r * ALD + v * 8);
            *(uint4*)&Khi_s[so] = *(const uint4*)(Khg + src);
            *(uint4*)&Klo_s[so] = *(const uint4*)(Klg + src);
            *(uint4*)&Vhi_s[so] = *(const uint4*)(Vhg + src);
            *(uint4*)&Vlo_s[so] = *(const uint4*)(Vlg + src);
        }
        __syncthreads();

        float s[8][4];
#pragma unroll
        for (int nf = 0; nf < 8; nf++)
#pragma unroll
            for (int e = 0; e < 4; e++) s[nf][e] = 0.0f;

#pragma unroll
        for (int ks = 0; ks < 4; ks++) {
            uint32_t ah[4], al[4];
            ldm_x4(ah[0], ah[1], ah[2], ah[3], qb_hi + (uint32_t)(ks * 32));
            ldm_x4(al[0], al[1], al[2], al[3], qb_lo + (uint32_t)(ks * 32));
#pragma unroll
            for (int g = 0; g < 4; g++) {
                uint32_t off = (uint32_t)((g * 16 * ALD + ks * 16) * 2);
                uint32_t r0, r1, r2, r3, t0, t1, t2, t3;
                ldm_x4(r0, r1, r2, r3, kb_hi + off);
                ldm_x4(t0, t1, t2, t3, kb_lo + off);
                mma_bf16(s[2 * g],     ah, r0, r2);
                mma_bf16(s[2 * g],     al, r0, r2);
                mma_bf16(s[2 * g],     ah, t0, t2);
                mma_bf16(s[2 * g + 1], ah, r1, r3);
                mma_bf16(s[2 * g + 1], al, r1, r3);
                mma_bf16(s[2 * g + 1], ah, t1, t3);
            }
        }

        if (kt >= ktmax - 1) {
#pragma unroll
            for (int nf = 0; nf < 8; nf++) {
                int cb = k0 + nf * 8 + (lane & 3) * 2;
#pragma unroll
                for (int e = 0; e < 4; e++) {
                    int col = cb + (e & 1);
                    int row = (e < 2) ? row0 : row0 + 8;
                    float v = s[nf][e] * scale;
                    s[nf][e] = (col > row) ? -10000.0f : v;
                }
            }
        } else {
#pragma unroll
            for (int nf = 0; nf < 8; nf++)
#pragma unroll
                for (int e = 0; e < 4; e++) s[nf][e] *= scale;
        }

#pragma unroll
        for (int i = 0; i < 2; i++) {
            float mx = -1e30f;
#pragma unroll
            for (int nf = 0; nf < 8; nf++)
                mx = fmaxf(mx, fmaxf(s[nf][2 * i], s[nf][2 * i + 1]));
            mx = fmaxf(mx, __shfl_xor_sync(0xffffffffu, mx, 1));
            mx = fmaxf(mx, __shfl_xor_sync(0xffffffffu, mx, 2));
            float mn = fmaxf(m_[i], mx);
            float alpha = __expf(m_[i] - mn);
            float sum = 0.0f;
#pragma unroll
            for (int nf = 0; nf < 8; nf++) {
                float p0 = __expf(s[nf][2 * i] - mn);
                float p1 = __expf(s[nf][2 * i + 1] - mn);
                s[nf][2 * i] = p0; s[nf][2 * i + 1] = p1;
                sum += p0 + p1;
            }
            sum += __shfl_xor_sync(0xffffffffu, sum, 1);
            sum += __shfl_xor_sync(0xffffffffu, sum, 2);
            l_[i] = l_[i] * alpha + sum;
            m_[i] = mn;
#pragma unroll
            for (int j = 0; j < 8; j++) {
                o[j][2 * i] *= alpha; o[j][2 * i + 1] *= alpha;
            }
        }

#pragma unroll
        for (int c = 0; c < 4; c++) {
            uint32_t aph[4], apl[4];
            aph[0] = packbf(s[2 * c][1], s[2 * c][0]);
            aph[1] = packbf(s[2 * c][3], s[2 * c][2]);
            aph[2] = packbf(s[2 * c + 1][1], s[2 * c + 1][0]);
            aph[3] = packbf(s[2 * c + 1][3], s[2 * c + 1][2]);
            apl[0] = packbf(s[2 * c][1] - hif(aph[0]), s[2 * c][0] - lof(aph[0]));
            apl[1] = packbf(s[2 * c][3] - hif(aph[1]), s[2 * c][2] - lof(aph[1]));
            apl[2] = packbf(s[2 * c + 1][1] - hif(aph[2]),
                            s[2 * c + 1][0] - lof(aph[2]));
            apl[3] = packbf(s[2 * c + 1][3] - hif(aph[3]),
                            s[2 * c + 1][2] - lof(aph[3]));
#pragma unroll
            for (int g = 0; g < 4; g++) {
                uint32_t off = (uint32_t)((c * 16 * ALD + g * 16) * 2);
                uint32_t r0, r1, r2, r3, t0, t1, t2, t3;
                ldm_x4_t(r0, r1, r2, r3, vb_hi + off);
                ldm_x4_t(t0, t1, t2, t3, vb_lo + off);
                mma_bf16(o[2 * g],     aph, r0, r1);
                mma_bf16(o[2 * g],     apl, r0, r1);
                mma_bf16(o[2 * g],     aph, t0, t1);
                mma_bf16(o[2 * g + 1], aph, r2, r3);
                mma_bf16(o[2 * g + 1], apl, r2, r3);
                mma_bf16(o[2 * g + 1], aph, t2, t3);
            }
        }
    }

    float inv0 = 1.0f / l_[0], inv1 = 1.0f / l_[1];
    int d0 = (lane & 3) * 2;
    size_t rb0 = ((size_t)(b * SS + row0)) * EE + h * DD;
    size_t rb1 = rb0 + (size_t)8 * EE;
#pragma unroll
    for (int j = 0; j < 8; j++) {
        int d = j * 8 + d0;
        float v0 = o[j][0] * inv0, v1 = o[j][1] * inv0;
        float v2 = o[j][2] * inv1, v3 = o[j][3] * inv1;
        uint32_t h01 = packbf(v1, v0);
        uint32_t l01 = packbf(v1 - hif(h01), v0 - lof(h01));
        uint32_t h23 = packbf(v3, v2);
        uint32_t l23 = packbf(v3 - hif(h23), v2 - lof(h23));
        *(uint32_t*)&g_ahi[rb0 + d] = h01;
        *(uint32_t*)&g_alo[rb0 + d] = l01;
        *(uint32_t*)&g_ahi[rb1 + d] = h23;
        *(uint32_t*)&g_alo[rb1 + d] = l23;
    }
}

// ---------------------------------------------------------------------------
extern "C" void kernel_launch(void* const* d_in, const int* in_sizes, int n_in,
                              void* d_out, int out_size)
{
    const float* hidden = (const float*)d_in[0];   // [B,S,E]
    const float* w_attn = (const float*)d_in[1];   // [E, 3E]
    const float* b_attn = (const float*)d_in[2];   // [3E]
    const float* w_proj = (const float*)d_in[3];   // [E, E]
    const float* b_proj = (const float*)d_in[4];   // [E]
    float* out = (float*)d_out;                    // [B,S,E] fp32

    // Prep: bf16 hi/lo splits (+ weight transposes)
    split_kernel<<<(MROWS * KDIM) / (256 * 4), 256>>>(hidden);
    tsplit_kernel<<<dim3(N_QKV / 32, KDIM / 32), 256>>>(w_attn, 0, N_QKV);
    tsplit_kernel<<<dim3(EE / 32, KDIM / 32), 256>>>(w_proj, 1, EE);

    // 1) QKV GEMM (tensor cores, pipelined) -> Q/K/V bf16 hi/lo [B,H,S,D]
    cudaFuncSetAttribute(mma_gemm, cudaFuncAttributeMaxDynamicSharedMemorySize,
                         GEMM_SMEM_BYTES);
    mma_gemm<<<dim3(N_QKV / 128, MROWS / 128), 256, GEMM_SMEM_BYTES>>>(
        b_attn, nullptr, 1);

    // 2) Causal flash attention (tensor cores, 3-pass split both GEMMs)
    cudaFuncSetAttribute(attn_mma_kernel,
                         cudaFuncAttributeMaxDynamicSharedMemorySize,
                         ATTN_SMEM_BYTES);
    attn_mma_kernel<<<dim3(SS / 128, HH, BB), 256, ATTN_SMEM_BYTES>>>();

    // 3) Output projection -> d_out
    mma_gemm<<<dim3(EE / 128, MROWS / 128), 256, GEMM_SMEM_BYTES>>>(
        b_proj, out, 0);
}

// round 7
// speedup vs baseline: 2.5391x; 1.0641x over previous
#include <cuda_runtime.h>
#include <cuda_bf16.h>
#include <cstdint>
#include <math.h>

// Problem constants
#define BB 2
#define SS 2048
#define EE 1024
#define HH 16
#define DD 64
#define MROWS (BB*SS)          // 4096
#define KDIM 1024
#define N_QKV 3072

// ---------------------------------------------------------------------------
// Scratch (allocation-free: device globals)
// ---------------------------------------------------------------------------
__device__ __nv_bfloat16 g_qhi[BB*HH*SS*DD];
__device__ __nv_bfloat16 g_qlo[BB*HH*SS*DD];
__device__ __nv_bfloat16 g_khi[BB*HH*SS*DD];
__device__ __nv_bfloat16 g_klo[BB*HH*SS*DD];
__device__ __nv_bfloat16 g_vhi[BB*HH*SS*DD];
__device__ __nv_bfloat16 g_vlo[BB*HH*SS*DD];

__device__ __nv_bfloat16 g_hhi[MROWS*KDIM];     // hidden hi
__device__ __nv_bfloat16 g_hlo[MROWS*KDIM];     // hidden lo
__device__ __nv_bfloat16 g_ahi[MROWS*KDIM];     // attn-out hi (merged heads)
__device__ __nv_bfloat16 g_alo[MROWS*KDIM];     // attn-out lo
__device__ __nv_bfloat16 g_wqkvThi[N_QKV*KDIM]; // w_attn^T hi
__device__ __nv_bfloat16 g_wqkvTlo[N_QKV*KDIM];
__device__ __nv_bfloat16 g_wprojThi[EE*KDIM];   // w_proj^T hi
__device__ __nv_bfloat16 g_wprojTlo[EE*KDIM];

// ---------------------------------------------------------------------------
// PTX helpers
// ---------------------------------------------------------------------------
__device__ __forceinline__ uint32_t smem_u32(const void* p) {
    uint32_t a;
    asm("{ .reg .u64 t; cvta.to.shared.u64 t, %1; cvt.u32.u64 %0, t; }"
        : "=r"(a) : "l"(p));
    return a;
}

__device__ __forceinline__ void ldm_x4(uint32_t& r0, uint32_t& r1,
                                       uint32_t& r2, uint32_t& r3,
                                       uint32_t addr) {
    asm volatile("ldmatrix.sync.aligned.m8n8.x4.shared.b16 {%0,%1,%2,%3}, [%4];"
                 : "=r"(r0), "=r"(r1), "=r"(r2), "=r"(r3) : "r"(addr));
}
__device__ __forceinline__ void ldm_x4_t(uint32_t& r0, uint32_t& r1,
                                         uint32_t& r2, uint32_t& r3,
                                         uint32_t addr) {
    asm volatile("ldmatrix.sync.aligned.m8n8.x4.trans.shared.b16 {%0,%1,%2,%3}, [%4];"
                 : "=r"(r0), "=r"(r1), "=r"(r2), "=r"(r3) : "r"(addr));
}

__device__ __forceinline__ void mma_bf16(float* d, const uint32_t* a,
                                         uint32_t b0, uint32_t b1) {
    asm volatile(
        "mma.sync.aligned.m16n8k16.row.col.f32.bf16.bf16.f32 "
        "{%0,%1,%2,%3}, {%4,%5,%6,%7}, {%8,%9}, {%0,%1,%2,%3};"
        : "+f"(d[0]), "+f"(d[1]), "+f"(d[2]), "+f"(d[3])
        : "r"(a[0]), "r"(a[1]), "r"(a[2]), "r"(a[3]), "r"(b0), "r"(b1));
}

__device__ __forceinline__ void cpa16(uint32_t dst, const void* src) {
    asm volatile("cp.async.cg.shared.global [%0], [%1], 16;"
                 :: "r"(dst), "l"(src));
}
#define CPA_COMMIT() asm volatile("cp.async.commit_group;" ::: "memory")
#define CPA_WAIT(n)  asm volatile("cp.async.wait_group %0;" :: "n"(n) : "memory")

__device__ __forceinline__ uint32_t packbf(float hi, float lo) {
    uint32_t d;
    asm("cvt.rn.bf16x2.f32 %0, %1, %2;" : "=r"(d) : "f"(hi), "f"(lo));
    return d;
}
__device__ __forceinline__ float lof(uint32_t u) {
    return __uint_as_float(u << 16);
}
__device__ __forceinline__ float hif(uint32_t u) {
    return __uint_as_float(u & 0xffff0000u);
}

// ---------------------------------------------------------------------------
// Prep kernel 1: split fp32 -> bf16 hi/lo (hidden only)
// ---------------------------------------------------------------------------
__global__ __launch_bounds__(256) void split_kernel(const float* __restrict__ x)
{
    size_t i0 = ((size_t)blockIdx.x * 256 + threadIdx.x) * 4;
    float4 v = *(const float4*)&x[i0];
    __nv_bfloat16 h0 = __float2bfloat16(v.x);
    __nv_bfloat16 h1 = __float2bfloat16(v.y);
    __nv_bfloat16 h2 = __float2bfloat16(v.z);
    __nv_bfloat16 h3 = __float2bfloat16(v.w);
    __nv_bfloat162 hp0; hp0.x = h0; hp0.y = h1;
    __nv_bfloat162 hp1; hp1.x = h2; hp1.y = h3;
    __nv_bfloat162 lp0;
    lp0.x = __float2bfloat16(v.x - __bfloat162float(h0));
    lp0.y = __float2bfloat16(v.y - __bfloat162float(h1));
    __nv_bfloat162 lp1;
    lp1.x = __float2bfloat16(v.z - __bfloat162float(h2));
    lp1.y = __float2bfloat16(v.w - __bfloat162float(h3));
    *(__nv_bfloat162*)&g_hhi[i0]     = hp0;
    *(__nv_bfloat162*)&g_hhi[i0 + 2] = hp1;
    *(__nv_bfloat162*)&g_hlo[i0]     = lp0;
    *(__nv_bfloat162*)&g_hlo[i0 + 2] = lp1;
}

// ---------------------------------------------------------------------------
// Prep kernel 2: W [K,N] row-major -> W^T [N,K] bf16 hi/lo
// ---------------------------------------------------------------------------
__global__ __launch_bounds__(256) void tsplit_kernel(const float* __restrict__ W,
                                                     int which, int N)
{
    __nv_bfloat16* Thi = which ? g_wprojThi : g_wqkvThi;
    __nv_bfloat16* Tlo = which ? g_wprojTlo : g_wqkvTlo;
    __shared__ float t[32][33];
    int n0 = blockIdx.x * 32, k0 = blockIdx.y * 32;
    int tx = threadIdx.x & 31, ty = threadIdx.x >> 5;
#pragma unroll
    for (int r = 0; r < 32; r += 8)
        t[ty + r][tx] = W[(size_t)(k0 + ty + r) * N + n0 + tx];
    __syncthreads();
#pragma unroll
    for (int r = 0; r < 32; r += 8) {
        float v = t[tx][ty + r];
        __nv_bfloat16 h = __float2bfloat16(v);
        size_t o = (size_t)(n0 + ty + r) * KDIM + k0 + tx;
        Thi[o] = h;
        Tlo[o] = __float2bfloat16(v - __bfloat162float(h));
    }
}

// ---------------------------------------------------------------------------
// Tensor-core GEMM: bf16 3-pass split, 3-stage cp.async, XOR-swizzled smem,
// one barrier per chunk.
// Swizzle: 64B rows (32 bf16). 16B-vec v of row r stored at v ^ ((r>>1)&3).
// Conflict-free for cp.async stores and all ldmatrix phases.
// mode 1: hidden x w_attn^T -> Q/K/V bf16 hi/lo [B,H,S,D]
// mode 0: attn x w_proj^T   -> fp32 outp row-major
// ---------------------------------------------------------------------------
#define BK 32
#define GARR 8192u                        // one 128x32 bf16 array (bytes)
#define GSTAGE (4u * GARR)                // Ahi,Alo,Bhi,Blo = 32 KB
#define GEMM_SMEM_BYTES (3 * GSTAGE)      // 96 KB

__global__ __launch_bounds__(256, 2) void mma_gemm(const float* __restrict__ bias,
                                                   float* __restrict__ outp,
                                                   int mode)
{
    extern __shared__ __nv_bfloat16 gsm[];
    uint32_t sbase = smem_u32(gsm);

    const __nv_bfloat16* Ahi = mode ? g_hhi : g_ahi;
    const __nv_bfloat16* Alo = mode ? g_hlo : g_alo;
    const __nv_bfloat16* Bhi = mode ? g_wqkvThi : g_wprojThi;
    const __nv_bfloat16* Blo = mode ? g_wqkvTlo : g_wprojTlo;

    int tid = threadIdx.x;
    int wid = tid >> 5, lane = tid & 31;
    int warp_m = wid & 1, warp_n = wid >> 1;          // 2 x 4
    int m0 = blockIdx.y * 128, n0 = blockIdx.x * 128;

    float acc[4][4][4];
#pragma unroll
    for (int i = 0; i < 4; i++)
#pragma unroll
        for (int j = 0; j < 4; j++)
#pragma unroll
            for (int r = 0; r < 4; r++) acc[i][j][r] = 0.0f;

    // ---- load coordinates (8 cp.asyncs / thread / stage) ----
    int lr = tid >> 1;                 // row 0..127
    int lv0 = (tid & 1) * 2;           // logical vec 0 or 2
    uint32_t swr = (uint32_t)((lr >> 1) & 3);
    uint32_t soff[2];
#pragma unroll
    for (int vv = 0; vv < 2; vv++) {
        uint32_t v = (uint32_t)(lv0 + vv);
        soff[vv] = (uint32_t)(lr * 64) + ((v ^ swr) << 4);
    }

    auto load_stage = [&](int st, int kc) {
        uint32_t sb = sbase + (uint32_t)st * GSTAGE;
#pragma unroll
        for (int vv = 0; vv < 2; vv++) {
            int v = lv0 + vv;
            size_t asrc = (size_t)(m0 + lr) * KDIM + kc + v * 8;
            size_t bsrc = (size_t)(n0 + lr) * KDIM + kc + v * 8;
            uint32_t o = soff[vv];
            cpa16(sb + o,             Ahi + asrc);
            cpa16(sb + GARR + o,      Alo + asrc);
            cpa16(sb + 2 * GARR + o,  Bhi + bsrc);
            cpa16(sb + 3 * GARR + o,  Blo + bsrc);
        }
    };

    // ---- ldmatrix addressing (swizzled) ----
    int lrow = lane & 15, lcol = lane >> 4;
    uint32_t x = (uint32_t)((lrow >> 1) & 3);
    // coff for ks=0 (cb = lcol) and ks=16 (cb = 2+lcol)
    uint32_t coff0 = (((uint32_t)lcol ^ x) << 4);
    uint32_t coff1 = ((((uint32_t)lcol + 2u) ^ x) << 4);
    uint32_t aoff[4], boff[4];
#pragma unroll
    for (int mf = 0; mf < 4; mf++)
        aoff[mf] = (uint32_t)((warp_m * 64 + mf * 16 + lrow) * 64);
#pragma unroll
    for (int pf = 0; pf < 2; pf++)
        boff[pf] = (uint32_t)((warp_n * 32 + pf * 16 + lrow) * 64);

    load_stage(0, 0);
    CPA_COMMIT();
    load_stage(1, BK);
    CPA_COMMIT();

    const int NITER = KDIM / BK;      // 32
    for (int c = 0; c < NITER; c++) {
        if (c < NITER - 1) { CPA_WAIT(1); } else { CPA_WAIT(0); }
        __syncthreads();
        if (c + 2 < NITER) {
            load_stage((c + 2) % 3, (c + 2) * BK);
            CPA_COMMIT();
        }

        uint32_t sb = sbase + (uint32_t)(c % 3) * GSTAGE;

#pragma unroll
        for (int ki = 0; ki < 2; ki++) {
            uint32_t coff = ki ? coff1 : coff0;
            uint32_t ah[4][4], al[4][4];
#pragma unroll
            for (int mf = 0; mf < 4; mf++) {
                ldm_x4(ah[mf][0], ah[mf][1], ah[mf][2], ah[mf][3],
                       sb + aoff[mf] + coff);
                ldm_x4(al[mf][0], al[mf][1], al[mf][2], al[mf][3],
                       sb + GARR + aoff[mf] + coff);
            }
            uint32_t bh[4][2], bl[4][2];
#pragma unroll
            for (int pf = 0; pf < 2; pf++) {
                uint32_t r0, r1, r2, r3;
                ldm_x4(r0, r1, r2, r3, sb + 2 * GARR + boff[pf] + coff);
                bh[pf * 2 + 0][0] = r0; bh[pf * 2 + 0][1] = r2;
                bh[pf * 2 + 1][0] = r1; bh[pf * 2 + 1][1] = r3;
                ldm_x4(r0, r1, r2, r3, sb + 3 * GARR + boff[pf] + coff);
                bl[pf * 2 + 0][0] = r0; bl[pf * 2 + 0][1] = r2;
                bl[pf * 2 + 1][0] = r1; bl[pf * 2 + 1][1] = r3;
            }
#pragma unroll
            for (int mf = 0; mf < 4; mf++)
#pragma unroll
                for (int nf = 0; nf < 4; nf++) {
                    mma_bf16(acc[mf][nf], ah[mf], bh[nf][0], bh[nf][1]);
                    mma_bf16(acc[mf][nf], al[mf], bh[nf][0], bh[nf][1]);
                    mma_bf16(acc[mf][nf], ah[mf], bl[nf][0], bl[nf][1]);
                }
        }
    }

    // Epilogue
    int gID = lane >> 2, tcol = lane & 3;
#pragma unroll
    for (int mf = 0; mf < 4; mf++) {
#pragma unroll
        for (int nf = 0; nf < 4; nf++) {
            int c = n0 + warp_n * 32 + nf * 8 + tcol * 2;
            float2 bv = *(const float2*)&bias[c];
#pragma unroll
            for (int half = 0; half < 2; half++) {
                int r = m0 + warp_m * 64 + mf * 16 + gID + half * 8;
                float2 v;
                v.x = acc[mf][nf][half * 2 + 0] + bv.x;
                v.y = acc[mf][nf][half * 2 + 1] + bv.y;
                if (mode == 0) {
                    *(float2*)&outp[(size_t)r * EE + c] = v;
                } else {
                    int part = c >> 10, e = c & 1023, h = e >> 6, d0 = e & 63;
                    __nv_bfloat16 *dh, *dl;
                    if (part == 0)      { dh = g_qhi; dl = g_qlo; }
                    else if (part == 1) { dh = g_khi; dl = g_klo; }
                    else                { dh = g_vhi; dl = g_vlo; }
                    int b = r >> 11, s = r & 2047;
                    size_t base = (((size_t)(b * HH + h)) * SS + s) * DD + d0;
                    uint32_t hp = packbf(v.y, v.x);
                    uint32_t lp = packbf(v.y - hif(hp), v.x - lof(hp));
                    *(uint32_t*)&dh[base] = hp;
                    *(uint32_t*)&dl[base] = lp;
                }
            }
        }
    }
}

// ---------------------------------------------------------------------------
// Tensor-core causal flash attention, bf16 3-pass split, 2-stage cp.async K/V,
// one barrier per kt iteration.
// ---------------------------------------------------------------------------
#define ALD 72
#define AQ_ELEMS (128 * ALD)                  // one Q array
#define AKV_ARR (64 * ALD)                    // one K/V array
#define AKV_STAGE (4 * AKV_ARR)               // Khi,Klo,Vhi,Vlo
#define OFF_KV0 (2 * AQ_ELEMS)
#define ATTN_SMEM_ELEMS (2 * AQ_ELEMS + 2 * AKV_STAGE)
#define ATTN_SMEM_BYTES (ATTN_SMEM_ELEMS * 2) // 110592 B

__global__ __launch_bounds__(256) void attn_mma_kernel()
{
    extern __shared__ __nv_bfloat16 dsm[];
    __nv_bfloat16* Qhi_s = dsm;
    __nv_bfloat16* Qlo_s = dsm + AQ_ELEMS;
    uint32_t kvbase = smem_u32(dsm + OFF_KV0);

    int qt = gridDim.x - 1 - blockIdx.x;        // big tiles first
    int h  = blockIdx.y;
    int b  = blockIdx.z;
    int tid = threadIdx.x, wid = tid >> 5, lane = tid & 31;

    size_t bh = ((size_t)(b * HH + h)) * SS * DD;
    const __nv_bfloat16* Qhg = g_qhi + bh;
    const __nv_bfloat16* Qlg = g_qlo + bh;
    const __nv_bfloat16* Khg = g_khi + bh;
    const __nv_bfloat16* Klg = g_klo + bh;
    const __nv_bfloat16* Vhg = g_vhi + bh;
    const __nv_bfloat16* Vlg = g_vlo + bh;

    int q0 = qt * 128;

    // Q tile (plain loads; covered by first barrier)
#pragma unroll
    for (int t = 0; t < 4; t++) {
        int i = tid + t * 256;
        int r = i >> 3, v = i & 7;
        size_t src = (size_t)(q0 + r) * DD + v * 8;
        uint32_t so = (uint32_t)(r * ALD + v * 8);
        *(uint4*)&Qhi_s[so] = *(const uint4*)(Qhg + src);
        *(uint4*)&Qlo_s[so] = *(const uint4*)(Qlg + src);
    }

    // K/V stage loader (cp.async, 8 per thread)
    auto load_kv = [&](int st, int k0) {
        uint32_t sb = kvbase + (uint32_t)(st * AKV_STAGE * 2);
#pragma unroll
        for (int t = 0; t < 2; t++) {
            int i = tid + t * 256;
            int r = i >> 3, v = i & 7;
            size_t src = (size_t)(k0 + r) * DD + v * 8;
            uint32_t o = (uint32_t)((r * ALD + v * 8) * 2);
            cpa16(sb + o,                    Khg + src);
            cpa16(sb + AKV_ARR * 2 + o,      Klg + src);
            cpa16(sb + 2 * AKV_ARR * 2 + o,  Vhg + src);
            cpa16(sb + 3 * AKV_ARR * 2 + o,  Vlg + src);
        }
    };

    float o[8][4];
#pragma unroll
    for (int j = 0; j < 8; j++)
#pragma unroll
        for (int e = 0; e < 4; e++) o[j][e] = 0.0f;
    float m_[2] = {-1e30f, -1e30f}, l_[2] = {0.0f, 0.0f};

    int lrow = lane & 15, lcol = lane >> 4;
    uint32_t qb_hi = smem_u32(Qhi_s) +
        (uint32_t)(((wid * 16 + lrow) * ALD + lcol * 8) * 2);
    uint32_t qb_lo = qb_hi + (uint32_t)(AQ_ELEMS * 2);
    uint32_t kvo = (uint32_t)((lrow * ALD + lcol * 8) * 2);

    int row0 = q0 + wid * 16 + (lane >> 2);
    const float scale = 1.0f / 16.0f;

    int ktmax = 2 * qt + 1;
    load_kv(0, 0);
    CPA_COMMIT();

    for (int kt = 0; kt <= ktmax; kt++) {
        CPA_WAIT(0);
        __syncthreads();
        if (kt + 1 <= ktmax) {
            load_kv((kt + 1) & 1, (kt + 1) * 64);
            CPA_COMMIT();
        }

        uint32_t sb = kvbase + (uint32_t)((kt & 1) * AKV_STAGE * 2);
        uint32_t kb_hi = sb + kvo;
        uint32_t kb_lo = sb + AKV_ARR * 2 + kvo;
        uint32_t vb_hi = sb + 2 * AKV_ARR * 2 + kvo;
        uint32_t vb_lo = sb + 3 * AKV_ARR * 2 + kvo;
        int k0 = kt * 64;

        float s[8][4];
#pragma unroll
        for (int nf = 0; nf < 8; nf++)
#pragma unroll
            for (int e = 0; e < 4; e++) s[nf][e] = 0.0f;

#pragma unroll
        for (int ks = 0; ks < 4; ks++) {
            uint32_t ah[4], al[4];
            ldm_x4(ah[0], ah[1], ah[2], ah[3], qb_hi + (uint32_t)(ks * 32));
            ldm_x4(al[0], al[1], al[2], al[3], qb_lo + (uint32_t)(ks * 32));
#pragma unroll
            for (int g = 0; g < 4; g++) {
                uint32_t off = (uint32_t)((g * 16 * ALD + ks * 16) * 2);
                uint32_t r0, r1, r2, r3, t0, t1, t2, t3;
                ldm_x4(r0, r1, r2, r3, kb_hi + off);
                ldm_x4(t0, t1, t2, t3, kb_lo + off);
                mma_bf16(s[2 * g],     ah, r0, r2);
                mma_bf16(s[2 * g],     al, r0, r2);
                mma_bf16(s[2 * g],     ah, t0, t2);
                mma_bf16(s[2 * g + 1], ah, r1, r3);
                mma_bf16(s[2 * g + 1], al, r1, r3);
                mma_bf16(s[2 * g + 1], ah, t1, t3);
            }
        }

        if (kt >= ktmax - 1) {
#pragma unroll
            for (int nf = 0; nf < 8; nf++) {
                int cb = k0 + nf * 8 + (lane & 3) * 2;
#pragma unroll
                for (int e = 0; e < 4; e++) {
                    int col = cb + (e & 1);
                    int row = (e < 2) ? row0 : row0 + 8;
                    float v = s[nf][e] * scale;
                    s[nf][e] = (col > row) ? -10000.0f : v;
                }
            }
        } else {
#pragma unroll
            for (int nf = 0; nf < 8; nf++)
#pragma unroll
                for (int e = 0; e < 4; e++) s[nf][e] *= scale;
        }

#pragma unroll
        for (int i = 0; i < 2; i++) {
            float mx = -1e30f;
#pragma unroll
            for (int nf = 0; nf < 8; nf++)
                mx = fmaxf(mx, fmaxf(s[nf][2 * i], s[nf][2 * i + 1]));
            mx = fmaxf(mx, __shfl_xor_sync(0xffffffffu, mx, 1));
            mx = fmaxf(mx, __shfl_xor_sync(0xffffffffu, mx, 2));
            float mn = fmaxf(m_[i], mx);
            float alpha = __expf(m_[i] - mn);
            float sum = 0.0f;
#pragma unroll
            for (int nf = 0; nf < 8; nf++) {
                float p0 = __expf(s[nf][2 * i] - mn);
                float p1 = __expf(s[nf][2 * i + 1] - mn);
                s[nf][2 * i] = p0; s[nf][2 * i + 1] = p1;
                sum += p0 + p1;
            }
            sum += __shfl_xor_sync(0xffffffffu, sum, 1);
            sum += __shfl_xor_sync(0xffffffffu, sum, 2);
            l_[i] = l_[i] * alpha + sum;
            m_[i] = mn;
#pragma unroll
            for (int j = 0; j < 8; j++) {
                o[j][2 * i] *= alpha; o[j][2 * i + 1] *= alpha;
            }
        }

#pragma unroll
        for (int c = 0; c < 4; c++) {
            uint32_t aph[4], apl[4];
            aph[0] = packbf(s[2 * c][1], s[2 * c][0]);
            aph[1] = packbf(s[2 * c][3], s[2 * c][2]);
            aph[2] = packbf(s[2 * c + 1][1], s[2 * c + 1][0]);
            aph[3] = packbf(s[2 * c + 1][3], s[2 * c + 1][2]);
            apl[0] = packbf(s[2 * c][1] - hif(aph[0]), s[2 * c][0] - lof(aph[0]));
            apl[1] = packbf(s[2 * c][3] - hif(aph[1]), s[2 * c][2] - lof(aph[1]));
            apl[2] = packbf(s[2 * c + 1][1] - hif(aph[2]),
                            s[2 * c + 1][0] - lof(aph[2]));
            apl[3] = packbf(s[2 * c + 1][3] - hif(aph[3]),
                            s[2 * c + 1][2] - lof(aph[3]));
#pragma unroll
            for (int g = 0; g < 4; g++) {
                uint32_t off = (uint32_t)((c * 16 * ALD + g * 16) * 2);
                uint32_t r0, r1, r2, r3, t0, t1, t2, t3;
                ldm_x4_t(r0, r1, r2, r3, vb_hi + off);
                ldm_x4_t(t0, t1, t2, t3, vb_lo + off);
                mma_bf16(o[2 * g],     aph, r0, r1);
                mma_bf16(o[2 * g],     apl, r0, r1);
                mma_bf16(o[2 * g],     aph, t0, t1);
                mma_bf16(o[2 * g + 1], aph, r2, r3);
                mma_bf16(o[2 * g + 1], apl, r2, r3);
                mma_bf16(o[2 * g + 1], aph, t2, t3);
            }
        }
    }

    float inv0 = 1.0f / l_[0], inv1 = 1.0f / l_[1];
    int d0 = (lane & 3) * 2;
    size_t rb0 = ((size_t)(b * SS + row0)) * EE + h * DD;
    size_t rb1 = rb0 + (size_t)8 * EE;
#pragma unroll
    for (int j = 0; j < 8; j++) {
        int d = j * 8 + d0;
        float v0 = o[j][0] * inv0, v1 = o[j][1] * inv0;
        float v2 = o[j][2] * inv1, v3 = o[j][3] * inv1;
        uint32_t h01 = packbf(v1, v0);
        uint32_t l01 = packbf(v1 - hif(h01), v0 - lof(h01));
        uint32_t h23 = packbf(v3, v2);
        uint32_t l23 = packbf(v3 - hif(h23), v2 - lof(h23));
        *(uint32_t*)&g_ahi[rb0 + d] = h01;
        *(uint32_t*)&g_alo[rb0 + d] = l01;
        *(uint32_t*)&g_ahi[rb1 + d] = h23;
        *(uint32_t*)&g_alo[rb1 + d] = l23;
    }
}

// ---------------------------------------------------------------------------
extern "C" void kernel_launch(void* const* d_in, const int* in_sizes, int n_in,
                              void* d_out, int out_size)
{
    const float* hidden = (const float*)d_in[0];   // [B,S,E]
    const float* w_attn = (const float*)d_in[1];   // [E, 3E]
    const float* b_attn = (const float*)d_in[2];   // [3E]
    const float* w_proj = (const float*)d_in[3];   // [E, E]
    const float* b_proj = (const float*)d_in[4];   // [E]
    float* out = (float*)d_out;                    // [B,S,E] fp32

    split_kernel<<<(MROWS * KDIM) / (256 * 4), 256>>>(hidden);
    tsplit_kernel<<<dim3(N_QKV / 32, KDIM / 32), 256>>>(w_attn, 0, N_QKV);
    tsplit_kernel<<<dim3(EE / 32, KDIM / 32), 256>>>(w_proj, 1, EE);

    cudaFuncSetAttribute(mma_gemm, cudaFuncAttributeMaxDynamicSharedMemorySize,
                         GEMM_SMEM_BYTES);
    mma_gemm<<<dim3(N_QKV / 128, MROWS / 128), 256, GEMM_SMEM_BYTES>>>(
        b_attn, nullptr, 1);

    cudaFuncSetAttribute(attn_mma_kernel,
                         cudaFuncAttributeMaxDynamicSharedMemorySize,
                         ATTN_SMEM_BYTES);
    attn_mma_kernel<<<dim3(SS / 128, HH, BB), 256, ATTN_SMEM_BYTES>>>();

    mma_gemm<<<dim3(EE / 128, MROWS / 128), 256, GEMM_SMEM_BYTES>>>(
        b_proj, out, 0);
}

// round 8
// speedup vs baseline: 2.5731x; 1.0134x over previous
#include <cuda_runtime.h>
#include <cuda_bf16.h>
#include <cstdint>
#include <math.h>

// Problem constants
#define BB 2
#define SS 2048
#define EE 1024
#define HH 16
#define DD 64
#define MROWS (BB*SS)          // 4096
#define KDIM 1024
#define N_QKV 3072

// ---------------------------------------------------------------------------
// Scratch (allocation-free: device globals)
// ---------------------------------------------------------------------------
__device__ __nv_bfloat16 g_qhi[BB*HH*SS*DD];
__device__ __nv_bfloat16 g_qlo[BB*HH*SS*DD];
__device__ __nv_bfloat16 g_khi[BB*HH*SS*DD];
__device__ __nv_bfloat16 g_klo[BB*HH*SS*DD];
__device__ __nv_bfloat16 g_vhi[BB*HH*SS*DD];
__device__ __nv_bfloat16 g_vlo[BB*HH*SS*DD];

__device__ __nv_bfloat16 g_hhi[MROWS*KDIM];     // hidden hi
__device__ __nv_bfloat16 g_hlo[MROWS*KDIM];     // hidden lo
__device__ __nv_bfloat16 g_ahi[MROWS*KDIM];     // attn-out hi (merged heads)
__device__ __nv_bfloat16 g_alo[MROWS*KDIM];     // attn-out lo
__device__ __nv_bfloat16 g_wqkvThi[N_QKV*KDIM]; // w_attn^T hi
__device__ __nv_bfloat16 g_wqkvTlo[N_QKV*KDIM];
__device__ __nv_bfloat16 g_wprojThi[EE*KDIM];   // w_proj^T hi
__device__ __nv_bfloat16 g_wprojTlo[EE*KDIM];

// ---------------------------------------------------------------------------
// PTX helpers
// ---------------------------------------------------------------------------
__device__ __forceinline__ uint32_t smem_u32(const void* p) {
    uint32_t a;
    asm("{ .reg .u64 t; cvta.to.shared.u64 t, %1; cvt.u32.u64 %0, t; }"
        : "=r"(a) : "l"(p));
    return a;
}

__device__ __forceinline__ void ldm_x4(uint32_t& r0, uint32_t& r1,
                                       uint32_t& r2, uint32_t& r3,
                                       uint32_t addr) {
    asm volatile("ldmatrix.sync.aligned.m8n8.x4.shared.b16 {%0,%1,%2,%3}, [%4];"
                 : "=r"(r0), "=r"(r1), "=r"(r2), "=r"(r3) : "r"(addr));
}
__device__ __forceinline__ void ldm_x4_t(uint32_t& r0, uint32_t& r1,
                                         uint32_t& r2, uint32_t& r3,
                                         uint32_t addr) {
    asm volatile("ldmatrix.sync.aligned.m8n8.x4.trans.shared.b16 {%0,%1,%2,%3}, [%4];"
                 : "=r"(r0), "=r"(r1), "=r"(r2), "=r"(r3) : "r"(addr));
}

__device__ __forceinline__ void mma_bf16(float* d, const uint32_t* a,
                                         uint32_t b0, uint32_t b1) {
    asm volatile(
        "mma.sync.aligned.m16n8k16.row.col.f32.bf16.bf16.f32 "
        "{%0,%1,%2,%3}, {%4,%5,%6,%7}, {%8,%9}, {%0,%1,%2,%3};"
        : "+f"(d[0]), "+f"(d[1]), "+f"(d[2]), "+f"(d[3])
        : "r"(a[0]), "r"(a[1]), "r"(a[2]), "r"(a[3]), "r"(b0), "r"(b1));
}

__device__ __forceinline__ void cpa16(uint32_t dst, const void* src) {
    asm volatile("cp.async.cg.shared.global [%0], [%1], 16;"
                 :: "r"(dst), "l"(src));
}
#define CPA_COMMIT() asm volatile("cp.async.commit_group;" ::: "memory")
#define CPA_WAIT(n)  asm volatile("cp.async.wait_group %0;" :: "n"(n) : "memory")

__device__ __forceinline__ uint32_t packbf(float hi, float lo) {
    uint32_t d;
    asm("cvt.rn.bf16x2.f32 %0, %1, %2;" : "=r"(d) : "f"(hi), "f"(lo));
    return d;
}
__device__ __forceinline__ float lof(uint32_t u) {
    return __uint_as_float(u << 16);
}
__device__ __forceinline__ float hif(uint32_t u) {
    return __uint_as_float(u & 0xffff0000u);
}

// ---------------------------------------------------------------------------
// Prep kernel 1: split fp32 -> bf16 hi/lo (hidden only)
// ---------------------------------------------------------------------------
__global__ __launch_bounds__(256) void split_kernel(const float* __restrict__ x)
{
    size_t i0 = ((size_t)blockIdx.x * 256 + threadIdx.x) * 4;
    float4 v = *(const float4*)&x[i0];
    __nv_bfloat16 h0 = __float2bfloat16(v.x);
    __nv_bfloat16 h1 = __float2bfloat16(v.y);
    __nv_bfloat16 h2 = __float2bfloat16(v.z);
    __nv_bfloat16 h3 = __float2bfloat16(v.w);
    __nv_bfloat162 hp0; hp0.x = h0; hp0.y = h1;
    __nv_bfloat162 hp1; hp1.x = h2; hp1.y = h3;
    __nv_bfloat162 lp0;
    lp0.x = __float2bfloat16(v.x - __bfloat162float(h0));
    lp0.y = __float2bfloat16(v.y - __bfloat162float(h1));
    __nv_bfloat162 lp1;
    lp1.x = __float2bfloat16(v.z - __bfloat162float(h2));
    lp1.y = __float2bfloat16(v.w - __bfloat162float(h3));
    *(__nv_bfloat162*)&g_hhi[i0]     = hp0;
    *(__nv_bfloat162*)&g_hhi[i0 + 2] = hp1;
    *(__nv_bfloat162*)&g_hlo[i0]     = lp0;
    *(__nv_bfloat162*)&g_hlo[i0 + 2] = lp1;
}

// ---------------------------------------------------------------------------
// Prep kernel 2: W [K,N] row-major -> W^T [N,K] bf16 hi/lo
// ---------------------------------------------------------------------------
__global__ __launch_bounds__(256) void tsplit_kernel(const float* __restrict__ W,
                                                     int which, int N)
{
    __nv_bfloat16* Thi = which ? g_wprojThi : g_wqkvThi;
    __nv_bfloat16* Tlo = which ? g_wprojTlo : g_wqkvTlo;
    __shared__ float t[32][33];
    int n0 = blockIdx.x * 32, k0 = blockIdx.y * 32;
    int tx = threadIdx.x & 31, ty = threadIdx.x >> 5;
#pragma unroll
    for (int r = 0; r < 32; r += 8)
        t[ty + r][tx] = W[(size_t)(k0 + ty + r) * N + n0 + tx];
    __syncthreads();
#pragma unroll
    for (int r = 0; r < 32; r += 8) {
        float v = t[tx][ty + r];
        __nv_bfloat16 h = __float2bfloat16(v);
        size_t o = (size_t)(n0 + ty + r) * KDIM + k0 + tx;
        Thi[o] = h;
        Tlo[o] = __float2bfloat16(v - __bfloat162float(h));
    }
}

// ---------------------------------------------------------------------------
// Tensor-core GEMM: bf16 3-pass split, 3-stage cp.async, XOR-swizzled smem,
// one barrier per chunk, PASS-MAJOR MMA ordering (no back-to-back acc RAW).
// ---------------------------------------------------------------------------
#define BK 32
#define GARR 8192u                        // one 128x32 bf16 array (bytes)
#define GSTAGE (4u * GARR)                // Ahi,Alo,Bhi,Blo = 32 KB
#define GEMM_SMEM_BYTES (3 * GSTAGE)      // 96 KB

__global__ __launch_bounds__(256, 2) void mma_gemm(const float* __restrict__ bias,
                                                   float* __restrict__ outp,
                                                   int mode)
{
    extern __shared__ __nv_bfloat16 gsm[];
    uint32_t sbase = smem_u32(gsm);
    uint32_t send = sbase + 3u * GSTAGE;

    const __nv_bfloat16* Ahi = mode ? g_hhi : g_ahi;
    const __nv_bfloat16* Alo = mode ? g_hlo : g_alo;
    const __nv_bfloat16* Bhi = mode ? g_wqkvThi : g_wprojThi;
    const __nv_bfloat16* Blo = mode ? g_wqkvTlo : g_wprojTlo;

    int tid = threadIdx.x;
    int wid = tid >> 5, lane = tid & 31;
    int warp_m = wid & 1, warp_n = wid >> 1;          // 2 x 4
    int m0 = blockIdx.y * 128, n0 = blockIdx.x * 128;

    float acc[4][4][4];
#pragma unroll
    for (int i = 0; i < 4; i++)
#pragma unroll
        for (int j = 0; j < 4; j++)
#pragma unroll
            for (int r = 0; r < 4; r++) acc[i][j][r] = 0.0f;

    // ---- load coordinates (8 cp.asyncs / thread / stage) ----
    int lr = tid >> 1;                 // row 0..127
    int lv0 = (tid & 1) * 2;           // logical vec 0 or 2
    uint32_t swr = (uint32_t)((lr >> 1) & 3);
    uint32_t soff[2];
#pragma unroll
    for (int vv = 0; vv < 2; vv++) {
        uint32_t v = (uint32_t)(lv0 + vv);
        soff[vv] = (uint32_t)(lr * 64) + ((v ^ swr) << 4);
    }

    auto load_stage = [&](uint32_t sb, int kc) {
#pragma unroll
        for (int vv = 0; vv < 2; vv++) {
            int v = lv0 + vv;
            size_t asrc = (size_t)(m0 + lr) * KDIM + kc + v * 8;
            size_t bsrc = (size_t)(n0 + lr) * KDIM + kc + v * 8;
            uint32_t o = soff[vv];
            cpa16(sb + o,             Ahi + asrc);
            cpa16(sb + GARR + o,      Alo + asrc);
            cpa16(sb + 2 * GARR + o,  Bhi + bsrc);
            cpa16(sb + 3 * GARR + o,  Blo + bsrc);
        }
    };

    // ---- ldmatrix addressing (swizzled) ----
    int lrow = lane & 15, lcol = lane >> 4;
    uint32_t x = (uint32_t)((lrow >> 1) & 3);
    uint32_t coff0 = (((uint32_t)lcol ^ x) << 4);
    uint32_t coff1 = ((((uint32_t)lcol + 2u) ^ x) << 4);
    uint32_t aoff[4], boff[4];
#pragma unroll
    for (int mf = 0; mf < 4; mf++)
        aoff[mf] = (uint32_t)((warp_m * 64 + mf * 16 + lrow) * 64);
#pragma unroll
    for (int pf = 0; pf < 2; pf++)
        boff[pf] = (uint32_t)((warp_n * 32 + pf * 16 + lrow) * 64);

    load_stage(sbase, 0);
    CPA_COMMIT();
    load_stage(sbase + GSTAGE, BK);
    CPA_COMMIT();

    uint32_t sb_c = sbase;                 // compute stage
    uint32_t sb_l = sbase + 2u * GSTAGE;   // next load stage

    const int NITER = KDIM / BK;      // 32
    for (int c = 0; c < NITER; c++) {
        if (c < NITER - 1) { CPA_WAIT(1); } else { CPA_WAIT(0); }
        __syncthreads();
        if (c + 2 < NITER) {
            load_stage(sb_l, (c + 2) * BK);
            CPA_COMMIT();
            sb_l += GSTAGE; if (sb_l == send) sb_l = sbase;
        }

        uint32_t sb = sb_c;
        sb_c += GSTAGE; if (sb_c == send) sb_c = sbase;

#pragma unroll
        for (int ki = 0; ki < 2; ki++) {
            uint32_t coff = ki ? coff1 : coff0;
            uint32_t ah[4][4], al[4][4];
#pragma unroll
            for (int mf = 0; mf < 4; mf++) {
                ldm_x4(ah[mf][0], ah[mf][1], ah[mf][2], ah[mf][3],
                       sb + aoff[mf] + coff);
                ldm_x4(al[mf][0], al[mf][1], al[mf][2], al[mf][3],
                       sb + GARR + aoff[mf] + coff);
            }
            uint32_t bh[4][2], bl[4][2];
#pragma unroll
            for (int pf = 0; pf < 2; pf++) {
                uint32_t r0, r1, r2, r3;
                ldm_x4(r0, r1, r2, r3, sb + 2 * GARR + boff[pf] + coff);
                bh[pf * 2 + 0][0] = r0; bh[pf * 2 + 0][1] = r2;
                bh[pf * 2 + 1][0] = r1; bh[pf * 2 + 1][1] = r3;
                ldm_x4(r0, r1, r2, r3, sb + 3 * GARR + boff[pf] + coff);
                bl[pf * 2 + 0][0] = r0; bl[pf * 2 + 0][1] = r2;
                bl[pf * 2 + 1][0] = r1; bl[pf * 2 + 1][1] = r3;
            }
            // pass-major ordering: no back-to-back RAW on any accumulator
#pragma unroll
            for (int mf = 0; mf < 4; mf++)
#pragma unroll
                for (int nf = 0; nf < 4; nf++)
                    mma_bf16(acc[mf][nf], ah[mf], bh[nf][0], bh[nf][1]);
#pragma unroll
            for (int mf = 0; mf < 4; mf++)
#pragma unroll
                for (int nf = 0; nf < 4; nf++)
                    mma_bf16(acc[mf][nf], al[mf], bh[nf][0], bh[nf][1]);
#pragma unroll
            for (int mf = 0; mf < 4; mf++)
#pragma unroll
                for (int nf = 0; nf < 4; nf++)
                    mma_bf16(acc[mf][nf], ah[mf], bl[nf][0], bl[nf][1]);
        }
    }

    // Epilogue
    int gID = lane >> 2, tcol = lane & 3;
#pragma unroll
    for (int mf = 0; mf < 4; mf++) {
#pragma unroll
        for (int nf = 0; nf < 4; nf++) {
            int c = n0 + warp_n * 32 + nf * 8 + tcol * 2;
            float2 bv = *(const float2*)&bias[c];
#pragma unroll
            for (int half = 0; half < 2; half++) {
                int r = m0 + warp_m * 64 + mf * 16 + gID + half * 8;
                float2 v;
                v.x = acc[mf][nf][half * 2 + 0] + bv.x;
                v.y = acc[mf][nf][half * 2 + 1] + bv.y;
                if (mode == 0) {
                    *(float2*)&outp[(size_t)r * EE + c] = v;
                } else {
                    int part = c >> 10, e = c & 1023, h = e >> 6, d0 = e & 63;
                    __nv_bfloat16 *dh, *dl;
                    if (part == 0)      { dh = g_qhi; dl = g_qlo; }
                    else if (part == 1) { dh = g_khi; dl = g_klo; }
                    else                { dh = g_vhi; dl = g_vlo; }
                    int b = r >> 11, s = r & 2047;
                    size_t base = (((size_t)(b * HH + h)) * SS + s) * DD + d0;
                    uint32_t hp = packbf(v.y, v.x);
                    uint32_t lp = packbf(v.y - hif(hp), v.x - lof(hp));
                    *(uint32_t*)&dh[base] = hp;
                    *(uint32_t*)&dl[base] = lp;
                }
            }
        }
    }
}

// ---------------------------------------------------------------------------
// Tensor-core causal flash attention: bf16 3-pass split, 2-stage cp.async K/V,
// one barrier per kt, pass-spread MMA ordering, log2-domain softmax.
// ---------------------------------------------------------------------------
#define ALD 72
#define AQ_ELEMS (128 * ALD)
#define AKV_ARR (64 * ALD)
#define AKV_STAGE (4 * AKV_ARR)
#define OFF_KV0 (2 * AQ_ELEMS)
#define ATTN_SMEM_ELEMS (2 * AQ_ELEMS + 2 * AKV_STAGE)
#define ATTN_SMEM_BYTES (ATTN_SMEM_ELEMS * 2)

#define LOG2E 1.4426950408889634f

__global__ __launch_bounds__(256) void attn_mma_kernel()
{
    extern __shared__ __nv_bfloat16 dsm[];
    __nv_bfloat16* Qhi_s = dsm;
    __nv_bfloat16* Qlo_s = dsm + AQ_ELEMS;
    uint32_t kvbase = smem_u32(dsm + OFF_KV0);

    int qt = gridDim.x - 1 - blockIdx.x;        // big tiles first
    int h  = blockIdx.y;
    int b  = blockIdx.z;
    int tid = threadIdx.x, wid = tid >> 5, lane = tid & 31;

    size_t bh = ((size_t)(b * HH + h)) * SS * DD;
    const __nv_bfloat16* Qhg = g_qhi + bh;
    const __nv_bfloat16* Qlg = g_qlo + bh;
    const __nv_bfloat16* Khg = g_khi + bh;
    const __nv_bfloat16* Klg = g_klo + bh;
    const __nv_bfloat16* Vhg = g_vhi + bh;
    const __nv_bfloat16* Vlg = g_vlo + bh;

    int q0 = qt * 128;

    // Q tile (plain loads; covered by first barrier)
#pragma unroll
    for (int t = 0; t < 4; t++) {
        int i = tid + t * 256;
        int r = i >> 3, v = i & 7;
        size_t src = (size_t)(q0 + r) * DD + v * 8;
        uint32_t so = (uint32_t)(r * ALD + v * 8);
        *(uint4*)&Qhi_s[so] = *(const uint4*)(Qhg + src);
        *(uint4*)&Qlo_s[so] = *(const uint4*)(Qlg + src);
    }

    auto load_kv = [&](int st, int k0) {
        uint32_t sb = kvbase + (uint32_t)(st * AKV_STAGE * 2);
#pragma unroll
        for (int t = 0; t < 2; t++) {
            int i = tid + t * 256;
            int r = i >> 3, v = i & 7;
            size_t src = (size_t)(k0 + r) * DD + v * 8;
            uint32_t o = (uint32_t)((r * ALD + v * 8) * 2);
            cpa16(sb + o,                    Khg + src);
            cpa16(sb + AKV_ARR * 2 + o,      Klg + src);
            cpa16(sb + 2 * AKV_ARR * 2 + o,  Vhg + src);
            cpa16(sb + 3 * AKV_ARR * 2 + o,  Vlg + src);
        }
    };

    float o[8][4];
#pragma unroll
    for (int j = 0; j < 8; j++)
#pragma unroll
        for (int e = 0; e < 4; e++) o[j][e] = 0.0f;
    float m_[2] = {-1e30f, -1e30f}, l_[2] = {0.0f, 0.0f};

    int lrow = lane & 15, lcol = lane >> 4;
    uint32_t qb_hi = smem_u32(Qhi_s) +
        (uint32_t)(((wid * 16 + lrow) * ALD + lcol * 8) * 2);
    uint32_t qb_lo = qb_hi + (uint32_t)(AQ_ELEMS * 2);
    uint32_t kvo = (uint32_t)((lrow * ALD + lcol * 8) * 2);

    int row0 = q0 + wid * 16 + (lane >> 2);
    const float scale2 = (1.0f / 16.0f) * LOG2E;   // log2-domain scale
    const float maskv = -10000.0f * LOG2E;

    int ktmax = 2 * qt + 1;
    load_kv(0, 0);
    CPA_COMMIT();

    for (int kt = 0; kt <= ktmax; kt++) {
        CPA_WAIT(0);
        __syncthreads();
        if (kt + 1 <= ktmax) {
            load_kv((kt + 1) & 1, (kt + 1) * 64);
            CPA_COMMIT();
        }

        uint32_t sb = kvbase + (uint32_t)((kt & 1) * AKV_STAGE * 2);
        uint32_t kb_hi = sb + kvo;
        uint32_t kb_lo = sb + AKV_ARR * 2 + kvo;
        uint32_t vb_hi = sb + 2 * AKV_ARR * 2 + kvo;
        uint32_t vb_lo = sb + 3 * AKV_ARR * 2 + kvo;
        int k0 = kt * 64;

        float s[8][4];
#pragma unroll
        for (int nf = 0; nf < 8; nf++)
#pragma unroll
            for (int e = 0; e < 4; e++) s[nf][e] = 0.0f;

#pragma unroll
        for (int ks = 0; ks < 4; ks++) {
            uint32_t ah[4], al[4];
            ldm_x4(ah[0], ah[1], ah[2], ah[3], qb_hi + (uint32_t)(ks * 32));
            ldm_x4(al[0], al[1], al[2], al[3], qb_lo + (uint32_t)(ks * 32));
#pragma unroll
            for (int g = 0; g < 4; g++) {
                uint32_t off = (uint32_t)((g * 16 * ALD + ks * 16) * 2);
                uint32_t r0, r1, r2, r3, t0, t1, t2, t3;
                ldm_x4(r0, r1, r2, r3, kb_hi + off);
                ldm_x4(t0, t1, t2, t3, kb_lo + off);
                // spread passes: interleave the two accumulators per pass
                mma_bf16(s[2 * g],     ah, r0, r2);
                mma_bf16(s[2 * g + 1], ah, r1, r3);
                mma_bf16(s[2 * g],     al, r0, r2);
                mma_bf16(s[2 * g + 1], al, r1, r3);
                mma_bf16(s[2 * g],     ah, t0, t2);
                mma_bf16(s[2 * g + 1], ah, t1, t3);
            }
        }

        if (kt >= ktmax - 1) {
#pragma unroll
            for (int nf = 0; nf < 8; nf++) {
                int cb = k0 + nf * 8 + (lane & 3) * 2;
#pragma unroll
                for (int e = 0; e < 4; e++) {
                    int col = cb + (e & 1);
                    int row = (e < 2) ? row0 : row0 + 8;
                    float v = s[nf][e] * scale2;
                    s[nf][e] = (col > row) ? maskv : v;
                }
            }
        } else {
#pragma unroll
            for (int nf = 0; nf < 8; nf++)
#pragma unroll
                for (int e = 0; e < 4; e++) s[nf][e] *= scale2;
        }

        // online softmax in log2 domain
#pragma unroll
        for (int i = 0; i < 2; i++) {
            float mx = -1e30f;
#pragma unroll
            for (int nf = 0; nf < 8; nf++)
                mx = fmaxf(mx, fmaxf(s[nf][2 * i], s[nf][2 * i + 1]));
            mx = fmaxf(mx, __shfl_xor_sync(0xffffffffu, mx, 1));
            mx = fmaxf(mx, __shfl_xor_sync(0xffffffffu, mx, 2));
            float mn = fmaxf(m_[i], mx);
            float alpha = exp2f(m_[i] - mn);
            float sum = 0.0f;
#pragma unroll
            for (int nf = 0; nf < 8; nf++) {
                float p0 = exp2f(s[nf][2 * i] - mn);
                float p1 = exp2f(s[nf][2 * i + 1] - mn);
                s[nf][2 * i] = p0; s[nf][2 * i + 1] = p1;
                sum += p0 + p1;
            }
            sum += __shfl_xor_sync(0xffffffffu, sum, 1);
            sum += __shfl_xor_sync(0xffffffffu, sum, 2);
            l_[i] = l_[i] * alpha + sum;
            m_[i] = mn;
#pragma unroll
            for (int j = 0; j < 8; j++) {
                o[j][2 * i] *= alpha; o[j][2 * i + 1] *= alpha;
            }
        }

#pragma unroll
        for (int c = 0; c < 4; c++) {
            uint32_t aph[4], apl[4];
            aph[0] = packbf(s[2 * c][1], s[2 * c][0]);
            aph[1] = packbf(s[2 * c][3], s[2 * c][2]);
            aph[2] = packbf(s[2 * c + 1][1], s[2 * c + 1][0]);
            aph[3] = packbf(s[2 * c + 1][3], s[2 * c + 1][2]);
            apl[0] = packbf(s[2 * c][1] - hif(aph[0]), s[2 * c][0] - lof(aph[0]));
            apl[1] = packbf(s[2 * c][3] - hif(aph[1]), s[2 * c][2] - lof(aph[1]));
            apl[2] = packbf(s[2 * c + 1][1] - hif(aph[2]),
                            s[2 * c + 1][0] - lof(aph[2]));
            apl[3] = packbf(s[2 * c + 1][3] - hif(aph[3]),
                            s[2 * c + 1][2] - lof(aph[3]));
#pragma unroll
            for (int g = 0; g < 4; g++) {
                uint32_t off = (uint32_t)((c * 16 * ALD + g * 16) * 2);
                uint32_t r0, r1, r2, r3, t0, t1, t2, t3;
                ldm_x4_t(r0, r1, r2, r3, vb_hi + off);
                ldm_x4_t(t0, t1, t2, t3, vb_lo + off);
                mma_bf16(o[2 * g],     aph, r0, r1);
                mma_bf16(o[2 * g + 1], aph, r2, r3);
                mma_bf16(o[2 * g],     apl, r0, r1);
                mma_bf16(o[2 * g + 1], apl, r2, r3);
                mma_bf16(o[2 * g],     aph, t0, t1);
                mma_bf16(o[2 * g + 1], aph, t2, t3);
            }
        }
    }

    float inv0 = 1.0f / l_[0], inv1 = 1.0f / l_[1];
    int d0 = (lane & 3) * 2;
    size_t rb0 = ((size_t)(b * SS + row0)) * EE + h * DD;
    size_t rb1 = rb0 + (size_t)8 * EE;
#pragma unroll
    for (int j = 0; j < 8; j++) {
        int d = j * 8 + d0;
        float v0 = o[j][0] * inv0, v1 = o[j][1] * inv0;
        float v2 = o[j][2] * inv1, v3 = o[j][3] * inv1;
        uint32_t h01 = packbf(v1, v0);
        uint32_t l01 = packbf(v1 - hif(h01), v0 - lof(h01));
        uint32_t h23 = packbf(v3, v2);
        uint32_t l23 = packbf(v3 - hif(h23), v2 - lof(h23));
        *(uint32_t*)&g_ahi[rb0 + d] = h01;
        *(uint32_t*)&g_alo[rb0 + d] = l01;
        *(uint32_t*)&g_ahi[rb1 + d] = h23;
        *(uint32_t*)&g_alo[rb1 + d] = l23;
    }
}

// ---------------------------------------------------------------------------
extern "C" void kernel_launch(void* const* d_in, const int* in_sizes, int n_in,
                              void* d_out, int out_size)
{
    const float* hidden = (const float*)d_in[0];   // [B,S,E]
    const float* w_attn = (const float*)d_in[1];   // [E, 3E]
    const float* b_attn = (const float*)d_in[2];   // [3E]
    const float* w_proj = (const float*)d_in[3];   // [E, E]
    const float* b_proj = (const float*)d_in[4];   // [E]
    float* out = (float*)d_out;                    // [B,S,E] fp32

    split_kernel<<<(MROWS * KDIM) / (256 * 4), 256>>>(hidden);
    tsplit_kernel<<<dim3(N_QKV / 32, KDIM / 32), 256>>>(w_attn, 0, N_QKV);
    tsplit_kernel<<<dim3(EE / 32, KDIM / 32), 256>>>(w_proj, 1, EE);

    cudaFuncSetAttribute(mma_gemm, cudaFuncAttributeMaxDynamicSharedMemorySize,
                         GEMM_SMEM_BYTES);
    mma_gemm<<<dim3(N_QKV / 128, MROWS / 128), 256, GEMM_SMEM_BYTES>>>(
        b_attn, nullptr, 1);

    cudaFuncSetAttribute(attn_mma_kernel,
                         cudaFuncAttributeMaxDynamicSharedMemorySize,
                         ATTN_SMEM_BYTES);
    attn_mma_kernel<<<dim3(SS / 128, HH, BB), 256, ATTN_SMEM_BYTES>>>();

    mma_gemm<<<dim3(EE / 128, MROWS / 128), 256, GEMM_SMEM_BYTES>>>(
        b_proj, out, 0);
}

// round 9
// speedup vs baseline: 3.0887x; 1.2004x over previous
#include <cuda_runtime.h>
#include <cuda_fp16.h>
#include <cstdint>
#include <math.h>

// Problem constants
#define BB 2
#define SS 2048
#define EE 1024
#define HH 16
#define DD 64
#define MROWS (BB*SS)          // 4096
#define KDIM 1024
#define N_QKV 3072

// ---------------------------------------------------------------------------
// Scratch (allocation-free: device globals) — fp16 hi/lo splits
// ---------------------------------------------------------------------------
__device__ __half g_qhi[BB*HH*SS*DD];
__device__ __half g_qlo[BB*HH*SS*DD];
__device__ __half g_khi[BB*HH*SS*DD];
__device__ __half g_klo[BB*HH*SS*DD];
__device__ __half g_vhi[BB*HH*SS*DD];          // V: hi only (2-pass PV)

__device__ __half g_hhi[MROWS*KDIM];           // hidden hi
__device__ __half g_hlo[MROWS*KDIM];           // hidden lo
__device__ __half g_ahi[MROWS*KDIM];           // attn-out hi (merged heads)
__device__ __half g_alo[MROWS*KDIM];           // attn-out lo
__device__ __half g_wqkvThi[N_QKV*KDIM];       // w_attn^T hi
__device__ __half g_wqkvTlo[N_QKV*KDIM];       // w_attn^T lo (Q/K blocks only)
__device__ __half g_wprojThi[EE*KDIM];         // w_proj^T hi (2-pass: no lo)

// ---------------------------------------------------------------------------
// PTX helpers
// ---------------------------------------------------------------------------
__device__ __forceinline__ uint32_t smem_u32(const void* p) {
    uint32_t a;
    asm("{ .reg .u64 t; cvta.to.shared.u64 t, %1; cvt.u32.u64 %0, t; }"
        : "=r"(a) : "l"(p));
    return a;
}

__device__ __forceinline__ void ldm_x4(uint32_t& r0, uint32_t& r1,
                                       uint32_t& r2, uint32_t& r3,
                                       uint32_t addr) {
    asm volatile("ldmatrix.sync.aligned.m8n8.x4.shared.b16 {%0,%1,%2,%3}, [%4];"
                 : "=r"(r0), "=r"(r1), "=r"(r2), "=r"(r3) : "r"(addr));
}
__device__ __forceinline__ void ldm_x4_t(uint32_t& r0, uint32_t& r1,
                                         uint32_t& r2, uint32_t& r3,
                                         uint32_t addr) {
    asm volatile("ldmatrix.sync.aligned.m8n8.x4.trans.shared.b16 {%0,%1,%2,%3}, [%4];"
                 : "=r"(r0), "=r"(r1), "=r"(r2), "=r"(r3) : "r"(addr));
}

__device__ __forceinline__ void mma_f16(float* d, const uint32_t* a,
                                        uint32_t b0, uint32_t b1) {
    asm volatile(
        "mma.sync.aligned.m16n8k16.row.col.f32.f16.f16.f32 "
        "{%0,%1,%2,%3}, {%4,%5,%6,%7}, {%8,%9}, {%0,%1,%2,%3};"
        : "+f"(d[0]), "+f"(d[1]), "+f"(d[2]), "+f"(d[3])
        : "r"(a[0]), "r"(a[1]), "r"(a[2]), "r"(a[3]), "r"(b0), "r"(b1));
}

__device__ __forceinline__ void cpa16(uint32_t dst, const void* src) {
    asm volatile("cp.async.cg.shared.global [%0], [%1], 16;"
                 :: "r"(dst), "l"(src));
}
#define CPA_COMMIT() asm volatile("cp.async.commit_group;" ::: "memory")
#define CPA_WAIT(n)  asm volatile("cp.async.wait_group %0;" :: "n"(n) : "memory")

// pack two fp32 into f16x2: first arg -> upper half, second -> lower half
__device__ __forceinline__ uint32_t packf16(float hi, float lo) {
    uint32_t d;
    asm("cvt.rn.f16x2.f32 %0, %1, %2;" : "=r"(d) : "f"(hi), "f"(lo));
    return d;
}
__device__ __forceinline__ float lof16(uint32_t u) {
    return __half2float(__ushort_as_half((unsigned short)(u & 0xffffu)));
}
__device__ __forceinline__ float hif16(uint32_t u) {
    return __half2float(__ushort_as_half((unsigned short)(u >> 16)));
}

// ---------------------------------------------------------------------------
// Prep kernel 1: split fp32 -> fp16 hi/lo (hidden)
// ---------------------------------------------------------------------------
__global__ __launch_bounds__(256) void split_kernel(const float* __restrict__ x)
{
    size_t i0 = ((size_t)blockIdx.x * 256 + threadIdx.x) * 4;
    float4 v = *(const float4*)&x[i0];
    __half h0 = __float2half_rn(v.x);
    __half h1 = __float2half_rn(v.y);
    __half h2 = __float2half_rn(v.z);
    __half h3 = __float2half_rn(v.w);
    __half2 hp0; hp0.x = h0; hp0.y = h1;
    __half2 hp1; hp1.x = h2; hp1.y = h3;
    __half2 lp0;
    lp0.x = __float2half_rn(v.x - __half2float(h0));
    lp0.y = __float2half_rn(v.y - __half2float(h1));
    __half2 lp1;
    lp1.x = __float2half_rn(v.z - __half2float(h2));
    lp1.y = __float2half_rn(v.w - __half2float(h3));
    *(__half2*)&g_hhi[i0]     = hp0;
    *(__half2*)&g_hhi[i0 + 2] = hp1;
    *(__half2*)&g_hlo[i0]     = lp0;
    *(__half2*)&g_hlo[i0 + 2] = lp1;
}

// ---------------------------------------------------------------------------
// Prep kernel 2: W [K,N] row-major -> W^T [N,K] fp16 hi/lo
// which 0: w_attn (hi+lo).  which 1: w_proj (hi only; consumed 2-pass)
// ---------------------------------------------------------------------------
__global__ __launch_bounds__(256) void tsplit_kernel(const float* __restrict__ W,
                                                     int which, int N)
{
    __shared__ float t[32][33];
    int n0 = blockIdx.x * 32, k0 = blockIdx.y * 32;
    int tx = threadIdx.x & 31, ty = threadIdx.x >> 5;
#pragma unroll
    for (int r = 0; r < 32; r += 8)
        t[ty + r][tx] = W[(size_t)(k0 + ty + r) * N + n0 + tx];
    __syncthreads();
#pragma unroll
    for (int r = 0; r < 32; r += 8) {
        float v = t[tx][ty + r];
        __half h = __float2half_rn(v);
        size_t o = (size_t)(n0 + ty + r) * KDIM + k0 + tx;
        if (which) {
            g_wprojThi[o] = h;
        } else {
            g_wqkvThi[o] = h;
            g_wqkvTlo[o] = __float2half_rn(v - __half2float(h));
        }
    }
}

// ---------------------------------------------------------------------------
// Tensor-core GEMM: fp16 split, 3-stage cp.async, XOR-swizzled smem.
// Pass count: mode 1 (QKV): 3 passes for Q/K cols (n0<2048), 2 for V cols.
//             mode 0 (proj): 2 passes (B hi only).
// ---------------------------------------------------------------------------
#define BK 32
#define GARR 8192u                        // one 128x32 fp16 array (bytes)
#define GSTAGE (4u * GARR)                // Ahi,Alo,Bhi,Blo = 32 KB
#define GEMM_SMEM_BYTES (3 * GSTAGE)      // 96 KB

__global__ __launch_bounds__(256, 2) void mma_gemm(const float* __restrict__ bias,
                                                   float* __restrict__ outp,
                                                   int mode)
{
    extern __shared__ __half gsm[];
    uint32_t sbase = smem_u32(gsm);
    uint32_t send = sbase + 3u * GSTAGE;

    const __half* Ahi = mode ? g_hhi : g_ahi;
    const __half* Alo = mode ? g_hlo : g_alo;
    const __half* Bhi = mode ? g_wqkvThi : g_wprojThi;
    const __half* Blo = g_wqkvTlo;          // only used when p3

    int tid = threadIdx.x;
    int wid = tid >> 5, lane = tid & 31;
    int warp_m = wid & 1, warp_n = wid >> 1;          // 2 x 4
    int m0 = blockIdx.y * 128, n0 = blockIdx.x * 128;
    const int p3 = (mode == 1) && (n0 < 2048);        // third pass?

    float acc[4][4][4];
#pragma unroll
    for (int i = 0; i < 4; i++)
#pragma unroll
        for (int j = 0; j < 4; j++)
#pragma unroll
            for (int r = 0; r < 4; r++) acc[i][j][r] = 0.0f;

    // ---- load coordinates ----
    int lr = tid >> 1;                 // row 0..127
    int lv0 = (tid & 1) * 2;           // logical vec 0 or 2
    uint32_t swr = (uint32_t)((lr >> 1) & 3);
    uint32_t soff[2];
#pragma unroll
    for (int vv = 0; vv < 2; vv++) {
        uint32_t v = (uint32_t)(lv0 + vv);
        soff[vv] = (uint32_t)(lr * 64) + ((v ^ swr) << 4);
    }

    auto load_stage = [&](uint32_t sb, int kc) {
#pragma unroll
        for (int vv = 0; vv < 2; vv++) {
            int v = lv0 + vv;
            size_t asrc = (size_t)(m0 + lr) * KDIM + kc + v * 8;
            size_t bsrc = (size_t)(n0 + lr) * KDIM + kc + v * 8;
            uint32_t o = soff[vv];
            cpa16(sb + o,             Ahi + asrc);
            cpa16(sb + GARR + o,      Alo + asrc);
            cpa16(sb + 2 * GARR + o,  Bhi + bsrc);
            if (p3) cpa16(sb + 3 * GARR + o, Blo + bsrc);
        }
    };

    // ---- ldmatrix addressing (swizzled) ----
    int lrow = lane & 15, lcol = lane >> 4;
    uint32_t x = (uint32_t)((lrow >> 1) & 3);
    uint32_t coff0 = (((uint32_t)lcol ^ x) << 4);
    uint32_t coff1 = ((((uint32_t)lcol + 2u) ^ x) << 4);
    uint32_t aoff[4], boff[2];
#pragma unroll
    for (int mf = 0; mf < 4; mf++)
        aoff[mf] = (uint32_t)((warp_m * 64 + mf * 16 + lrow) * 64);
#pragma unroll
    for (int pf = 0; pf < 2; pf++)
        boff[pf] = (uint32_t)((warp_n * 32 + pf * 16 + lrow) * 64);

    load_stage(sbase, 0);
    CPA_COMMIT();
    load_stage(sbase + GSTAGE, BK);
    CPA_COMMIT();

    uint32_t sb_c = sbase;                 // compute stage
    uint32_t sb_l = sbase + 2u * GSTAGE;   // next load stage

    const int NITER = KDIM / BK;      // 32
    for (int c = 0; c < NITER; c++) {
        if (c < NITER - 1) { CPA_WAIT(1); } else { CPA_WAIT(0); }
        __syncthreads();
        if (c + 2 < NITER) {
            load_stage(sb_l, (c + 2) * BK);
            CPA_COMMIT();
            sb_l += GSTAGE; if (sb_l == send) sb_l = sbase;
        }

        uint32_t sb = sb_c;
        sb_c += GSTAGE; if (sb_c == send) sb_c = sbase;

#pragma unroll
        for (int ki = 0; ki < 2; ki++) {
            uint32_t coff = ki ? coff1 : coff0;
            uint32_t ah[4][4], al[4][4];
#pragma unroll
            for (int mf = 0; mf < 4; mf++) {
                ldm_x4(ah[mf][0], ah[mf][1], ah[mf][2], ah[mf][3],
                       sb + aoff[mf] + coff);
                ldm_x4(al[mf][0], al[mf][1], al[mf][2], al[mf][3],
                       sb + GARR + aoff[mf] + coff);
            }
            uint32_t bh[4][2];
#pragma unroll
            for (int pf = 0; pf < 2; pf++) {
                uint32_t r0, r1, r2, r3;
                ldm_x4(r0, r1, r2, r3, sb + 2 * GARR + boff[pf] + coff);
                bh[pf * 2 + 0][0] = r0; bh[pf * 2 + 0][1] = r2;
                bh[pf * 2 + 1][0] = r1; bh[pf * 2 + 1][1] = r3;
            }
#pragma unroll
            for (int mf = 0; mf < 4; mf++)
#pragma unroll
                for (int nf = 0; nf < 4; nf++)
                    mma_f16(acc[mf][nf], ah[mf], bh[nf][0], bh[nf][1]);
#pragma unroll
            for (int mf = 0; mf < 4; mf++)
#pragma unroll
                for (int nf = 0; nf < 4; nf++)
                    mma_f16(acc[mf][nf], al[mf], bh[nf][0], bh[nf][1]);
            if (p3) {
                uint32_t bl[4][2];
#pragma unroll
                for (int pf = 0; pf < 2; pf++) {
                    uint32_t r0, r1, r2, r3;
                    ldm_x4(r0, r1, r2, r3, sb + 3 * GARR + boff[pf] + coff);
                    bl[pf * 2 + 0][0] = r0; bl[pf * 2 + 0][1] = r2;
                    bl[pf * 2 + 1][0] = r1; bl[pf * 2 + 1][1] = r3;
                }
#pragma unroll
                for (int mf = 0; mf < 4; mf++)
#pragma unroll
                    for (int nf = 0; nf < 4; nf++)
                        mma_f16(acc[mf][nf], ah[mf], bl[nf][0], bl[nf][1]);
            }
        }
    }

    // Epilogue
    int gID = lane >> 2, tcol = lane & 3;
#pragma unroll
    for (int mf = 0; mf < 4; mf++) {
#pragma unroll
        for (int nf = 0; nf < 4; nf++) {
            int c = n0 + warp_n * 32 + nf * 8 + tcol * 2;
            float2 bv = *(const float2*)&bias[c];
#pragma unroll
            for (int half = 0; half < 2; half++) {
                int r = m0 + warp_m * 64 + mf * 16 + gID + half * 8;
                float2 v;
                v.x = acc[mf][nf][half * 2 + 0] + bv.x;
                v.y = acc[mf][nf][half * 2 + 1] + bv.y;
                if (mode == 0) {
                    *(float2*)&outp[(size_t)r * EE + c] = v;
                } else {
                    int part = c >> 10, e = c & 1023, h = e >> 6, d0 = e & 63;
                    int b = r >> 11, s = r & 2047;
                    size_t base = (((size_t)(b * HH + h)) * SS + s) * DD + d0;
                    uint32_t hp = packf16(v.y, v.x);
                    if (part == 2) {
                        *(uint32_t*)&g_vhi[base] = hp;
                    } else {
                        uint32_t lp = packf16(v.y - hif16(hp), v.x - lof16(hp));
                        if (part == 0) {
                            *(uint32_t*)&g_qhi[base] = hp;
                            *(uint32_t*)&g_qlo[base] = lp;
                        } else {
                            *(uint32_t*)&g_khi[base] = hp;
                            *(uint32_t*)&g_klo[base] = lp;
                        }
                    }
                }
            }
        }
    }
}

// ---------------------------------------------------------------------------
// Tensor-core causal flash attention: fp16 split, QK^T 3-pass, PV 2-pass,
// 2-stage cp.async K/V (Khi,Klo,Vhi), log2 softmax, 2 CTAs/SM.
// ---------------------------------------------------------------------------
#define ALD 72
#define AQ_ELEMS (128 * ALD)
#define AKV_ARR (64 * ALD)
#define AKV_STAGE (3 * AKV_ARR)               // Khi,Klo,Vhi
#define OFF_KV0 (2 * AQ_ELEMS)
#define ATTN_SMEM_ELEMS (2 * AQ_ELEMS + 2 * AKV_STAGE)
#define ATTN_SMEM_BYTES (ATTN_SMEM_ELEMS * 2)   // 92160 B

#define LOG2E 1.4426950408889634f

__global__ __launch_bounds__(256, 2) void attn_mma_kernel()
{
    extern __shared__ __half dsm[];
    __half* Qhi_s = dsm;
    __half* Qlo_s = dsm + AQ_ELEMS;
    uint32_t kvbase = smem_u32(dsm + OFF_KV0);

    int qt = gridDim.x - 1 - blockIdx.x;        // big tiles first
    int h  = blockIdx.y;
    int b  = blockIdx.z;
    int tid = threadIdx.x, wid = tid >> 5, lane = tid & 31;

    size_t bh = ((size_t)(b * HH + h)) * SS * DD;
    const __half* Qhg = g_qhi + bh;
    const __half* Qlg = g_qlo + bh;
    const __half* Khg = g_khi + bh;
    const __half* Klg = g_klo + bh;
    const __half* Vhg = g_vhi + bh;

    int q0 = qt * 128;

    // Q tile (plain loads; covered by first barrier)
#pragma unroll
    for (int t = 0; t < 4; t++) {
        int i = tid + t * 256;
        int r = i >> 3, v = i & 7;
        size_t src = (size_t)(q0 + r) * DD + v * 8;
        uint32_t so = (uint32_t)(r * ALD + v * 8);
        *(uint4*)&Qhi_s[so] = *(const uint4*)(Qhg + src);
        *(uint4*)&Qlo_s[so] = *(const uint4*)(Qlg + src);
    }

    auto load_kv = [&](int st, int k0) {
        uint32_t sb = kvbase + (uint32_t)(st * AKV_STAGE * 2);
#pragma unroll
        for (int t = 0; t < 2; t++) {
            int i = tid + t * 256;
            int r = i >> 3, v = i & 7;
            size_t src = (size_t)(k0 + r) * DD + v * 8;
            uint32_t o = (uint32_t)((r * ALD + v * 8) * 2);
            cpa16(sb + o,                   Khg + src);
            cpa16(sb + AKV_ARR * 2 + o,     Klg + src);
            cpa16(sb + 2 * AKV_ARR * 2 + o, Vhg + src);
        }
    };

    float o[8][4];
#pragma unroll
    for (int j = 0; j < 8; j++)
#pragma unroll
        for (int e = 0; e < 4; e++) o[j][e] = 0.0f;
    float m_[2] = {-1e30f, -1e30f}, l_[2] = {0.0f, 0.0f};

    int lrow = lane & 15, lcol = lane >> 4;
    uint32_t qb_hi = smem_u32(Qhi_s) +
        (uint32_t)(((wid * 16 + lrow) * ALD + lcol * 8) * 2);
    uint32_t qb_lo = qb_hi + (uint32_t)(AQ_ELEMS * 2);
    uint32_t kvo = (uint32_t)((lrow * ALD + lcol * 8) * 2);

    int row0 = q0 + wid * 16 + (lane >> 2);
    const float scale2 = (1.0f / 16.0f) * LOG2E;
    const float maskv = -10000.0f * LOG2E;

    int ktmax = 2 * qt + 1;
    load_kv(0, 0);
    CPA_COMMIT();

    for (int kt = 0; kt <= ktmax; kt++) {
        CPA_WAIT(0);
        __syncthreads();
        if (kt + 1 <= ktmax) {
            load_kv((kt + 1) & 1, (kt + 1) * 64);
            CPA_COMMIT();
        }

        uint32_t sb = kvbase + (uint32_t)((kt & 1) * AKV_STAGE * 2);
        uint32_t kb_hi = sb + kvo;
        uint32_t kb_lo = sb + AKV_ARR * 2 + kvo;
        uint32_t vb_hi = sb + 2 * AKV_ARR * 2 + kvo;
        int k0 = kt * 64;

        float s[8][4];
#pragma unroll
        for (int nf = 0; nf < 8; nf++)
#pragma unroll
            for (int e = 0; e < 4; e++) s[nf][e] = 0.0f;

#pragma unroll
        for (int ks = 0; ks < 4; ks++) {
            uint32_t ah[4], al[4];
            ldm_x4(ah[0], ah[1], ah[2], ah[3], qb_hi + (uint32_t)(ks * 32));
            ldm_x4(al[0], al[1], al[2], al[3], qb_lo + (uint32_t)(ks * 32));
#pragma unroll
            for (int g = 0; g < 4; g++) {
                uint32_t off = (uint32_t)((g * 16 * ALD + ks * 16) * 2);
                uint32_t r0, r1, r2, r3, t0, t1, t2, t3;
                ldm_x4(r0, r1, r2, r3, kb_hi + off);
                ldm_x4(t0, t1, t2, t3, kb_lo + off);
                mma_f16(s[2 * g],     ah, r0, r2);
                mma_f16(s[2 * g + 1], ah, r1, r3);
                mma_f16(s[2 * g],     al, r0, r2);
                mma_f16(s[2 * g + 1], al, r1, r3);
                mma_f16(s[2 * g],     ah, t0, t2);
                mma_f16(s[2 * g + 1], ah, t1, t3);
            }
        }

        if (kt >= ktmax - 1) {
#pragma unroll
            for (int nf = 0; nf < 8; nf++) {
                int cb = k0 + nf * 8 + (lane & 3) * 2;
#pragma unroll
                for (int e = 0; e < 4; e++) {
                    int col = cb + (e & 1);
                    int row = (e < 2) ? row0 : row0 + 8;
                    float v = s[nf][e] * scale2;
                    s[nf][e] = (col > row) ? maskv : v;
                }
            }
        } else {
#pragma unroll
            for (int nf = 0; nf < 8; nf++)
#pragma unroll
                for (int e = 0; e < 4; e++) s[nf][e] *= scale2;
        }

        // online softmax (log2 domain)
#pragma unroll
        for (int i = 0; i < 2; i++) {
            float mx = -1e30f;
#pragma unroll
            for (int nf = 0; nf < 8; nf++)
                mx = fmaxf(mx, fmaxf(s[nf][2 * i], s[nf][2 * i + 1]));
            mx = fmaxf(mx, __shfl_xor_sync(0xffffffffu, mx, 1));
            mx = fmaxf(mx, __shfl_xor_sync(0xffffffffu, mx, 2));
            float mn = fmaxf(m_[i], mx);
            float alpha = exp2f(m_[i] - mn);
            float sum = 0.0f;
#pragma unroll
            for (int nf = 0; nf < 8; nf++) {
                float p0 = exp2f(s[nf][2 * i] - mn);
                float p1 = exp2f(s[nf][2 * i + 1] - mn);
                s[nf][2 * i] = p0; s[nf][2 * i + 1] = p1;
                sum += p0 + p1;
            }
            sum += __shfl_xor_sync(0xffffffffu, sum, 1);
            sum += __shfl_xor_sync(0xffffffffu, sum, 2);
            l_[i] = l_[i] * alpha + sum;
            m_[i] = mn;
#pragma unroll
            for (int j = 0; j < 8; j++) {
                o[j][2 * i] *= alpha; o[j][2 * i + 1] *= alpha;
            }
        }

        // O += P V  (2-pass: P hi + P lo, V hi only)
#pragma unroll
        for (int c = 0; c < 4; c++) {
            uint32_t aph[4], apl[4];
            aph[0] = packf16(s[2 * c][1], s[2 * c][0]);
            aph[1] = packf16(s[2 * c][3], s[2 * c][2]);
            aph[2] = packf16(s[2 * c + 1][1], s[2 * c + 1][0]);
            aph[3] = packf16(s[2 * c + 1][3], s[2 * c + 1][2]);
            apl[0] = packf16(s[2 * c][1] - hif16(aph[0]),
                             s[2 * c][0] - lof16(aph[0]));
            apl[1] = packf16(s[2 * c][3] - hif16(aph[1]),
                             s[2 * c][2] - lof16(aph[1]));
            apl[2] = packf16(s[2 * c + 1][1] - hif16(aph[2]),
                             s[2 * c + 1][0] - lof16(aph[2]));
            apl[3] = packf16(s[2 * c + 1][3] - hif16(aph[3]),
                             s[2 * c + 1][2] - lof16(aph[3]));
#pragma unroll
            for (int g = 0; g < 4; g++) {
                uint32_t off = (uint32_t)((c * 16 * ALD + g * 16) * 2);
                uint32_t r0, r1, r2, r3;
                ldm_x4_t(r0, r1, r2, r3, vb_hi + off);
                mma_f16(o[2 * g],     aph, r0, r1);
                mma_f16(o[2 * g + 1], aph, r2, r3);
                mma_f16(o[2 * g],     apl, r0, r1);
                mma_f16(o[2 * g + 1], apl, r2, r3);
            }
        }
    }

    // epilogue: O/l -> fp16 hi/lo merged-head [B*S, E]
    float inv0 = 1.0f / l_[0], inv1 = 1.0f / l_[1];
    int d0 = (lane & 3) * 2;
    size_t rb0 = ((size_t)(b * SS + row0)) * EE + h * DD;
    size_t rb1 = rb0 + (size_t)8 * EE;
#pragma unroll
    for (int j = 0; j < 8; j++) {
        int d = j * 8 + d0;
        float v0 = o[j][0] * inv0, v1 = o[j][1] * inv0;
        float v2 = o[j][2] * inv1, v3 = o[j][3] * inv1;
        uint32_t h01 = packf16(v1, v0);
        uint32_t l01 = packf16(v1 - hif16(h01), v0 - lof16(h01));
        uint32_t h23 = packf16(v3, v2);
        uint32_t l23 = packf16(v3 - hif16(h23), v2 - lof16(h23));
        *(uint32_t*)&g_ahi[rb0 + d] = h01;
        *(uint32_t*)&g_alo[rb0 + d] = l01;
        *(uint32_t*)&g_ahi[rb1 + d] = h23;
        *(uint32_t*)&g_alo[rb1 + d] = l23;
    }
}

// ---------------------------------------------------------------------------
extern "C" void kernel_launch(void* const* d_in, const int* in_sizes, int n_in,
                              void* d_out, int out_size)
{
    const float* hidden = (const float*)d_in[0];   // [B,S,E]
    const float* w_attn = (const float*)d_in[1];   // [E, 3E]
    const float* b_attn = (const float*)d_in[2];   // [3E]
    const float* w_proj = (const float*)d_in[3];   // [E, E]
    const float* b_proj = (const float*)d_in[4];   // [E]
    float* out = (float*)d_out;                    // [B,S,E] fp32

    split_kernel<<<(MROWS * KDIM) / (256 * 4), 256>>>(hidden);
    tsplit_kernel<<<dim3(N_QKV / 32, KDIM / 32), 256>>>(w_attn, 0, N_QKV);
    tsplit_kernel<<<dim3(EE / 32, KDIM / 32), 256>>>(w_proj, 1, EE);

    cudaFuncSetAttribute(mma_gemm, cudaFuncAttributeMaxDynamicSharedMemorySize,
                         GEMM_SMEM_BYTES);
    mma_gemm<<<dim3(N_QKV / 128, MROWS / 128), 256, GEMM_SMEM_BYTES>>>(
        b_attn, nullptr, 1);

    cudaFuncSetAttribute(attn_mma_kernel,
                         cudaFuncAttributeMaxDynamicSharedMemorySize,
                         ATTN_SMEM_BYTES);
    attn_mma_kernel<<<dim3(SS / 128, HH, BB), 256, ATTN_SMEM_BYTES>>>();

    mma_gemm<<<dim3(EE / 128, MROWS / 128), 256, GEMM_SMEM_BYTES>>>(
        b_proj, out, 0);
}

// round 10
// speedup vs baseline: 3.5505x; 1.1495x over previous
#include <cuda_runtime.h>
#include <cuda_fp16.h>
#include <cstdint>
#include <math.h>

// Problem constants
#define BB 2
#define SS 2048
#define EE 1024
#define HH 16
#define DD 64
#define MROWS (BB*SS)          // 4096
#define KDIM 1024
#define N_QKV 3072

// ---------------------------------------------------------------------------
// Scratch (allocation-free: device globals) — fp16 hi/lo splits
// ---------------------------------------------------------------------------
__device__ __half g_qhi[BB*HH*SS*DD];
__device__ __half g_qlo[BB*HH*SS*DD];
__device__ __half g_khi[BB*HH*SS*DD];
__device__ __half g_klo[BB*HH*SS*DD];
__device__ __half g_vhi[BB*HH*SS*DD];          // V: hi only (1-pass PV)

__device__ __half g_hhi[MROWS*KDIM];           // hidden hi
__device__ __half g_hlo[MROWS*KDIM];           // hidden lo
__device__ __half g_ahi[MROWS*KDIM];           // attn-out (hi only; 1-pass proj)
__device__ __half g_wqkvThi[N_QKV*KDIM];       // w_attn^T hi
__device__ __half g_wqkvTlo[N_QKV*KDIM];       // w_attn^T lo (Q/K blocks only)
__device__ __half g_wprojThi[EE*KDIM];         // w_proj^T hi

// ---------------------------------------------------------------------------
// PTX helpers
// ---------------------------------------------------------------------------
__device__ __forceinline__ uint32_t smem_u32(const void* p) {
    uint32_t a;
    asm("{ .reg .u64 t; cvta.to.shared.u64 t, %1; cvt.u32.u64 %0, t; }"
        : "=r"(a) : "l"(p));
    return a;
}

__device__ __forceinline__ void ldm_x4(uint32_t& r0, uint32_t& r1,
                                       uint32_t& r2, uint32_t& r3,
                                       uint32_t addr) {
    asm volatile("ldmatrix.sync.aligned.m8n8.x4.shared.b16 {%0,%1,%2,%3}, [%4];"
                 : "=r"(r0), "=r"(r1), "=r"(r2), "=r"(r3) : "r"(addr));
}
__device__ __forceinline__ void ldm_x4_t(uint32_t& r0, uint32_t& r1,
                                         uint32_t& r2, uint32_t& r3,
                                         uint32_t addr) {
    asm volatile("ldmatrix.sync.aligned.m8n8.x4.trans.shared.b16 {%0,%1,%2,%3}, [%4];"
                 : "=r"(r0), "=r"(r1), "=r"(r2), "=r"(r3) : "r"(addr));
}

__device__ __forceinline__ void mma_f16(float* d, const uint32_t* a,
                                        uint32_t b0, uint32_t b1) {
    asm volatile(
        "mma.sync.aligned.m16n8k16.row.col.f32.f16.f16.f32 "
        "{%0,%1,%2,%3}, {%4,%5,%6,%7}, {%8,%9}, {%0,%1,%2,%3};"
        : "+f"(d[0]), "+f"(d[1]), "+f"(d[2]), "+f"(d[3])
        : "r"(a[0]), "r"(a[1]), "r"(a[2]), "r"(a[3]), "r"(b0), "r"(b1));
}

__device__ __forceinline__ void cpa16(uint32_t dst, const void* src) {
    asm volatile("cp.async.cg.shared.global [%0], [%1], 16;"
                 :: "r"(dst), "l"(src));
}
#define CPA_COMMIT() asm volatile("cp.async.commit_group;" ::: "memory")
#define CPA_WAIT(n)  asm volatile("cp.async.wait_group %0;" :: "n"(n) : "memory")

__device__ __forceinline__ uint32_t packf16(float hi, float lo) {
    uint32_t d;
    asm("cvt.rn.f16x2.f32 %0, %1, %2;" : "=r"(d) : "f"(hi), "f"(lo));
    return d;
}
__device__ __forceinline__ float lof16(uint32_t u) {
    return __half2float(__ushort_as_half((unsigned short)(u & 0xffffu)));
}
__device__ __forceinline__ float hif16(uint32_t u) {
    return __half2float(__ushort_as_half((unsigned short)(u >> 16)));
}

// ---------------------------------------------------------------------------
// Prep kernel 1: split fp32 -> fp16 hi/lo (hidden)
// ---------------------------------------------------------------------------
__global__ __launch_bounds__(256) void split_kernel(const float* __restrict__ x)
{
    size_t i0 = ((size_t)blockIdx.x * 256 + threadIdx.x) * 4;
    float4 v = *(const float4*)&x[i0];
    __half h0 = __float2half_rn(v.x);
    __half h1 = __float2half_rn(v.y);
    __half h2 = __float2half_rn(v.z);
    __half h3 = __float2half_rn(v.w);
    __half2 hp0; hp0.x = h0; hp0.y = h1;
    __half2 hp1; hp1.x = h2; hp1.y = h3;
    __half2 lp0;
    lp0.x = __float2half_rn(v.x - __half2float(h0));
    lp0.y = __float2half_rn(v.y - __half2float(h1));
    __half2 lp1;
    lp1.x = __float2half_rn(v.z - __half2float(h2));
    lp1.y = __float2half_rn(v.w - __half2float(h3));
    *(__half2*)&g_hhi[i0]     = hp0;
    *(__half2*)&g_hhi[i0 + 2] = hp1;
    *(__half2*)&g_hlo[i0]     = lp0;
    *(__half2*)&g_hlo[i0 + 2] = lp1;
}

// ---------------------------------------------------------------------------
// Prep kernel 2: W [K,N] row-major -> W^T [N,K] fp16 hi/lo
// which 0: w_attn (hi+lo).  which 1: w_proj (hi only)
// ---------------------------------------------------------------------------
__global__ __launch_bounds__(256) void tsplit_kernel(const float* __restrict__ W,
                                                     int which, int N)
{
    __shared__ float t[32][33];
    int n0 = blockIdx.x * 32, k0 = blockIdx.y * 32;
    int tx = threadIdx.x & 31, ty = threadIdx.x >> 5;
#pragma unroll
    for (int r = 0; r < 32; r += 8)
        t[ty + r][tx] = W[(size_t)(k0 + ty + r) * N + n0 + tx];
    __syncthreads();
#pragma unroll
    for (int r = 0; r < 32; r += 8) {
        float v = t[tx][ty + r];
        __half h = __float2half_rn(v);
        size_t o = (size_t)(n0 + ty + r) * KDIM + k0 + tx;
        if (which) {
            g_wprojThi[o] = h;
        } else {
            g_wqkvThi[o] = h;
            g_wqkvTlo[o] = __float2half_rn(v - __half2float(h));
        }
    }
}

// ---------------------------------------------------------------------------
// Tensor-core GEMM: fp16 split, 3-stage cp.async, XOR-swizzled smem.
// p3 = (mode==1 && n0<2048): 3-pass (scores path Q/K).
// else 1-pass pure fp16 (V part of QKV; proj).
// ---------------------------------------------------------------------------
#define BK 32
#define GARR 8192u                        // one 128x32 fp16 array (bytes)
#define GSTAGE (4u * GARR)                // Ahi,Alo,Bhi,Blo = 32 KB
#define GEMM_SMEM_BYTES (3 * GSTAGE)      // 96 KB

__global__ __launch_bounds__(256, 2) void mma_gemm(const float* __restrict__ bias,
                                                   float* __restrict__ outp,
                                                   int mode)
{
    extern __shared__ __half gsm[];
    uint32_t sbase = smem_u32(gsm);
    uint32_t send = sbase + 3u * GSTAGE;

    const __half* Ahi = mode ? g_hhi : g_ahi;
    const __half* Alo = g_hlo;              // only used when p3
    const __half* Bhi = mode ? g_wqkvThi : g_wprojThi;
    const __half* Blo = g_wqkvTlo;          // only used when p3

    int tid = threadIdx.x;
    int wid = tid >> 5, lane = tid & 31;
    int warp_m = wid & 1, warp_n = wid >> 1;          // 2 x 4
    int m0 = blockIdx.y * 128, n0 = blockIdx.x * 128;
    const int p3 = (mode == 1) && (n0 < 2048);        // 3-pass (Q/K)?

    float acc[4][4][4];
#pragma unroll
    for (int i = 0; i < 4; i++)
#pragma unroll
        for (int j = 0; j < 4; j++)
#pragma unroll
            for (int r = 0; r < 4; r++) acc[i][j][r] = 0.0f;

    // ---- load coordinates ----
    int lr = tid >> 1;                 // row 0..127
    int lv0 = (tid & 1) * 2;           // logical vec 0 or 2
    uint32_t swr = (uint32_t)((lr >> 1) & 3);
    uint32_t soff[2];
#pragma unroll
    for (int vv = 0; vv < 2; vv++) {
        uint32_t v = (uint32_t)(lv0 + vv);
        soff[vv] = (uint32_t)(lr * 64) + ((v ^ swr) << 4);
    }

    auto load_stage = [&](uint32_t sb, int kc) {
#pragma unroll
        for (int vv = 0; vv < 2; vv++) {
            int v = lv0 + vv;
            size_t asrc = (size_t)(m0 + lr) * KDIM + kc + v * 8;
            size_t bsrc = (size_t)(n0 + lr) * KDIM + kc + v * 8;
            uint32_t o = soff[vv];
            cpa16(sb + o,             Ahi + asrc);
            cpa16(sb + 2 * GARR + o,  Bhi + bsrc);
            if (p3) {
                cpa16(sb + GARR + o,     Alo + asrc);
                cpa16(sb + 3 * GARR + o, Blo + bsrc);
            }
        }
    };

    // ---- ldmatrix addressing (swizzled) ----
    int lrow = lane & 15, lcol = lane >> 4;
    uint32_t x = (uint32_t)((lrow >> 1) & 3);
    uint32_t coff0 = (((uint32_t)lcol ^ x) << 4);
    uint32_t coff1 = ((((uint32_t)lcol + 2u) ^ x) << 4);
    uint32_t aoff[4], boff[2];
#pragma unroll
    for (int mf = 0; mf < 4; mf++)
        aoff[mf] = (uint32_t)((warp_m * 64 + mf * 16 + lrow) * 64);
#pragma unroll
    for (int pf = 0; pf < 2; pf++)
        boff[pf] = (uint32_t)((warp_n * 32 + pf * 16 + lrow) * 64);

    load_stage(sbase, 0);
    CPA_COMMIT();
    load_stage(sbase + GSTAGE, BK);
    CPA_COMMIT();

    uint32_t sb_c = sbase;                 // compute stage
    uint32_t sb_l = sbase + 2u * GSTAGE;   // next load stage

    const int NITER = KDIM / BK;      // 32
    for (int c = 0; c < NITER; c++) {
        if (c < NITER - 1) { CPA_WAIT(1); } else { CPA_WAIT(0); }
        __syncthreads();
        if (c + 2 < NITER) {
            load_stage(sb_l, (c + 2) * BK);
            CPA_COMMIT();
            sb_l += GSTAGE; if (sb_l == send) sb_l = sbase;
        }

        uint32_t sb = sb_c;
        sb_c += GSTAGE; if (sb_c == send) sb_c = sbase;

#pragma unroll
        for (int ki = 0; ki < 2; ki++) {
            uint32_t coff = ki ? coff1 : coff0;
            uint32_t ah[4][4];
#pragma unroll
            for (int mf = 0; mf < 4; mf++)
                ldm_x4(ah[mf][0], ah[mf][1], ah[mf][2], ah[mf][3],
                       sb + aoff[mf] + coff);
            uint32_t bh[4][2];
#pragma unroll
            for (int pf = 0; pf < 2; pf++) {
                uint32_t r0, r1, r2, r3;
                ldm_x4(r0, r1, r2, r3, sb + 2 * GARR + boff[pf] + coff);
                bh[pf * 2 + 0][0] = r0; bh[pf * 2 + 0][1] = r2;
                bh[pf * 2 + 1][0] = r1; bh[pf * 2 + 1][1] = r3;
            }
#pragma unroll
            for (int mf = 0; mf < 4; mf++)
#pragma unroll
                for (int nf = 0; nf < 4; nf++)
                    mma_f16(acc[mf][nf], ah[mf], bh[nf][0], bh[nf][1]);
            if (p3) {
                uint32_t al[4][4];
#pragma unroll
                for (int mf = 0; mf < 4; mf++)
                    ldm_x4(al[mf][0], al[mf][1], al[mf][2], al[mf][3],
                           sb + GARR + aoff[mf] + coff);
#pragma unroll
                for (int mf = 0; mf < 4; mf++)
#pragma unroll
                    for (int nf = 0; nf < 4; nf++)
                        mma_f16(acc[mf][nf], al[mf], bh[nf][0], bh[nf][1]);
                uint32_t bl[4][2];
#pragma unroll
                for (int pf = 0; pf < 2; pf++) {
                    uint32_t r0, r1, r2, r3;
                    ldm_x4(r0, r1, r2, r3, sb + 3 * GARR + boff[pf] + coff);
                    bl[pf * 2 + 0][0] = r0; bl[pf * 2 + 0][1] = r2;
                    bl[pf * 2 + 1][0] = r1; bl[pf * 2 + 1][1] = r3;
                }
#pragma unroll
                for (int mf = 0; mf < 4; mf++)
#pragma unroll
                    for (int nf = 0; nf < 4; nf++)
                        mma_f16(acc[mf][nf], ah[mf], bl[nf][0], bl[nf][1]);
            }
        }
    }

    // Epilogue
    int gID = lane >> 2, tcol = lane & 3;
#pragma unroll
    for (int mf = 0; mf < 4; mf++) {
#pragma unroll
        for (int nf = 0; nf < 4; nf++) {
            int c = n0 + warp_n * 32 + nf * 8 + tcol * 2;
            float2 bv = *(const float2*)&bias[c];
#pragma unroll
            for (int half = 0; half < 2; half++) {
                int r = m0 + warp_m * 64 + mf * 16 + gID + half * 8;
                float2 v;
                v.x = acc[mf][nf][half * 2 + 0] + bv.x;
                v.y = acc[mf][nf][half * 2 + 1] + bv.y;
                if (mode == 0) {
                    *(float2*)&outp[(size_t)r * EE + c] = v;
                } else {
                    int part = c >> 10, e = c & 1023, h = e >> 6, d0 = e & 63;
                    int b = r >> 11, s = r & 2047;
                    size_t base = (((size_t)(b * HH + h)) * SS + s) * DD + d0;
                    uint32_t hp = packf16(v.y, v.x);
                    if (part == 2) {
                        *(uint32_t*)&g_vhi[base] = hp;
                    } else {
                        uint32_t lp = packf16(v.y - hif16(hp), v.x - lof16(hp));
                        if (part == 0) {
                            *(uint32_t*)&g_qhi[base] = hp;
                            *(uint32_t*)&g_qlo[base] = lp;
                        } else {
                            *(uint32_t*)&g_khi[base] = hp;
                            *(uint32_t*)&g_klo[base] = lp;
                        }
                    }
                }
            }
        }
    }
}

// ---------------------------------------------------------------------------
// Tensor-core causal flash attention: QK^T 3-pass fp16 split, PV 1-pass,
// 2-stage cp.async K/V (Khi,Klo,Vhi), log2 softmax, 2 CTAs/SM.
// ---------------------------------------------------------------------------
#define ALD 72
#define AQ_ELEMS (128 * ALD)
#define AKV_ARR (64 * ALD)
#define AKV_STAGE (3 * AKV_ARR)               // Khi,Klo,Vhi
#define OFF_KV0 (2 * AQ_ELEMS)
#define ATTN_SMEM_ELEMS (2 * AQ_ELEMS + 2 * AKV_STAGE)
#define ATTN_SMEM_BYTES (ATTN_SMEM_ELEMS * 2)   // 92160 B

#define LOG2E 1.4426950408889634f

__global__ __launch_bounds__(256, 2) void attn_mma_kernel()
{
    extern __shared__ __half dsm[];
    __half* Qhi_s = dsm;
    __half* Qlo_s = dsm + AQ_ELEMS;
    uint32_t kvbase = smem_u32(dsm + OFF_KV0);

    int qt = gridDim.x - 1 - blockIdx.x;        // big tiles first
    int h  = blockIdx.y;
    int b  = blockIdx.z;
    int tid = threadIdx.x, wid = tid >> 5, lane = tid & 31;

    size_t bh = ((size_t)(b * HH + h)) * SS * DD;
    const __half* Qhg = g_qhi + bh;
    const __half* Qlg = g_qlo + bh;
    const __half* Khg = g_khi + bh;
    const __half* Klg = g_klo + bh;
    const __half* Vhg = g_vhi + bh;

    int q0 = qt * 128;

#pragma unroll
    for (int t = 0; t < 4; t++) {
        int i = tid + t * 256;
        int r = i >> 3, v = i & 7;
        size_t src = (size_t)(q0 + r) * DD + v * 8;
        uint32_t so = (uint32_t)(r * ALD + v * 8);
        *(uint4*)&Qhi_s[so] = *(const uint4*)(Qhg + src);
        *(uint4*)&Qlo_s[so] = *(const uint4*)(Qlg + src);
    }

    auto load_kv = [&](int st, int k0) {
        uint32_t sb = kvbase + (uint32_t)(st * AKV_STAGE * 2);
#pragma unroll
        for (int t = 0; t < 2; t++) {
            int i = tid + t * 256;
            int r = i >> 3, v = i & 7;
            size_t src = (size_t)(k0 + r) * DD + v * 8;
            uint32_t o = (uint32_t)((r * ALD + v * 8) * 2);
            cpa16(sb + o,                   Khg + src);
            cpa16(sb + AKV_ARR * 2 + o,     Klg + src);
            cpa16(sb + 2 * AKV_ARR * 2 + o, Vhg + src);
        }
    };

    float o[8][4];
#pragma unroll
    for (int j = 0; j < 8; j++)
#pragma unroll
        for (int e = 0; e < 4; e++) o[j][e] = 0.0f;
    float m_[2] = {-1e30f, -1e30f}, l_[2] = {0.0f, 0.0f};

    int lrow = lane & 15, lcol = lane >> 4;
    uint32_t qb_hi = smem_u32(Qhi_s) +
        (uint32_t)(((wid * 16 + lrow) * ALD + lcol * 8) * 2);
    uint32_t qb_lo = qb_hi + (uint32_t)(AQ_ELEMS * 2);
    uint32_t kvo = (uint32_t)((lrow * ALD + lcol * 8) * 2);

    int row0 = q0 + wid * 16 + (lane >> 2);
    const float scale2 = (1.0f / 16.0f) * LOG2E;
    const float maskv = -10000.0f * LOG2E;

    int ktmax = 2 * qt + 1;
    load_kv(0, 0);
    CPA_COMMIT();

    for (int kt = 0; kt <= ktmax; kt++) {
        CPA_WAIT(0);
        __syncthreads();
        if (kt + 1 <= ktmax) {
            load_kv((kt + 1) & 1, (kt + 1) * 64);
            CPA_COMMIT();
        }

        uint32_t sb = kvbase + (uint32_t)((kt & 1) * AKV_STAGE * 2);
        uint32_t kb_hi = sb + kvo;
        uint32_t kb_lo = sb + AKV_ARR * 2 + kvo;
        uint32_t vb_hi = sb + 2 * AKV_ARR * 2 + kvo;
        int k0 = kt * 64;

        float s[8][4];
#pragma unroll
        for (int nf = 0; nf < 8; nf++)
#pragma unroll
            for (int e = 0; e < 4; e++) s[nf][e] = 0.0f;

#pragma unroll
        for (int ks = 0; ks < 4; ks++) {
            uint32_t ah[4], al[4];
            ldm_x4(ah[0], ah[1], ah[2], ah[3], qb_hi + (uint32_t)(ks * 32));
            ldm_x4(al[0], al[1], al[2], al[3], qb_lo + (uint32_t)(ks * 32));
#pragma unroll
            for (int g = 0; g < 4; g++) {
                uint32_t off = (uint32_t)((g * 16 * ALD + ks * 16) * 2);
                uint32_t r0, r1, r2, r3, t0, t1, t2, t3;
                ldm_x4(r0, r1, r2, r3, kb_hi + off);
                ldm_x4(t0, t1, t2, t3, kb_lo + off);
                mma_f16(s[2 * g],     ah, r0, r2);
                mma_f16(s[2 * g + 1], ah, r1, r3);
                mma_f16(s[2 * g],     al, r0, r2);
                mma_f16(s[2 * g + 1], al, r1, r3);
                mma_f16(s[2 * g],     ah, t0, t2);
                mma_f16(s[2 * g + 1], ah, t1, t3);
            }
        }

        if (kt >= ktmax - 1) {
#pragma unroll
            for (int nf = 0; nf < 8; nf++) {
                int cb = k0 + nf * 8 + (lane & 3) * 2;
#pragma unroll
                for (int e = 0; e < 4; e++) {
                    int col = cb + (e & 1);
                    int row = (e < 2) ? row0 : row0 + 8;
                    float v = s[nf][e] * scale2;
                    s[nf][e] = (col > row) ? maskv : v;
                }
            }
        } else {
#pragma unroll
            for (int nf = 0; nf < 8; nf++)
#pragma unroll
                for (int e = 0; e < 4; e++) s[nf][e] *= scale2;
        }

        // online softmax (log2 domain)
#pragma unroll
        for (int i = 0; i < 2; i++) {
            float mx = -1e30f;
#pragma unroll
            for (int nf = 0; nf < 8; nf++)
                mx = fmaxf(mx, fmaxf(s[nf][2 * i], s[nf][2 * i + 1]));
            mx = fmaxf(mx, __shfl_xor_sync(0xffffffffu, mx, 1));
            mx = fmaxf(mx, __shfl_xor_sync(0xffffffffu, mx, 2));
            float mn = fmaxf(m_[i], mx);
            float alpha = exp2f(m_[i] - mn);
            float sum = 0.0f;
#pragma unroll
            for (int nf = 0; nf < 8; nf++) {
                float p0 = exp2f(s[nf][2 * i] - mn);
                float p1 = exp2f(s[nf][2 * i + 1] - mn);
                s[nf][2 * i] = p0; s[nf][2 * i + 1] = p1;
                sum += p0 + p1;
            }
            sum += __shfl_xor_sync(0xffffffffu, sum, 1);
            sum += __shfl_xor_sync(0xffffffffu, sum, 2);
            l_[i] = l_[i] * alpha + sum;
            m_[i] = mn;
#pragma unroll
            for (int j = 0; j < 8; j++) {
                o[j][2 * i] *= alpha; o[j][2 * i + 1] *= alpha;
            }
        }

        // O += P V  (1-pass: P hi only, V hi only)
#pragma unroll
        for (int c = 0; c < 4; c++) {
            uint32_t aph[4];
            aph[0] = packf16(s[2 * c][1], s[2 * c][0]);
            aph[1] = packf16(s[2 * c][3], s[2 * c][2]);
            aph[2] = packf16(s[2 * c + 1][1], s[2 * c + 1][0]);
            aph[3] = packf16(s[2 * c + 1][3], s[2 * c + 1][2]);
#pragma unroll
            for (int g = 0; g < 4; g++) {
                uint32_t off = (uint32_t)((c * 16 * ALD + g * 16) * 2);
                uint32_t r0, r1, r2, r3;
                ldm_x4_t(r0, r1, r2, r3, vb_hi + off);
                mma_f16(o[2 * g],     aph, r0, r1);
                mma_f16(o[2 * g + 1], aph, r2, r3);
            }
        }
    }

    // epilogue: O/l -> fp16 (hi only) merged-head [B*S, E]
    float inv0 = 1.0f / l_[0], inv1 = 1.0f / l_[1];
    int d0 = (lane & 3) * 2;
    size_t rb0 = ((size_t)(b * SS + row0)) * EE + h * DD;
    size_t rb1 = rb0 + (size_t)8 * EE;
#pragma unroll
    for (int j = 0; j < 8; j++) {
        int d = j * 8 + d0;
        float v0 = o[j][0] * inv0, v1 = o[j][1] * inv0;
        float v2 = o[j][2] * inv1, v3 = o[j][3] * inv1;
        *(uint32_t*)&g_ahi[rb0 + d] = packf16(v1, v0);
        *(uint32_t*)&g_ahi[rb1 + d] = packf16(v3, v2);
    }
}

// ---------------------------------------------------------------------------
extern "C" void kernel_launch(void* const* d_in, const int* in_sizes, int n_in,
                              void* d_out, int out_size)
{
    const float* hidden = (const float*)d_in[0];   // [B,S,E]
    const float* w_attn = (const float*)d_in[1];   // [E, 3E]
    const float* b_attn = (const float*)d_in[2];   // [3E]
    const float* w_proj = (const float*)d_in[3];   // [E, E]
    const float* b_proj = (const float*)d_in[4];   // [E]
    float* out = (float*)d_out;                    // [B,S,E] fp32

    split_kernel<<<(MROWS * KDIM) / (256 * 4), 256>>>(hidden);
    tsplit_kernel<<<dim3(N_QKV / 32, KDIM / 32), 256>>>(w_attn, 0, N_QKV);
    tsplit_kernel<<<dim3(EE / 32, KDIM / 32), 256>>>(w_proj, 1, EE);

    cudaFuncSetAttribute(mma_gemm, cudaFuncAttributeMaxDynamicSharedMemorySize,
                         GEMM_SMEM_BYTES);
    mma_gemm<<<dim3(N_QKV / 128, MROWS / 128), 256, GEMM_SMEM_BYTES>>>(
        b_attn, nullptr, 1);

    cudaFuncSetAttribute(attn_mma_kernel,
                         cudaFuncAttributeMaxDynamicSharedMemorySize,
                         ATTN_SMEM_BYTES);
    attn_mma_kernel<<<dim3(SS / 128, HH, BB), 256, ATTN_SMEM_BYTES>>>();

    mma_gemm<<<dim3(EE / 128, MROWS / 128), 256, GEMM_SMEM_BYTES>>>(
        b_proj, out, 0);
}

// round 11
// speedup vs baseline: 3.5904x; 1.0112x over previous
#include <cuda_runtime.h>
#include <cuda_fp16.h>
#include <cstdint>
#include <math.h>

// Problem constants
#define BB 2
#define SS 2048
#define EE 1024
#define HH 16
#define DD 64
#define MROWS (BB*SS)          // 4096
#define KDIM 1024
#define N_QKV 3072

// ---------------------------------------------------------------------------
// Scratch (allocation-free: device globals) — fp16 hi/lo splits
// ---------------------------------------------------------------------------
__device__ __half g_qhi[BB*HH*SS*DD];
__device__ __half g_qlo[BB*HH*SS*DD];
__device__ __half g_khi[BB*HH*SS*DD];
__device__ __half g_klo[BB*HH*SS*DD];
__device__ __half g_vhi[BB*HH*SS*DD];          // V: hi only (1-pass PV)

__device__ __half g_hhi[MROWS*KDIM];           // hidden hi
__device__ __half g_hlo[MROWS*KDIM];           // hidden lo
__device__ __half g_ahi[MROWS*KDIM];           // attn-out (hi only; 1-pass proj)
__device__ __half g_wqkvThi[N_QKV*KDIM];       // w_attn^T hi
__device__ __half g_wqkvTlo[N_QKV*KDIM];       // w_attn^T lo (Q/K blocks only)
__device__ __half g_wprojThi[EE*KDIM];         // w_proj^T hi

// ---------------------------------------------------------------------------
// PTX helpers
// ---------------------------------------------------------------------------
__device__ __forceinline__ uint32_t smem_u32(const void* p) {
    uint32_t a;
    asm("{ .reg .u64 t; cvta.to.shared.u64 t, %1; cvt.u32.u64 %0, t; }"
        : "=r"(a) : "l"(p));
    return a;
}

__device__ __forceinline__ void ldm_x4(uint32_t& r0, uint32_t& r1,
                                       uint32_t& r2, uint32_t& r3,
                                       uint32_t addr) {
    asm volatile("ldmatrix.sync.aligned.m8n8.x4.shared.b16 {%0,%1,%2,%3}, [%4];"
                 : "=r"(r0), "=r"(r1), "=r"(r2), "=r"(r3) : "r"(addr));
}
__device__ __forceinline__ void ldm_x4_t(uint32_t& r0, uint32_t& r1,
                                         uint32_t& r2, uint32_t& r3,
                                         uint32_t addr) {
    asm volatile("ldmatrix.sync.aligned.m8n8.x4.trans.shared.b16 {%0,%1,%2,%3}, [%4];"
                 : "=r"(r0), "=r"(r1), "=r"(r2), "=r"(r3) : "r"(addr));
}

__device__ __forceinline__ void mma_f16(float* d, const uint32_t* a,
                                        uint32_t b0, uint32_t b1) {
    asm volatile(
        "mma.sync.aligned.m16n8k16.row.col.f32.f16.f16.f32 "
        "{%0,%1,%2,%3}, {%4,%5,%6,%7}, {%8,%9}, {%0,%1,%2,%3};"
        : "+f"(d[0]), "+f"(d[1]), "+f"(d[2]), "+f"(d[3])
        : "r"(a[0]), "r"(a[1]), "r"(a[2]), "r"(a[3]), "r"(b0), "r"(b1));
}

__device__ __forceinline__ void cpa16(uint32_t dst, const void* src) {
    asm volatile("cp.async.cg.shared.global [%0], [%1], 16;"
                 :: "r"(dst), "l"(src));
}
#define CPA_COMMIT() asm volatile("cp.async.commit_group;" ::: "memory")
#define CPA_WAIT(n)  asm volatile("cp.async.wait_group %0;" :: "n"(n) : "memory")

__device__ __forceinline__ uint32_t packf16(float hi, float lo) {
    uint32_t d;
    asm("cvt.rn.f16x2.f32 %0, %1, %2;" : "=r"(d) : "f"(hi), "f"(lo));
    return d;
}
__device__ __forceinline__ float lof16(uint32_t u) {
    return __half2float(__ushort_as_half((unsigned short)(u & 0xffffu)));
}
__device__ __forceinline__ float hif16(uint32_t u) {
    return __half2float(__ushort_as_half((unsigned short)(u >> 16)));
}
// guaranteed-MUFU exp2 (independent of fast-math flags)
__device__ __forceinline__ float ex2(float x) {
    float y;
    asm("ex2.approx.f32 %0, %1;" : "=f"(y) : "f"(x));
    return y;
}

// ---------------------------------------------------------------------------
// Prep kernel 1: split fp32 -> fp16 hi/lo (hidden)
// ---------------------------------------------------------------------------
__global__ __launch_bounds__(256) void split_kernel(const float* __restrict__ x)
{
    size_t i0 = ((size_t)blockIdx.x * 256 + threadIdx.x) * 4;
    float4 v = *(const float4*)&x[i0];
    __half h0 = __float2half_rn(v.x);
    __half h1 = __float2half_rn(v.y);
    __half h2 = __float2half_rn(v.z);
    __half h3 = __float2half_rn(v.w);
    __half2 hp0; hp0.x = h0; hp0.y = h1;
    __half2 hp1; hp1.x = h2; hp1.y = h3;
    __half2 lp0;
    lp0.x = __float2half_rn(v.x - __half2float(h0));
    lp0.y = __float2half_rn(v.y - __half2float(h1));
    __half2 lp1;
    lp1.x = __float2half_rn(v.z - __half2float(h2));
    lp1.y = __float2half_rn(v.w - __half2float(h3));
    *(__half2*)&g_hhi[i0]     = hp0;
    *(__half2*)&g_hhi[i0 + 2] = hp1;
    *(__half2*)&g_hlo[i0]     = lp0;
    *(__half2*)&g_hlo[i0 + 2] = lp1;
}

// ---------------------------------------------------------------------------
// Prep kernel 2: W [K,N] row-major -> W^T [N,K] fp16 hi/lo
// which 0: w_attn (hi+lo).  which 1: w_proj (hi only)
// ---------------------------------------------------------------------------
__global__ __launch_bounds__(256) void tsplit_kernel(const float* __restrict__ W,
                                                     int which, int N)
{
    __shared__ float t[32][33];
    int n0 = blockIdx.x * 32, k0 = blockIdx.y * 32;
    int tx = threadIdx.x & 31, ty = threadIdx.x >> 5;
#pragma unroll
    for (int r = 0; r < 32; r += 8)
        t[ty + r][tx] = W[(size_t)(k0 + ty + r) * N + n0 + tx];
    __syncthreads();
#pragma unroll
    for (int r = 0; r < 32; r += 8) {
        float v = t[tx][ty + r];
        __half h = __float2half_rn(v);
        size_t o = (size_t)(n0 + ty + r) * KDIM + k0 + tx;
        if (which) {
            g_wprojThi[o] = h;
        } else {
            g_wqkvThi[o] = h;
            g_wqkvTlo[o] = __float2half_rn(v - __half2float(h));
        }
    }
}

// ---------------------------------------------------------------------------
// Tensor-core GEMM: fp16 split, 3-stage cp.async, XOR-swizzled smem.
// p3 = (mode==1 && n0<2048): 3-pass (scores path Q/K).
// else 1-pass pure fp16 (V part of QKV; proj).
// ---------------------------------------------------------------------------
#define BK 32
#define GARR 8192u                        // one 128x32 fp16 array (bytes)
#define GSTAGE (4u * GARR)                // Ahi,Alo,Bhi,Blo = 32 KB
#define GEMM_SMEM_BYTES (3 * GSTAGE)      // 96 KB

__global__ __launch_bounds__(256, 2) void mma_gemm(const float* __restrict__ bias,
                                                   float* __restrict__ outp,
                                                   int mode)
{
    extern __shared__ __half gsm[];
    uint32_t sbase = smem_u32(gsm);
    uint32_t send = sbase + 3u * GSTAGE;

    const __half* Ahi = mode ? g_hhi : g_ahi;
    const __half* Alo = g_hlo;              // only used when p3
    const __half* Bhi = mode ? g_wqkvThi : g_wprojThi;
    const __half* Blo = g_wqkvTlo;          // only used when p3

    int tid = threadIdx.x;
    int wid = tid >> 5, lane = tid & 31;
    int warp_m = wid & 1, warp_n = wid >> 1;          // 2 x 4
    int m0 = blockIdx.y * 128, n0 = blockIdx.x * 128;
    const int p3 = (mode == 1) && (n0 < 2048);        // 3-pass (Q/K)?

    float acc[4][4][4];
#pragma unroll
    for (int i = 0; i < 4; i++)
#pragma unroll
        for (int j = 0; j < 4; j++)
#pragma unroll
            for (int r = 0; r < 4; r++) acc[i][j][r] = 0.0f;

    // ---- load coordinates ----
    int lr = tid >> 1;                 // row 0..127
    int lv0 = (tid & 1) * 2;           // logical vec 0 or 2
    uint32_t swr = (uint32_t)((lr >> 1) & 3);
    uint32_t soff[2];
#pragma unroll
    for (int vv = 0; vv < 2; vv++) {
        uint32_t v = (uint32_t)(lv0 + vv);
        soff[vv] = (uint32_t)(lr * 64) + ((v ^ swr) << 4);
    }

    auto load_stage = [&](uint32_t sb, int kc) {
#pragma unroll
        for (int vv = 0; vv < 2; vv++) {
            int v = lv0 + vv;
            size_t asrc = (size_t)(m0 + lr) * KDIM + kc + v * 8;
            size_t bsrc = (size_t)(n0 + lr) * KDIM + kc + v * 8;
            uint32_t o = soff[vv];
            cpa16(sb + o,             Ahi + asrc);
            cpa16(sb + 2 * GARR + o,  Bhi + bsrc);
            if (p3) {
                cpa16(sb + GARR + o,     Alo + asrc);
                cpa16(sb + 3 * GARR + o, Blo + bsrc);
            }
        }
    };

    // ---- ldmatrix addressing (swizzled) ----
    int lrow = lane & 15, lcol = lane >> 4;
    uint32_t x = (uint32_t)((lrow >> 1) & 3);
    uint32_t coff0 = (((uint32_t)lcol ^ x) << 4);
    uint32_t coff1 = ((((uint32_t)lcol + 2u) ^ x) << 4);
    uint32_t aoff[4], boff[2];
#pragma unroll
    for (int mf = 0; mf < 4; mf++)
        aoff[mf] = (uint32_t)((warp_m * 64 + mf * 16 + lrow) * 64);
#pragma unroll
    for (int pf = 0; pf < 2; pf++)
        boff[pf] = (uint32_t)((warp_n * 32 + pf * 16 + lrow) * 64);

    load_stage(sbase, 0);
    CPA_COMMIT();
    load_stage(sbase + GSTAGE, BK);
    CPA_COMMIT();

    uint32_t sb_c = sbase;                 // compute stage
    uint32_t sb_l = sbase + 2u * GSTAGE;   // next load stage

    const int NITER = KDIM / BK;      // 32
    for (int c = 0; c < NITER; c++) {
        if (c < NITER - 1) { CPA_WAIT(1); } else { CPA_WAIT(0); }
        __syncthreads();
        if (c + 2 < NITER) {
            load_stage(sb_l, (c + 2) * BK);
            CPA_COMMIT();
            sb_l += GSTAGE; if (sb_l == send) sb_l = sbase;
        }

        uint32_t sb = sb_c;
        sb_c += GSTAGE; if (sb_c == send) sb_c = sbase;

#pragma unroll
        for (int ki = 0; ki < 2; ki++) {
            uint32_t coff = ki ? coff1 : coff0;
            uint32_t ah[4][4];
#pragma unroll
            for (int mf = 0; mf < 4; mf++)
                ldm_x4(ah[mf][0], ah[mf][1], ah[mf][2], ah[mf][3],
                       sb + aoff[mf] + coff);
            uint32_t bh[4][2];
#pragma unroll
            for (int pf = 0; pf < 2; pf++) {
                uint32_t r0, r1, r2, r3;
                ldm_x4(r0, r1, r2, r3, sb + 2 * GARR + boff[pf] + coff);
                bh[pf * 2 + 0][0] = r0; bh[pf * 2 + 0][1] = r2;
                bh[pf * 2 + 1][0] = r1; bh[pf * 2 + 1][1] = r3;
            }
#pragma unroll
            for (int mf = 0; mf < 4; mf++)
#pragma unroll
                for (int nf = 0; nf < 4; nf++)
                    mma_f16(acc[mf][nf], ah[mf], bh[nf][0], bh[nf][1]);
            if (p3) {
                uint32_t al[4][4];
#pragma unroll
                for (int mf = 0; mf < 4; mf++)
                    ldm_x4(al[mf][0], al[mf][1], al[mf][2], al[mf][3],
                           sb + GARR + aoff[mf] + coff);
#pragma unroll
                for (int mf = 0; mf < 4; mf++)
#pragma unroll
                    for (int nf = 0; nf < 4; nf++)
                        mma_f16(acc[mf][nf], al[mf], bh[nf][0], bh[nf][1]);
                uint32_t bl[4][2];
#pragma unroll
                for (int pf = 0; pf < 2; pf++) {
                    uint32_t r0, r1, r2, r3;
                    ldm_x4(r0, r1, r2, r3, sb + 3 * GARR + boff[pf] + coff);
                    bl[pf * 2 + 0][0] = r0; bl[pf * 2 + 0][1] = r2;
                    bl[pf * 2 + 1][0] = r1; bl[pf * 2 + 1][1] = r3;
                }
#pragma unroll
                for (int mf = 0; mf < 4; mf++)
#pragma unroll
                    for (int nf = 0; nf < 4; nf++)
                        mma_f16(acc[mf][nf], ah[mf], bl[nf][0], bl[nf][1]);
            }
        }
    }

    // Epilogue
    int gID = lane >> 2, tcol = lane & 3;
#pragma unroll
    for (int mf = 0; mf < 4; mf++) {
#pragma unroll
        for (int nf = 0; nf < 4; nf++) {
            int c = n0 + warp_n * 32 + nf * 8 + tcol * 2;
            float2 bv = *(const float2*)&bias[c];
#pragma unroll
            for (int half = 0; half < 2; half++) {
                int r = m0 + warp_m * 64 + mf * 16 + gID + half * 8;
                float2 v;
                v.x = acc[mf][nf][half * 2 + 0] + bv.x;
                v.y = acc[mf][nf][half * 2 + 1] + bv.y;
                if (mode == 0) {
                    *(float2*)&outp[(size_t)r * EE + c] = v;
                } else {
                    int part = c >> 10, e = c & 1023, h = e >> 6, d0 = e & 63;
                    int b = r >> 11, s = r & 2047;
                    size_t base = (((size_t)(b * HH + h)) * SS + s) * DD + d0;
                    uint32_t hp = packf16(v.y, v.x);
                    if (part == 2) {
                        *(uint32_t*)&g_vhi[base] = hp;
                    } else {
                        uint32_t lp = packf16(v.y - hif16(hp), v.x - lof16(hp));
                        if (part == 0) {
                            *(uint32_t*)&g_qhi[base] = hp;
                            *(uint32_t*)&g_qlo[base] = lp;
                        } else {
                            *(uint32_t*)&g_khi[base] = hp;
                            *(uint32_t*)&g_klo[base] = lp;
                        }
                    }
                }
            }
        }
    }
}

// ---------------------------------------------------------------------------
// Tensor-core causal flash attention: QK^T 3-pass fp16 split, PV 1-pass,
// Q fragments hoisted to registers, 2-stage cp.async K/V, MUFU exp2.
// ---------------------------------------------------------------------------
#define ALD 72
#define AQ_ELEMS (128 * ALD)
#define AKV_ARR (64 * ALD)
#define AKV_STAGE (3 * AKV_ARR)               // Khi,Klo,Vhi
#define OFF_KV0 (2 * AQ_ELEMS)
#define ATTN_SMEM_ELEMS (2 * AQ_ELEMS + 2 * AKV_STAGE)
#define ATTN_SMEM_BYTES (ATTN_SMEM_ELEMS * 2)   // 92160 B

#define LOG2E 1.4426950408889634f

__global__ __launch_bounds__(256, 2) void attn_mma_kernel()
{
    extern __shared__ __half dsm[];
    __half* Qhi_s = dsm;
    __half* Qlo_s = dsm + AQ_ELEMS;
    uint32_t kvbase = smem_u32(dsm + OFF_KV0);

    int qt = gridDim.x - 1 - blockIdx.x;        // big tiles first
    int h  = blockIdx.y;
    int b  = blockIdx.z;
    int tid = threadIdx.x, wid = tid >> 5, lane = tid & 31;

    size_t bh = ((size_t)(b * HH + h)) * SS * DD;
    const __half* Qhg = g_qhi + bh;
    const __half* Qlg = g_qlo + bh;
    const __half* Khg = g_khi + bh;
    const __half* Klg = g_klo + bh;
    const __half* Vhg = g_vhi + bh;

    int q0 = qt * 128;

    // Q tile into smem
#pragma unroll
    for (int t = 0; t < 4; t++) {
        int i = tid + t * 256;
        int r = i >> 3, v = i & 7;
        size_t src = (size_t)(q0 + r) * DD + v * 8;
        uint32_t so = (uint32_t)(r * ALD + v * 8);
        *(uint4*)&Qhi_s[so] = *(const uint4*)(Qhg + src);
        *(uint4*)&Qlo_s[so] = *(const uint4*)(Qlg + src);
    }

    auto load_kv = [&](int st, int k0) {
        uint32_t sb = kvbase + (uint32_t)(st * AKV_STAGE * 2);
#pragma unroll
        for (int t = 0; t < 2; t++) {
            int i = tid + t * 256;
            int r = i >> 3, v = i & 7;
            size_t src = (size_t)(k0 + r) * DD + v * 8;
            uint32_t o = (uint32_t)((r * ALD + v * 8) * 2);
            cpa16(sb + o,                   Khg + src);
            cpa16(sb + AKV_ARR * 2 + o,     Klg + src);
            cpa16(sb + 2 * AKV_ARR * 2 + o, Vhg + src);
        }
    };

    // stage-0 KV loads can be issued right away (independent of Q smem)
    load_kv(0, 0);
    CPA_COMMIT();

    int lrow = lane & 15, lcol = lane >> 4;
    uint32_t qb_hi = smem_u32(Qhi_s) +
        (uint32_t)(((wid * 16 + lrow) * ALD + lcol * 8) * 2);
    uint32_t qb_lo = qb_hi + (uint32_t)(AQ_ELEMS * 2);
    uint32_t kvo = (uint32_t)((lrow * ALD + lcol * 8) * 2);

    // Hoist Q fragments into registers (one-time)
    __syncthreads();
    uint32_t qh[4][4], ql[4][4];
#pragma unroll
    for (int ks = 0; ks < 4; ks++) {
        ldm_x4(qh[ks][0], qh[ks][1], qh[ks][2], qh[ks][3],
               qb_hi + (uint32_t)(ks * 32));
        ldm_x4(ql[ks][0], ql[ks][1], ql[ks][2], ql[ks][3],
               qb_lo + (uint32_t)(ks * 32));
    }

    float o[8][4];
#pragma unroll
    for (int j = 0; j < 8; j++)
#pragma unroll
        for (int e = 0; e < 4; e++) o[j][e] = 0.0f;
    float m_[2] = {-1e30f, -1e30f}, l_[2] = {0.0f, 0.0f};

    int row0 = q0 + wid * 16 + (lane >> 2);
    const float scale2 = (1.0f / 16.0f) * LOG2E;
    const float maskv = -10000.0f * LOG2E;

    int ktmax = 2 * qt + 1;

    for (int kt = 0; kt <= ktmax; kt++) {
        CPA_WAIT(0);
        __syncthreads();
        if (kt + 1 <= ktmax) {
            load_kv((kt + 1) & 1, (kt + 1) * 64);
            CPA_COMMIT();
        }

        uint32_t sb = kvbase + (uint32_t)((kt & 1) * AKV_STAGE * 2);
        uint32_t kb_hi = sb + kvo;
        uint32_t kb_lo = sb + AKV_ARR * 2 + kvo;
        uint32_t vb_hi = sb + 2 * AKV_ARR * 2 + kvo;
        int k0 = kt * 64;

        float s[8][4];
#pragma unroll
        for (int nf = 0; nf < 8; nf++)
#pragma unroll
            for (int e = 0; e < 4; e++) s[nf][e] = 0.0f;

#pragma unroll
        for (int ks = 0; ks < 4; ks++) {
#pragma unroll
            for (int g = 0; g < 4; g++) {
                uint32_t off = (uint32_t)((g * 16 * ALD + ks * 16) * 2);
                uint32_t r0, r1, r2, r3, t0, t1, t2, t3;
                ldm_x4(r0, r1, r2, r3, kb_hi + off);
                ldm_x4(t0, t1, t2, t3, kb_lo + off);
                mma_f16(s[2 * g],     qh[ks], r0, r2);
                mma_f16(s[2 * g + 1], qh[ks], r1, r3);
                mma_f16(s[2 * g],     ql[ks], r0, r2);
                mma_f16(s[2 * g + 1], ql[ks], r1, r3);
                mma_f16(s[2 * g],     qh[ks], t0, t2);
                mma_f16(s[2 * g + 1], qh[ks], t1, t3);
            }
        }

        if (kt >= ktmax - 1) {
#pragma unroll
            for (int nf = 0; nf < 8; nf++) {
                int cb = k0 + nf * 8 + (lane & 3) * 2;
#pragma unroll
                for (int e = 0; e < 4; e++) {
                    int col = cb + (e & 1);
                    int row = (e < 2) ? row0 : row0 + 8;
                    float v = s[nf][e] * scale2;
                    s[nf][e] = (col > row) ? maskv : v;
                }
            }
        } else {
#pragma unroll
            for (int nf = 0; nf < 8; nf++)
#pragma unroll
                for (int e = 0; e < 4; e++) s[nf][e] *= scale2;
        }

        // online softmax (log2 domain, MUFU exp2)
#pragma unroll
        for (int i = 0; i < 2; i++) {
            float mx = -1e30f;
#pragma unroll
            for (int nf = 0; nf < 8; nf++)
                mx = fmaxf(mx, fmaxf(s[nf][2 * i], s[nf][2 * i + 1]));
            mx = fmaxf(mx, __shfl_xor_sync(0xffffffffu, mx, 1));
            mx = fmaxf(mx, __shfl_xor_sync(0xffffffffu, mx, 2));
            float mn = fmaxf(m_[i], mx);
            float alpha = ex2(m_[i] - mn);
            float sum = 0.0f;
#pragma unroll
            for (int nf = 0; nf < 8; nf++) {
                float p0 = ex2(s[nf][2 * i] - mn);
                float p1 = ex2(s[nf][2 * i + 1] - mn);
                s[nf][2 * i] = p0; s[nf][2 * i + 1] = p1;
                sum += p0 + p1;
            }
            sum += __shfl_xor_sync(0xffffffffu, sum, 1);
            sum += __shfl_xor_sync(0xffffffffu, sum, 2);
            l_[i] = l_[i] * alpha + sum;
            m_[i] = mn;
#pragma unroll
            for (int j = 0; j < 8; j++) {
                o[j][2 * i] *= alpha; o[j][2 * i + 1] *= alpha;
            }
        }

        // O += P V  (1-pass: P hi only, V hi only)
#pragma unroll
        for (int c = 0; c < 4; c++) {
            uint32_t aph[4];
            aph[0] = packf16(s[2 * c][1], s[2 * c][0]);
            aph[1] = packf16(s[2 * c][3], s[2 * c][2]);
            aph[2] = packf16(s[2 * c + 1][1], s[2 * c + 1][0]);
            aph[3] = packf16(s[2 * c + 1][3], s[2 * c + 1][2]);
#pragma unroll
            for (int g = 0; g < 4; g++) {
                uint32_t off = (uint32_t)((c * 16 * ALD + g * 16) * 2);
                uint32_t r0, r1, r2, r3;
                ldm_x4_t(r0, r1, r2, r3, vb_hi + off);
                mma_f16(o[2 * g],     aph, r0, r1);
                mma_f16(o[2 * g + 1], aph, r2, r3);
            }
        }
    }

    // epilogue: O/l -> fp16 (hi only) merged-head [B*S, E]
    float inv0 = 1.0f / l_[0], inv1 = 1.0f / l_[1];
    int d0 = (lane & 3) * 2;
    size_t rb0 = ((size_t)(b * SS + row0)) * EE + h * DD;
    size_t rb1 = rb0 + (size_t)8 * EE;
#pragma unroll
    for (int j = 0; j < 8; j++) {
        int d = j * 8 + d0;
        float v0 = o[j][0] * inv0, v1 = o[j][1] * inv0;
        float v2 = o[j][2] * inv1, v3 = o[j][3] * inv1;
        *(uint32_t*)&g_ahi[rb0 + d] = packf16(v1, v0);
        *(uint32_t*)&g_ahi[rb1 + d] = packf16(v3, v2);
    }
}

// ---------------------------------------------------------------------------
extern "C" void kernel_launch(void* const* d_in, const int* in_sizes, int n_in,
                              void* d_out, int out_size)
{
    const float* hidden = (const float*)d_in[0];   // [B,S,E]
    const float* w_attn = (const float*)d_in[1];   // [E, 3E]
    const float* b_attn = (const float*)d_in[2];   // [3E]
    const float* w_proj = (const float*)d_in[3];   // [E, E]
    const float* b_proj = (const float*)d_in[4];   // [E]
    float* out = (float*)d_out;                    // [B,S,E] fp32

    split_kernel<<<(MROWS * KDIM) / (256 * 4), 256>>>(hidden);
    tsplit_kernel<<<dim3(N_QKV / 32, KDIM / 32), 256>>>(w_attn, 0, N_QKV);
    tsplit_kernel<<<dim3(EE / 32, KDIM / 32), 256>>>(w_proj, 1, EE);

    cudaFuncSetAttribute(mma_gemm, cudaFuncAttributeMaxDynamicSharedMemorySize,
                         GEMM_SMEM_BYTES);
    mma_gemm<<<dim3(N_QKV / 128, MROWS / 128), 256, GEMM_SMEM_BYTES>>>(
        b_attn, nullptr, 1);

    cudaFuncSetAttribute(attn_mma_kernel,
                         cudaFuncAttributeMaxDynamicSharedMemorySize,
                         ATTN_SMEM_BYTES);
    attn_mma_kernel<<<dim3(SS / 128, HH, BB), 256, ATTN_SMEM_BYTES>>>();

    mma_gemm<<<dim3(EE / 128, MROWS / 128), 256, GEMM_SMEM_BYTES>>>(
        b_proj, out, 0);
}